// round 1
// baseline (speedup 1.0000x reference)
#include <cuda_runtime.h>
#include <cstdint>

// Problem constants
#define D_MODEL 1024
#define HIDDEN  2048
#define D_STATE 16
#define BATCH   2
#define SEQ     2048
#define MTOK    (BATCH * SEQ)        // 4096 token rows

// GEMM tiling
#define BM 128
#define BN 128
#define BK 16
#define TM 8
#define TN 8

// ---------------- scratch (static device globals; no allocation) -------------
__device__ float g_u[(size_t)MTOK * HIDDEN];      // u projection [M,H]
__device__ float g_g[(size_t)MTOK * HIDDEN];      // gate, then combined scan input
__device__ float g_y[(size_t)MTOK * HIDDEN];      // scan output
__device__ float g_dtpart[(MTOK / BM) * HIDDEN];  // 32 x H partial softplus col sums
__device__ float g_Ad[HIDDEN * D_STATE];
__device__ float g_Bd[HIDDEN * D_STATE];
__device__ float g_outp[(size_t)MTOK * D_MODEL];  // pre-LN output projection

// ---------------- helpers ----------------------------------------------------
__device__ __forceinline__ float softplusf(float x) {
    return fmaxf(x, 0.f) + log1pf(expf(-fabsf(x)));
}
__device__ __forceinline__ float sigmoidf_(float x) {
    return 1.f / (1.f + expf(-x));
}

// ---------------- GEMM: C[M,N] = A[M,K] * B[N,K]^T + bias -------------------
// MODE 0: store raw. MODE 1: store sigmoid. MODE 2: no store; write per-block
// column sums of softplus(val) into colsum[by*N + col] (deterministic).
template <int MODE>
__global__ __launch_bounds__(256) void gemm_nt(
    const float* __restrict__ A, const float* __restrict__ B,
    const float* __restrict__ bias, float* __restrict__ C,
    float* __restrict__ colsum, int M, int N, int K)
{
    __shared__ float As[BK][BM];
    __shared__ float Bs[BK][BN];

    const int tid = threadIdx.x;
    const int tx = tid & 15;       // 0..15 -> column group
    const int ty = tid >> 4;       // 0..15 -> row group
    const int bx = blockIdx.x;     // N tile
    const int by = blockIdx.y;     // M tile

    const float* Ab = A + (size_t)by * BM * K;
    const float* Bb = B + (size_t)bx * BN * K;

    const int lrow = tid >> 2;          // 0..63
    const int lcol = (tid & 3) << 2;    // 0,4,8,12

    float acc[TM][TN];
#pragma unroll
    for (int i = 0; i < TM; i++)
#pragma unroll
        for (int j = 0; j < TN; j++) acc[i][j] = 0.f;

    for (int k0 = 0; k0 < K; k0 += BK) {
        float4 a0 = *(const float4*)(Ab + (size_t)lrow * K + k0 + lcol);
        float4 a1 = *(const float4*)(Ab + (size_t)(lrow + 64) * K + k0 + lcol);
        float4 b0 = *(const float4*)(Bb + (size_t)lrow * K + k0 + lcol);
        float4 b1 = *(const float4*)(Bb + (size_t)(lrow + 64) * K + k0 + lcol);

        As[lcol + 0][lrow] = a0.x; As[lcol + 1][lrow] = a0.y;
        As[lcol + 2][lrow] = a0.z; As[lcol + 3][lrow] = a0.w;
        As[lcol + 0][lrow + 64] = a1.x; As[lcol + 1][lrow + 64] = a1.y;
        As[lcol + 2][lrow + 64] = a1.z; As[lcol + 3][lrow + 64] = a1.w;
        Bs[lcol + 0][lrow] = b0.x; Bs[lcol + 1][lrow] = b0.y;
        Bs[lcol + 2][lrow] = b0.z; Bs[lcol + 3][lrow] = b0.w;
        Bs[lcol + 0][lrow + 64] = b1.x; Bs[lcol + 1][lrow + 64] = b1.y;
        Bs[lcol + 2][lrow + 64] = b1.z; Bs[lcol + 3][lrow + 64] = b1.w;
        __syncthreads();

#pragma unroll
        for (int kk = 0; kk < BK; kk++) {
            float ar[TM], br[TN];
            *(float4*)&ar[0] = *(const float4*)&As[kk][ty * TM];
            *(float4*)&ar[4] = *(const float4*)&As[kk][ty * TM + 4];
            *(float4*)&br[0] = *(const float4*)&Bs[kk][tx * TN];
            *(float4*)&br[4] = *(const float4*)&Bs[kk][tx * TN + 4];
#pragma unroll
            for (int i = 0; i < TM; i++)
#pragma unroll
                for (int j = 0; j < TN; j++)
                    acc[i][j] = fmaf(ar[i], br[j], acc[i][j]);
        }
        __syncthreads();
    }

    const int colbase = bx * BN + tx * TN;
    float bv[TN];
#pragma unroll
    for (int j = 0; j < TN; j++) bv[j] = bias[colbase + j];

    if (MODE == 2) {
        float csum[TN];
#pragma unroll
        for (int j = 0; j < TN; j++) csum[j] = 0.f;
#pragma unroll
        for (int i = 0; i < TM; i++)
#pragma unroll
            for (int j = 0; j < TN; j++)
                csum[j] += softplusf(acc[i][j] + bv[j]);
        // reuse As as [16][128] reduction space (all threads past final sync)
        float* red = &As[0][0];
#pragma unroll
        for (int j = 0; j < TN; j++) red[ty * 128 + tx * TN + j] = csum[j];
        __syncthreads();
        if (ty == 0) {
#pragma unroll
            for (int j = 0; j < TN; j++) {
                float s = 0.f;
#pragma unroll
                for (int t = 0; t < 16; t++) s += red[t * 128 + tx * TN + j];
                colsum[(size_t)by * N + colbase + j] = s;
            }
        }
    } else {
        const int rowbase = by * BM + ty * TM;
#pragma unroll
        for (int i = 0; i < TM; i++) {
            float v[TN];
#pragma unroll
            for (int j = 0; j < TN; j++) {
                float val = acc[i][j] + bv[j];
                v[j] = (MODE == 1) ? sigmoidf_(val) : val;
            }
            float* Crow = C + (size_t)(rowbase + i) * N + colbase;
            *(float4*)&Crow[0] = *(const float4*)&v[0];
            *(float4*)&Crow[4] = *(const float4*)&v[4];
        }
    }
}

// ---------------- dt finalize + discretization --------------------------------
__global__ void disc_kernel(const float* __restrict__ A_raw,
                            const float* __restrict__ B_ssm)
{
    int idx = blockIdx.x * blockDim.x + threadIdx.x;
    if (idx >= HIDDEN * D_STATE) return;
    int h = idx / D_STATE;
    float sum = 0.f;
#pragma unroll
    for (int p = 0; p < MTOK / BM; p++) sum += g_dtpart[p * HIDDEN + h];
    float dt = sum * (1.f / (float)MTOK);
    dt = fminf(fmaxf(dt, 1e-3f), 2.0f);
    float a = -softplusf(A_raw[idx]);
    float ad = expf(a * dt);
    float bd = (ad - 1.0f) / (a + 1e-6f) * B_ssm[idx];
    g_Ad[idx] = ad;
    g_Bd[idx] = bd;
}

// ---------------- depthwise conv (cross-correlation, zero pad) + gate --------
__global__ __launch_bounds__(256) void combine_kernel(
    const float* __restrict__ conv_w, const float* __restrict__ conv_b)
{
    int idx = blockIdx.x * blockDim.x + threadIdx.x;  // < M*H
    int h = idx & (HIDDEN - 1);
    int l = (idx >> 11) & (SEQ - 1);  // HIDDEN == 2048 == 2^11
    float u0 = g_u[idx];
    float um = (l > 0) ? g_u[idx - HIDDEN] : 0.f;
    float up = (l < SEQ - 1) ? g_u[idx + HIDDEN] : 0.f;
    float hc = conv_b[h]
             + conv_w[h * 3 + 0] * um
             + conv_w[h * 3 + 1] * u0
             + conv_w[h * 3 + 2] * up;
    float g = g_g[idx];
    g_g[idx] = u0 * g + hc * (1.f - g);
}

// ---------------- selective scan: one thread per (b,h) chain -----------------
__global__ __launch_bounds__(32) void scan_kernel(const float* __restrict__ C_ssm)
{
    int idx = blockIdx.x * blockDim.x + threadIdx.x;  // < BATCH*HIDDEN
    int b = idx >> 11;
    int h = idx & (HIDDEN - 1);

    float ad[D_STATE], bd[D_STATE], cc[D_STATE], st[D_STATE];
#pragma unroll
    for (int j = 0; j < D_STATE; j++) {
        ad[j] = g_Ad[h * D_STATE + j];
        bd[j] = g_Bd[h * D_STATE + j];
        cc[j] = C_ssm[h * D_STATE + j];
        st[j] = 0.f;
    }
    const float* up = g_g + (size_t)b * SEQ * HIDDEN + h;
    float* yp = g_y + (size_t)b * SEQ * HIDDEN + h;

    float ucur = up[0];
    for (int t = 0; t < SEQ; t++) {
        float unext = (t + 1 < SEQ) ? up[(size_t)(t + 1) * HIDDEN] : 0.f;
        float y0 = 0.f, y1 = 0.f, y2 = 0.f, y3 = 0.f;
#pragma unroll
        for (int j = 0; j < D_STATE; j++)
            st[j] = fmaf(ad[j], st[j], bd[j] * ucur);
#pragma unroll
        for (int j = 0; j < D_STATE; j += 4) {
            y0 = fmaf(st[j + 0], cc[j + 0], y0);
            y1 = fmaf(st[j + 1], cc[j + 1], y1);
            y2 = fmaf(st[j + 2], cc[j + 2], y2);
            y3 = fmaf(st[j + 3], cc[j + 3], y3);
        }
        yp[(size_t)t * HIDDEN] = (y0 + y1) + (y2 + y3);
        ucur = unext;
    }
}

// ---------------- residual + layernorm ---------------------------------------
__global__ __launch_bounds__(256) void ln_kernel(
    const float* __restrict__ x, const float* __restrict__ lng,
    const float* __restrict__ lnb, float* __restrict__ out)
{
    int row = blockIdx.x;
    __shared__ float sh[D_MODEL];
    __shared__ float rs[20];
    const float* xr = x + (size_t)row * D_MODEL;
    const float* orow = g_outp + (size_t)row * D_MODEL;
    int tid = threadIdx.x;

    float s = 0.f, sq = 0.f;
    for (int i = tid; i < D_MODEL; i += 256) {
        float r = xr[i] + orow[i];
        sh[i] = r;
        s += r;
        sq += r * r;
    }
#pragma unroll
    for (int o = 16; o > 0; o >>= 1) {
        s += __shfl_xor_sync(0xffffffffu, s, o);
        sq += __shfl_xor_sync(0xffffffffu, sq, o);
    }
    int w = tid >> 5, ln = tid & 31;
    if (ln == 0) { rs[w] = s; rs[8 + w] = sq; }
    __syncthreads();
    if (tid == 0) {
        float ts = 0.f, tq = 0.f;
#pragma unroll
        for (int i = 0; i < 8; i++) { ts += rs[i]; tq += rs[8 + i]; }
        float mean = ts * (1.f / (float)D_MODEL);
        float var = tq * (1.f / (float)D_MODEL) - mean * mean;
        rs[16] = mean;
        rs[17] = rsqrtf(var + 1e-5f);
    }
    __syncthreads();
    float mean = rs[16], inv = rs[17];
    for (int i = tid; i < D_MODEL; i += 256)
        out[(size_t)row * D_MODEL + i] = (sh[i] - mean) * inv * lng[i] + lnb[i];
}

// ---------------- launch -----------------------------------------------------
extern "C" void kernel_launch(void* const* d_in, const int* in_sizes, int n_in,
                              void* d_out, int out_size)
{
    const float* x      = (const float*)d_in[0];
    const float* W_x    = (const float*)d_in[1];
    const float* b_x    = (const float*)d_in[2];
    const float* W_g    = (const float*)d_in[3];
    const float* b_g    = (const float*)d_in[4];
    const float* conv_w = (const float*)d_in[5];
    const float* conv_b = (const float*)d_in[6];
    const float* A_raw  = (const float*)d_in[7];
    const float* B_ssm  = (const float*)d_in[8];
    const float* C_ssm  = (const float*)d_in[9];
    const float* W_dt   = (const float*)d_in[10];
    const float* b_dt   = (const float*)d_in[11];
    const float* W_out  = (const float*)d_in[12];
    const float* b_out  = (const float*)d_in[13];
    const float* ln_g   = (const float*)d_in[14];
    const float* ln_b   = (const float*)d_in[15];
    float* out = (float*)d_out;

    float *pu, *pg, *py, *pdt, *pout;
    cudaGetSymbolAddress((void**)&pu, g_u);
    cudaGetSymbolAddress((void**)&pg, g_g);
    cudaGetSymbolAddress((void**)&py, g_y);
    cudaGetSymbolAddress((void**)&pdt, g_dtpart);
    cudaGetSymbolAddress((void**)&pout, g_outp);

    dim3 gridH(HIDDEN / BN, MTOK / BM);   // (16, 32)
    dim3 gridD(D_MODEL / BN, MTOK / BM);  // (8, 32)

    // u / gate / dt projections (K = D_MODEL)
    gemm_nt<0><<<gridH, 256>>>(x, W_x, b_x, pu, nullptr, MTOK, HIDDEN, D_MODEL);
    gemm_nt<1><<<gridH, 256>>>(x, W_g, b_g, pg, nullptr, MTOK, HIDDEN, D_MODEL);
    gemm_nt<2><<<gridH, 256>>>(x, W_dt, b_dt, nullptr, pdt, MTOK, HIDDEN, D_MODEL);

    disc_kernel<<<(HIDDEN * D_STATE + 255) / 256, 256>>>(A_raw, B_ssm);
    combine_kernel<<<(MTOK * HIDDEN) / 256, 256>>>(conv_w, conv_b);
    scan_kernel<<<(BATCH * HIDDEN) / 32, 32>>>(C_ssm);

    // output projection (K = HIDDEN)
    gemm_nt<0><<<gridD, 256>>>(py, W_out, b_out, pout, nullptr, MTOK, D_MODEL, HIDDEN);

    ln_kernel<<<MTOK, 256>>>(x, ln_g, ln_b, out);
}

// round 3
// speedup vs baseline: 2.6553x; 2.6553x over previous
#include <cuda_runtime.h>
#include <cuda_bf16.h>
#include <cstdint>

#define D_MODEL 1024
#define HIDDEN  2048
#define D_STATE 16
#define BATCH   2
#define SEQ     2048
#define MTOK    4096

// ---------------- GEMM tiling -------------------------------------------------
#define BM 128
#define BN 128
#define BKE 64                        // bf16 K elems per chunk (128B rows)
#define RB 128                        // row bytes
#define TILE_B (128 * 128)            // one operand tile: 16 KB
#define NSTAGE 3
#define STAGE_B (4 * TILE_B)          // Ahi, Alo, Bhi, Blo
#define SMEM_GEMM (NSTAGE * STAGE_B)  // 196608 B

// ---------------- scratch ----------------------------------------------------
__device__ float g_u[(size_t)MTOK * HIDDEN];
__device__ float g_g[(size_t)MTOK * HIDDEN];
__device__ float g_outp[(size_t)MTOK * D_MODEL];
__device__ float g_dtpart[(MTOK / BM) * HIDDEN];
__device__ float g_Ad[HIDDEN * D_STATE];
__device__ float g_Bd[HIDDEN * D_STATE];

__device__ __nv_bfloat16 g_xhi[(size_t)MTOK * D_MODEL];
__device__ __nv_bfloat16 g_xlo[(size_t)MTOK * D_MODEL];
__device__ __nv_bfloat16 g_wxhi[HIDDEN * D_MODEL];
__device__ __nv_bfloat16 g_wxlo[HIDDEN * D_MODEL];
__device__ __nv_bfloat16 g_wghi[HIDDEN * D_MODEL];
__device__ __nv_bfloat16 g_wglo[HIDDEN * D_MODEL];
__device__ __nv_bfloat16 g_wdthi[HIDDEN * D_MODEL];
__device__ __nv_bfloat16 g_wdtlo[HIDDEN * D_MODEL];
__device__ __nv_bfloat16 g_wohi[D_MODEL * HIDDEN];
__device__ __nv_bfloat16 g_wolo[D_MODEL * HIDDEN];
__device__ __nv_bfloat16 g_yhi[(size_t)MTOK * HIDDEN];
__device__ __nv_bfloat16 g_ylo[(size_t)MTOK * HIDDEN];

// ---------------- helpers ----------------------------------------------------
__device__ __forceinline__ float softplusf(float x) {
    return fmaxf(x, 0.f) + log1pf(expf(-fabsf(x)));
}
__device__ __forceinline__ float sigmoidf_(float x) {
    return 1.f / (1.f + expf(-x));
}
__device__ __forceinline__ uint32_t smem_u32(const void* p) {
    uint32_t a;
    asm("{ .reg .u64 t; cvta.to.shared.u64 t, %1; cvt.u32.u64 %0, t; }"
        : "=r"(a) : "l"(p));
    return a;
}
__device__ __forceinline__ void cpasync16(uint32_t saddr, const void* g) {
    asm volatile("cp.async.cg.shared.global [%0], [%1], 16;"
                 :: "r"(saddr), "l"(g));
}
__device__ __forceinline__ void ldm_x4(uint32_t* r, uint32_t addr) {
    asm volatile("ldmatrix.sync.aligned.m8n8.x4.shared.b16 {%0,%1,%2,%3}, [%4];"
                 : "=r"(r[0]), "=r"(r[1]), "=r"(r[2]), "=r"(r[3]) : "r"(addr));
}
__device__ __forceinline__ void mma_bf16(float* d, const uint32_t* a,
                                         const uint32_t* b) {
    asm volatile(
        "mma.sync.aligned.m16n8k16.row.col.f32.bf16.bf16.f32 "
        "{%0,%1,%2,%3}, {%4,%5,%6,%7}, {%8,%9}, {%0,%1,%2,%3};"
        : "+f"(d[0]), "+f"(d[1]), "+f"(d[2]), "+f"(d[3])
        : "r"(a[0]), "r"(a[1]), "r"(a[2]), "r"(a[3]), "r"(b[0]), "r"(b[1]));
}

// ---------------- fp32 -> bf16 hi/lo split -----------------------------------
__global__ __launch_bounds__(256) void split_kernel(
    const float4* __restrict__ src, __nv_bfloat162* __restrict__ hi,
    __nv_bfloat162* __restrict__ lo, int n4)
{
    int i = blockIdx.x * blockDim.x + threadIdx.x;
    if (i >= n4) return;
    float4 v = src[i];
    __nv_bfloat16 h0 = __float2bfloat16(v.x);
    __nv_bfloat16 h1 = __float2bfloat16(v.y);
    __nv_bfloat16 h2 = __float2bfloat16(v.z);
    __nv_bfloat16 h3 = __float2bfloat16(v.w);
    __nv_bfloat16 l0 = __float2bfloat16(v.x - __bfloat162float(h0));
    __nv_bfloat16 l1 = __float2bfloat16(v.y - __bfloat162float(h1));
    __nv_bfloat16 l2 = __float2bfloat16(v.z - __bfloat162float(h2));
    __nv_bfloat16 l3 = __float2bfloat16(v.w - __bfloat162float(h3));
    hi[i * 2 + 0] = __nv_bfloat162(h0, h1);
    hi[i * 2 + 1] = __nv_bfloat162(h2, h3);
    lo[i * 2 + 0] = __nv_bfloat162(l0, l1);
    lo[i * 2 + 1] = __nv_bfloat162(l2, l3);
}

// ---------------- HMMA GEMM: C[M,N] = A[M,K] * B[N,K]^T (3-term bf16) --------
// MODE 0: raw+bias. MODE 1: sigmoid. MODE 2: per-M-block softplus column sums.
template <int MODE>
__global__ __launch_bounds__(256, 1) void gemm_bf16x3(
    const __nv_bfloat16* __restrict__ Ahi, const __nv_bfloat16* __restrict__ Alo,
    const __nv_bfloat16* __restrict__ Bhi, const __nv_bfloat16* __restrict__ Blo,
    const float* __restrict__ bias, float* __restrict__ C,
    float* __restrict__ colsum, int M, int N, int K)
{
    extern __shared__ char smem[];
    const uint32_t sb = smem_u32(smem);
    const int tid = threadIdx.x;
    const int wid = tid >> 5, lane = tid & 31;
    const int wm = wid & 1, wn = wid >> 1;       // warp tile: 64(m) x 32(n)
    const int am0 = blockIdx.y * BM;
    const int bn0 = blockIdx.x * BN;

    // loader: seg = tid&7 (16B), row = tid>>3 (0..31), 4 row-blocks
    const int lseg = tid & 7;
    const int lrow = tid >> 3;

    auto load_chunk = [&](int ch) {
        uint32_t st = sb + (uint32_t)(ch % NSTAGE) * STAGE_B;
        int kb = ch * BKE + lseg * 8;
#pragma unroll
        for (int rb = 0; rb < 128; rb += 32) {
            int row = lrow + rb;
            uint32_t off = (uint32_t)row * RB + (uint32_t)lseg * 16u;
            uint32_t sw = off ^ ((off >> 3) & 0x70);
            size_t ga = (size_t)(am0 + row) * K + kb;
            size_t gb = (size_t)(bn0 + row) * K + kb;
            cpasync16(st + 0 * TILE_B + sw, Ahi + ga);
            cpasync16(st + 1 * TILE_B + sw, Alo + ga);
            cpasync16(st + 2 * TILE_B + sw, Bhi + gb);
            cpasync16(st + 3 * TILE_B + sw, Blo + gb);
        }
    };

    float acc[4][4][4];
#pragma unroll
    for (int i = 0; i < 4; i++)
#pragma unroll
        for (int j = 0; j < 4; j++)
#pragma unroll
            for (int v = 0; v < 4; v++) acc[i][j][v] = 0.f;

    // ldmatrix per-thread geometry
    const int arA = wm * 64 + (lane & 15);
    const int ahalf = lane >> 4;
    const uint32_t axor = (uint32_t)(arA & 7);
    uint32_t aoff[4];
#pragma unroll
    for (int mf = 0; mf < 4; mf++) aoff[mf] = (uint32_t)(arA + mf * 16) * RB;

    const int nrB = wn * 32 + (lane & 7) + ((lane >> 4) << 3);
    const int khalf = (lane >> 3) & 1;
    const uint32_t bxor = (uint32_t)(nrB & 7);
    uint32_t boff[2];
#pragma unroll
    for (int nf = 0; nf < 2; nf++) boff[nf] = (uint32_t)(nrB + nf * 16) * RB;

    const int NCH = K / BKE;
    load_chunk(0);
    asm volatile("cp.async.commit_group;");
    load_chunk(1);
    asm volatile("cp.async.commit_group;");

    for (int ch = 0; ch < NCH; ch++) {
        asm volatile("cp.async.wait_group 1;" ::: "memory");
        __syncthreads();
        const uint32_t st = sb + (uint32_t)(ch % NSTAGE) * STAGE_B;

#pragma unroll
        for (int ks = 0; ks < 4; ks++) {
            uint32_t a[4][4], bh[4][2], bl[4][2];
            const uint32_t asg = (((uint32_t)(ks * 2 + ahalf)) ^ axor) << 4;
            const uint32_t bsg = (((uint32_t)(ks * 2 + khalf)) ^ bxor) << 4;
            // B hi + lo
#pragma unroll
            for (int nf = 0; nf < 2; nf++) {
                uint32_t rr[4];
                ldm_x4(rr, st + 2 * TILE_B + boff[nf] + bsg);
                bh[nf * 2 + 0][0] = rr[0]; bh[nf * 2 + 0][1] = rr[1];
                bh[nf * 2 + 1][0] = rr[2]; bh[nf * 2 + 1][1] = rr[3];
                ldm_x4(rr, st + 3 * TILE_B + boff[nf] + bsg);
                bl[nf * 2 + 0][0] = rr[0]; bl[nf * 2 + 0][1] = rr[1];
                bl[nf * 2 + 1][0] = rr[2]; bl[nf * 2 + 1][1] = rr[3];
            }
            // A hi : hihi + hilo
#pragma unroll
            for (int mf = 0; mf < 4; mf++) {
                ldm_x4(a[mf], st + 0 * TILE_B + aoff[mf] + asg);
#pragma unroll
                for (int nfi = 0; nfi < 4; nfi++) {
                    mma_bf16(acc[mf][nfi], a[mf], bh[nfi]);
                    mma_bf16(acc[mf][nfi], a[mf], bl[nfi]);
                }
            }
            // A lo : lohi
#pragma unroll
            for (int mf = 0; mf < 4; mf++) {
                ldm_x4(a[mf], st + 1 * TILE_B + aoff[mf] + asg);
#pragma unroll
                for (int nfi = 0; nfi < 4; nfi++)
                    mma_bf16(acc[mf][nfi], a[mf], bh[nfi]);
            }
        }

        if (ch + 2 < NCH) load_chunk(ch + 2);
        asm volatile("cp.async.commit_group;");
    }

    // ---- epilogue ----
    if (MODE == 2) {
        __syncthreads();                 // tiles dead; reuse smem for reduction
        float* red = (float*)smem;       // [2][128]
#pragma unroll
        for (int nfi = 0; nfi < 4; nfi++) {
            const int colb = bn0 + wn * 32 + nfi * 8 + (lane & 3) * 2;
            const float b0 = bias[colb], b1 = bias[colb + 1];
            float s0 = 0.f, s1 = 0.f;
#pragma unroll
            for (int mf = 0; mf < 4; mf++) {
                s0 += softplusf(acc[mf][nfi][0] + b0);
                s1 += softplusf(acc[mf][nfi][1] + b1);
                s0 += softplusf(acc[mf][nfi][2] + b0);
                s1 += softplusf(acc[mf][nfi][3] + b1);
            }
#pragma unroll
            for (int o = 4; o <= 16; o <<= 1) {
                s0 += __shfl_xor_sync(0xffffffffu, s0, o);
                s1 += __shfl_xor_sync(0xffffffffu, s1, o);
            }
            if (lane < 4) {
                int c = wn * 32 + nfi * 8 + lane * 2;
                red[wm * 128 + c] = s0;
                red[wm * 128 + c + 1] = s1;
            }
        }
        __syncthreads();
        if (tid < 128)
            colsum[(size_t)blockIdx.y * N + bn0 + tid] =
                red[tid] + red[128 + tid];
    } else {
#pragma unroll
        for (int mf = 0; mf < 4; mf++) {
            const int r0 = am0 + wm * 64 + mf * 16 + (lane >> 2);
#pragma unroll
            for (int h = 0; h < 2; h++) {
                const int row = r0 + h * 8;
#pragma unroll
                for (int nfi = 0; nfi < 4; nfi++) {
                    const int col = bn0 + wn * 32 + nfi * 8 + (lane & 3) * 2;
                    float v0 = acc[mf][nfi][h * 2 + 0] + bias[col];
                    float v1 = acc[mf][nfi][h * 2 + 1] + bias[col + 1];
                    if (MODE == 1) { v0 = sigmoidf_(v0); v1 = sigmoidf_(v1); }
                    float2 o2 = make_float2(v0, v1);
                    *(float2*)&C[(size_t)row * N + col] = o2;
                }
            }
        }
    }
}

// ---------------- dt finalize + discretization --------------------------------
__global__ void disc_kernel(const float* __restrict__ A_raw,
                            const float* __restrict__ B_ssm)
{
    int idx = blockIdx.x * blockDim.x + threadIdx.x;
    if (idx >= HIDDEN * D_STATE) return;
    int h = idx / D_STATE;
    float sum = 0.f;
#pragma unroll
    for (int p = 0; p < MTOK / BM; p++) sum += g_dtpart[p * HIDDEN + h];
    float dt = sum * (1.f / (float)MTOK);
    dt = fminf(fmaxf(dt, 1e-3f), 2.0f);
    float a = -softplusf(A_raw[idx]);
    float ad = expf(a * dt);
    float bd = (ad - 1.0f) / (a + 1e-6f) * B_ssm[idx];
    g_Ad[idx] = ad;
    g_Bd[idx] = bd;
}

// ---------------- depthwise conv + gate --------------------------------------
__global__ __launch_bounds__(256) void combine_kernel(
    const float* __restrict__ conv_w, const float* __restrict__ conv_b)
{
    int idx = blockIdx.x * blockDim.x + threadIdx.x;
    int h = idx & (HIDDEN - 1);
    int l = (idx >> 11) & (SEQ - 1);
    float u0 = g_u[idx];
    float um = (l > 0) ? g_u[idx - HIDDEN] : 0.f;
    float up = (l < SEQ - 1) ? g_u[idx + HIDDEN] : 0.f;
    float hc = conv_b[h]
             + conv_w[h * 3 + 0] * um
             + conv_w[h * 3 + 1] * u0
             + conv_w[h * 3 + 2] * up;
    float g = g_g[idx];
    g_g[idx] = u0 * g + hc * (1.f - g);
}

// ---------------- selective scan (depth-8 prefetch, bf16 hi/lo out) ----------
__global__ __launch_bounds__(32) void scan_kernel(const float* __restrict__ C_ssm)
{
    int idx = blockIdx.x * blockDim.x + threadIdx.x;
    int b = idx >> 11;
    int h = idx & (HIDDEN - 1);

    float ad[D_STATE], bd[D_STATE], cc[D_STATE], st[D_STATE];
#pragma unroll
    for (int j = 0; j < D_STATE; j++) {
        ad[j] = g_Ad[h * D_STATE + j];
        bd[j] = g_Bd[h * D_STATE + j];
        cc[j] = C_ssm[h * D_STATE + j];
        st[j] = 0.f;
    }
    const float* up = g_g + (size_t)b * SEQ * HIDDEN + h;
    __nv_bfloat16* yh = g_yhi + (size_t)b * SEQ * HIDDEN + h;
    __nv_bfloat16* yl = g_ylo + (size_t)b * SEQ * HIDDEN + h;

    float pf[8];
#pragma unroll
    for (int q = 0; q < 8; q++) pf[q] = up[(size_t)q * HIDDEN];

    for (int t = 0; t < SEQ; t += 8) {
#pragma unroll
        for (int q = 0; q < 8; q++) {
            float ucur = pf[q];
            int tn = t + 8 + q;
            pf[q] = (tn < SEQ) ? up[(size_t)tn * HIDDEN] : 0.f;
            float y0 = 0.f, y1 = 0.f, y2 = 0.f, y3 = 0.f;
#pragma unroll
            for (int j = 0; j < D_STATE; j++)
                st[j] = fmaf(ad[j], st[j], bd[j] * ucur);
#pragma unroll
            for (int j = 0; j < D_STATE; j += 4) {
                y0 = fmaf(st[j + 0], cc[j + 0], y0);
                y1 = fmaf(st[j + 1], cc[j + 1], y1);
                y2 = fmaf(st[j + 2], cc[j + 2], y2);
                y3 = fmaf(st[j + 3], cc[j + 3], y3);
            }
            float yv = (y0 + y1) + (y2 + y3);
            __nv_bfloat16 hi = __float2bfloat16(yv);
            __nv_bfloat16 lo = __float2bfloat16(yv - __bfloat162float(hi));
            yh[(size_t)(t + q) * HIDDEN] = hi;
            yl[(size_t)(t + q) * HIDDEN] = lo;
        }
    }
}

// ---------------- residual + layernorm ---------------------------------------
__global__ __launch_bounds__(256) void ln_kernel(
    const float* __restrict__ x, const float* __restrict__ lng,
    const float* __restrict__ lnb, float* __restrict__ out)
{
    int row = blockIdx.x;
    __shared__ float sh[D_MODEL];
    __shared__ float rs[20];
    const float* xr = x + (size_t)row * D_MODEL;
    const float* orow = g_outp + (size_t)row * D_MODEL;
    int tid = threadIdx.x;

    float s = 0.f, sq = 0.f;
    for (int i = tid; i < D_MODEL; i += 256) {
        float r = xr[i] + orow[i];
        sh[i] = r;
        s += r;
        sq += r * r;
    }
#pragma unroll
    for (int o = 16; o > 0; o >>= 1) {
        s += __shfl_xor_sync(0xffffffffu, s, o);
        sq += __shfl_xor_sync(0xffffffffu, sq, o);
    }
    int w = tid >> 5, ln = tid & 31;
    if (ln == 0) { rs[w] = s; rs[8 + w] = sq; }
    __syncthreads();
    if (tid == 0) {
        float ts = 0.f, tq = 0.f;
#pragma unroll
        for (int i = 0; i < 8; i++) { ts += rs[i]; tq += rs[8 + i]; }
        float mean = ts * (1.f / (float)D_MODEL);
        float var = tq * (1.f / (float)D_MODEL) - mean * mean;
        rs[16] = mean;
        rs[17] = rsqrtf(var + 1e-5f);
    }
    __syncthreads();
    float mean = rs[16], inv = rs[17];
    for (int i = tid; i < D_MODEL; i += 256)
        out[(size_t)row * D_MODEL + i] = (sh[i] - mean) * inv * lng[i] + lnb[i];
}

// ---------------- launch -----------------------------------------------------
extern "C" void kernel_launch(void* const* d_in, const int* in_sizes, int n_in,
                              void* d_out, int out_size)
{
    const float* x      = (const float*)d_in[0];
    const float* W_x    = (const float*)d_in[1];
    const float* b_x    = (const float*)d_in[2];
    const float* W_g    = (const float*)d_in[3];
    const float* b_g    = (const float*)d_in[4];
    const float* conv_w = (const float*)d_in[5];
    const float* conv_b = (const float*)d_in[6];
    const float* A_raw  = (const float*)d_in[7];
    const float* B_ssm  = (const float*)d_in[8];
    const float* C_ssm  = (const float*)d_in[9];
    const float* W_dt   = (const float*)d_in[10];
    const float* b_dt   = (const float*)d_in[11];
    const float* W_out  = (const float*)d_in[12];
    const float* b_out  = (const float*)d_in[13];
    const float* ln_g   = (const float*)d_in[14];
    const float* ln_b   = (const float*)d_in[15];
    float* out = (float*)d_out;

    float *pu, *pg, *pdt, *pout;
    __nv_bfloat16 *pxh, *pxl, *pwxh, *pwxl, *pwgh, *pwgl, *pwdh, *pwdl,
                  *pwoh, *pwol, *pyh, *pyl;
    cudaGetSymbolAddress((void**)&pu, g_u);
    cudaGetSymbolAddress((void**)&pg, g_g);
    cudaGetSymbolAddress((void**)&pdt, g_dtpart);
    cudaGetSymbolAddress((void**)&pout, g_outp);
    cudaGetSymbolAddress((void**)&pxh, g_xhi);
    cudaGetSymbolAddress((void**)&pxl, g_xlo);
    cudaGetSymbolAddress((void**)&pwxh, g_wxhi);
    cudaGetSymbolAddress((void**)&pwxl, g_wxlo);
    cudaGetSymbolAddress((void**)&pwgh, g_wghi);
    cudaGetSymbolAddress((void**)&pwgl, g_wglo);
    cudaGetSymbolAddress((void**)&pwdh, g_wdthi);
    cudaGetSymbolAddress((void**)&pwdl, g_wdtlo);
    cudaGetSymbolAddress((void**)&pwoh, g_wohi);
    cudaGetSymbolAddress((void**)&pwol, g_wolo);
    cudaGetSymbolAddress((void**)&pyh, g_yhi);
    cudaGetSymbolAddress((void**)&pyl, g_ylo);

    cudaFuncSetAttribute(gemm_bf16x3<0>, cudaFuncAttributeMaxDynamicSharedMemorySize, SMEM_GEMM);
    cudaFuncSetAttribute(gemm_bf16x3<1>, cudaFuncAttributeMaxDynamicSharedMemorySize, SMEM_GEMM);
    cudaFuncSetAttribute(gemm_bf16x3<2>, cudaFuncAttributeMaxDynamicSharedMemorySize, SMEM_GEMM);

    auto splitN = [&](const float* src, __nv_bfloat16* hi, __nv_bfloat16* lo, int n) {
        int n4 = n / 4;
        split_kernel<<<(n4 + 255) / 256, 256>>>((const float4*)src,
                                                (__nv_bfloat162*)hi,
                                                (__nv_bfloat162*)lo, n4);
    };
    splitN(x,     pxh, pxl, MTOK * D_MODEL);
    splitN(W_x,   pwxh, pwxl, HIDDEN * D_MODEL);
    splitN(W_g,   pwgh, pwgl, HIDDEN * D_MODEL);
    splitN(W_dt,  pwdh, pwdl, HIDDEN * D_MODEL);
    splitN(W_out, pwoh, pwol, D_MODEL * HIDDEN);

    dim3 gridH(HIDDEN / BN, MTOK / BM);    // (16, 32)
    dim3 gridD(D_MODEL / BN, MTOK / BM);   // (8, 32)

    gemm_bf16x3<0><<<gridH, 256, SMEM_GEMM>>>(pxh, pxl, pwxh, pwxl, b_x, pu, nullptr,
                                              MTOK, HIDDEN, D_MODEL);
    gemm_bf16x3<1><<<gridH, 256, SMEM_GEMM>>>(pxh, pxl, pwgh, pwgl, b_g, pg, nullptr,
                                              MTOK, HIDDEN, D_MODEL);
    gemm_bf16x3<2><<<gridH, 256, SMEM_GEMM>>>(pxh, pxl, pwdh, pwdl, b_dt, nullptr, pdt,
                                              MTOK, HIDDEN, D_MODEL);

    disc_kernel<<<(HIDDEN * D_STATE + 255) / 256, 256>>>(A_raw, B_ssm);
    combine_kernel<<<(MTOK * HIDDEN) / 256, 256>>>(conv_w, conv_b);
    scan_kernel<<<(BATCH * HIDDEN) / 32, 32>>>(C_ssm);

    gemm_bf16x3<0><<<gridD, 256, SMEM_GEMM>>>(pyh, pyl, pwoh, pwol, b_out, pout, nullptr,
                                              MTOK, D_MODEL, HIDDEN);

    ln_kernel<<<MTOK, 256>>>(x, ln_g, ln_b, out);
}

// round 4
// speedup vs baseline: 3.5290x; 1.3290x over previous
#include <cuda_runtime.h>
#include <cuda_bf16.h>
#include <cstdint>

#define D_MODEL 1024
#define HIDDEN  2048
#define D_STATE 16
#define BATCH   2
#define SEQ     2048
#define MTOK    4096
#define NCHK    16
#define CHK     128

// ---------------- GEMM tiling -------------------------------------------------
#define BM 128
#define BN 128
#define BKE 64
#define RB 128
#define TILE_B (128 * 128)
#define NSTAGE 3
#define STAGE_B (4 * TILE_B)
#define SMEM_GEMM (NSTAGE * STAGE_B)      // 196608 (3-stage, 4-tile kernels)
#define STAGE_UG (6 * TILE_B)
#define SMEM_UG (2 * STAGE_UG)            // 196608 (2-stage, 6-tile fused)

// ---------------- scratch ----------------------------------------------------
__device__ float g_u[(size_t)MTOK * HIDDEN];      // u, then y_local (fp32)
__device__ float g_g[(size_t)MTOK * HIDDEN];      // gate, then scan input
__device__ float g_outp[(size_t)MTOK * D_MODEL];
__device__ float g_dtpart[(MTOK / BM) * HIDDEN];
__device__ float g_Ad[HIDDEN * D_STATE];
__device__ float g_Bd[HIDDEN * D_STATE];
__device__ float g_state[(size_t)BATCH * NCHK * HIDDEN * D_STATE];
__device__ float g_init[(size_t)BATCH * NCHK * HIDDEN * D_STATE];

__device__ __nv_bfloat16 g_xhi[(size_t)MTOK * D_MODEL];
__device__ __nv_bfloat16 g_xlo[(size_t)MTOK * D_MODEL];
__device__ __nv_bfloat16 g_wxhi[HIDDEN * D_MODEL];
__device__ __nv_bfloat16 g_wxlo[HIDDEN * D_MODEL];
__device__ __nv_bfloat16 g_wghi[HIDDEN * D_MODEL];
__device__ __nv_bfloat16 g_wglo[HIDDEN * D_MODEL];
__device__ __nv_bfloat16 g_wdthi[HIDDEN * D_MODEL];
__device__ __nv_bfloat16 g_wdtlo[HIDDEN * D_MODEL];
__device__ __nv_bfloat16 g_wohi[D_MODEL * HIDDEN];
__device__ __nv_bfloat16 g_wolo[D_MODEL * HIDDEN];
__device__ __nv_bfloat16 g_yhi[(size_t)MTOK * HIDDEN];
__device__ __nv_bfloat16 g_ylo[(size_t)MTOK * HIDDEN];

// ---------------- helpers ----------------------------------------------------
__device__ __forceinline__ float softplusf(float x) {
    return fmaxf(x, 0.f) + log1pf(expf(-fabsf(x)));
}
__device__ __forceinline__ float sigmoidf_(float x) {
    return 1.f / (1.f + expf(-x));
}
__device__ __forceinline__ uint32_t smem_u32(const void* p) {
    uint32_t a;
    asm("{ .reg .u64 t; cvta.to.shared.u64 t, %1; cvt.u32.u64 %0, t; }"
        : "=r"(a) : "l"(p));
    return a;
}
__device__ __forceinline__ void cpasync16(uint32_t saddr, const void* g) {
    asm volatile("cp.async.cg.shared.global [%0], [%1], 16;"
                 :: "r"(saddr), "l"(g));
}
__device__ __forceinline__ void ldm_x4(uint32_t* r, uint32_t addr) {
    asm volatile("ldmatrix.sync.aligned.m8n8.x4.shared.b16 {%0,%1,%2,%3}, [%4];"
                 : "=r"(r[0]), "=r"(r[1]), "=r"(r[2]), "=r"(r[3]) : "r"(addr));
}
__device__ __forceinline__ void mma_bf16(float* d, const uint32_t* a,
                                         const uint32_t* b) {
    asm volatile(
        "mma.sync.aligned.m16n8k16.row.col.f32.bf16.bf16.f32 "
        "{%0,%1,%2,%3}, {%4,%5,%6,%7}, {%8,%9}, {%0,%1,%2,%3};"
        : "+f"(d[0]), "+f"(d[1]), "+f"(d[2]), "+f"(d[3])
        : "r"(a[0]), "r"(a[1]), "r"(a[2]), "r"(a[3]), "r"(b[0]), "r"(b[1]));
}

// ---------------- fp32 -> bf16 hi/lo split -----------------------------------
__global__ __launch_bounds__(256) void split_kernel(
    const float4* __restrict__ src, __nv_bfloat162* __restrict__ hi,
    __nv_bfloat162* __restrict__ lo, int n4)
{
    int i = blockIdx.x * blockDim.x + threadIdx.x;
    if (i >= n4) return;
    float4 v = src[i];
    __nv_bfloat16 h0 = __float2bfloat16(v.x);
    __nv_bfloat16 h1 = __float2bfloat16(v.y);
    __nv_bfloat16 h2 = __float2bfloat16(v.z);
    __nv_bfloat16 h3 = __float2bfloat16(v.w);
    __nv_bfloat16 l0 = __float2bfloat16(v.x - __bfloat162float(h0));
    __nv_bfloat16 l1 = __float2bfloat16(v.y - __bfloat162float(h1));
    __nv_bfloat16 l2 = __float2bfloat16(v.z - __bfloat162float(h2));
    __nv_bfloat16 l3 = __float2bfloat16(v.w - __bfloat162float(h3));
    hi[i * 2 + 0] = __nv_bfloat162(h0, h1);
    hi[i * 2 + 1] = __nv_bfloat162(h2, h3);
    lo[i * 2 + 0] = __nv_bfloat162(l0, l1);
    lo[i * 2 + 1] = __nv_bfloat162(l2, l3);
}

// ---------------- fused u + gate GEMM (shared A, 2-stage, 6 tiles) -----------
__global__ __launch_bounds__(256, 1) void gemm_ug(
    const __nv_bfloat16* __restrict__ Ahi, const __nv_bfloat16* __restrict__ Alo,
    const __nv_bfloat16* __restrict__ Xhi, const __nv_bfloat16* __restrict__ Xlo,
    const __nv_bfloat16* __restrict__ Ghi, const __nv_bfloat16* __restrict__ Glo,
    const float* __restrict__ bx, const float* __restrict__ bg,
    float* __restrict__ Cu, float* __restrict__ Cg, int M, int N, int K)
{
    extern __shared__ char smem[];
    const uint32_t sb = smem_u32(smem);
    const int tid = threadIdx.x;
    const int wid = tid >> 5, lane = tid & 31;
    const int wm = wid & 1, wn = wid >> 1;
    const int am0 = blockIdx.y * BM;
    const int bn0 = blockIdx.x * BN;
    const int lseg = tid & 7;
    const int lrow = tid >> 3;

    auto load_chunk = [&](int ch) {
        uint32_t st = sb + (uint32_t)(ch & 1) * STAGE_UG;
        int kb = ch * BKE + lseg * 8;
#pragma unroll
        for (int rb = 0; rb < 128; rb += 32) {
            int row = lrow + rb;
            uint32_t off = (uint32_t)row * RB + (uint32_t)lseg * 16u;
            uint32_t sw = off ^ ((off >> 3) & 0x70);
            size_t ga = (size_t)(am0 + row) * K + kb;
            size_t gb = (size_t)(bn0 + row) * K + kb;
            cpasync16(st + 0 * TILE_B + sw, Ahi + ga);
            cpasync16(st + 1 * TILE_B + sw, Alo + ga);
            cpasync16(st + 2 * TILE_B + sw, Xhi + gb);
            cpasync16(st + 3 * TILE_B + sw, Xlo + gb);
            cpasync16(st + 4 * TILE_B + sw, Ghi + gb);
            cpasync16(st + 5 * TILE_B + sw, Glo + gb);
        }
    };

    float acc_u[4][4][4], acc_g[4][4][4];
#pragma unroll
    for (int i = 0; i < 4; i++)
#pragma unroll
        for (int j = 0; j < 4; j++)
#pragma unroll
            for (int v = 0; v < 4; v++) { acc_u[i][j][v] = 0.f; acc_g[i][j][v] = 0.f; }

    const int arA = wm * 64 + (lane & 15);
    const int ahalf = lane >> 4;
    const uint32_t axor = (uint32_t)(arA & 7);
    uint32_t aoff[4];
#pragma unroll
    for (int mf = 0; mf < 4; mf++) aoff[mf] = (uint32_t)(arA + mf * 16) * RB;

    const int nrB = wn * 32 + (lane & 7) + ((lane >> 4) << 3);
    const int khalf = (lane >> 3) & 1;
    const uint32_t bxor = (uint32_t)(nrB & 7);
    uint32_t boff[2];
#pragma unroll
    for (int nf = 0; nf < 2; nf++) boff[nf] = (uint32_t)(nrB + nf * 16) * RB;

    const int NCH = K / BKE;
    load_chunk(0);
    asm volatile("cp.async.commit_group;");

    for (int ch = 0; ch < NCH; ch++) {
        if (ch + 1 < NCH) load_chunk(ch + 1);
        asm volatile("cp.async.commit_group;");
        asm volatile("cp.async.wait_group 1;" ::: "memory");
        __syncthreads();
        const uint32_t st = sb + (uint32_t)(ch & 1) * STAGE_UG;

#pragma unroll
        for (int ks = 0; ks < 4; ks++) {
            const uint32_t asg = (((uint32_t)(ks * 2 + ahalf)) ^ axor) << 4;
            const uint32_t bsg = (((uint32_t)(ks * 2 + khalf)) ^ bxor) << 4;
            uint32_t ah[4][4], al[4][4];
#pragma unroll
            for (int mf = 0; mf < 4; mf++) {
                ldm_x4(ah[mf], st + 0 * TILE_B + aoff[mf] + asg);
                ldm_x4(al[mf], st + 1 * TILE_B + aoff[mf] + asg);
            }
#pragma unroll
            for (int w = 0; w < 2; w++) {
                uint32_t bh[4][2], bl[4][2];
#pragma unroll
                for (int nf = 0; nf < 2; nf++) {
                    uint32_t rr[4];
                    ldm_x4(rr, st + (2 + 2 * w) * TILE_B + boff[nf] + bsg);
                    bh[nf * 2 + 0][0] = rr[0]; bh[nf * 2 + 0][1] = rr[1];
                    bh[nf * 2 + 1][0] = rr[2]; bh[nf * 2 + 1][1] = rr[3];
                    ldm_x4(rr, st + (3 + 2 * w) * TILE_B + boff[nf] + bsg);
                    bl[nf * 2 + 0][0] = rr[0]; bl[nf * 2 + 0][1] = rr[1];
                    bl[nf * 2 + 1][0] = rr[2]; bl[nf * 2 + 1][1] = rr[3];
                }
                float (*acc)[4][4] = (w == 0) ? acc_u : acc_g;
#pragma unroll
                for (int mf = 0; mf < 4; mf++)
#pragma unroll
                    for (int nfi = 0; nfi < 4; nfi++) {
                        mma_bf16(acc[mf][nfi], ah[mf], bh[nfi]);
                        mma_bf16(acc[mf][nfi], ah[mf], bl[nfi]);
                        mma_bf16(acc[mf][nfi], al[mf], bh[nfi]);
                    }
            }
        }
        __syncthreads();
    }

#pragma unroll
    for (int mf = 0; mf < 4; mf++) {
        const int r0 = am0 + wm * 64 + mf * 16 + (lane >> 2);
#pragma unroll
        for (int h = 0; h < 2; h++) {
            const int row = r0 + h * 8;
#pragma unroll
            for (int nfi = 0; nfi < 4; nfi++) {
                const int col = bn0 + wn * 32 + nfi * 8 + (lane & 3) * 2;
                float u0 = acc_u[mf][nfi][h * 2 + 0] + bx[col];
                float u1 = acc_u[mf][nfi][h * 2 + 1] + bx[col + 1];
                float g0 = sigmoidf_(acc_g[mf][nfi][h * 2 + 0] + bg[col]);
                float g1 = sigmoidf_(acc_g[mf][nfi][h * 2 + 1] + bg[col + 1]);
                *(float2*)&Cu[(size_t)row * N + col] = make_float2(u0, u1);
                *(float2*)&Cg[(size_t)row * N + col] = make_float2(g0, g1);
            }
        }
    }
}

// ---------------- HMMA GEMM (NT terms): MODE 0 raw, MODE 2 softplus colsums --
template <int MODE, int NT>
__global__ __launch_bounds__(256, 1) void gemm_bf16x3(
    const __nv_bfloat16* __restrict__ Ahi, const __nv_bfloat16* __restrict__ Alo,
    const __nv_bfloat16* __restrict__ Bhi, const __nv_bfloat16* __restrict__ Blo,
    const float* __restrict__ bias, float* __restrict__ C,
    float* __restrict__ colsum, int M, int N, int K)
{
    extern __shared__ char smem[];
    const uint32_t sb = smem_u32(smem);
    const int tid = threadIdx.x;
    const int wid = tid >> 5, lane = tid & 31;
    const int wm = wid & 1, wn = wid >> 1;
    const int am0 = blockIdx.y * BM;
    const int bn0 = blockIdx.x * BN;
    const int lseg = tid & 7;
    const int lrow = tid >> 3;

    auto load_chunk = [&](int ch) {
        uint32_t st = sb + (uint32_t)(ch % NSTAGE) * STAGE_B;
        int kb = ch * BKE + lseg * 8;
#pragma unroll
        for (int rb = 0; rb < 128; rb += 32) {
            int row = lrow + rb;
            uint32_t off = (uint32_t)row * RB + (uint32_t)lseg * 16u;
            uint32_t sw = off ^ ((off >> 3) & 0x70);
            size_t ga = (size_t)(am0 + row) * K + kb;
            size_t gb = (size_t)(bn0 + row) * K + kb;
            cpasync16(st + 0 * TILE_B + sw, Ahi + ga);
            cpasync16(st + 2 * TILE_B + sw, Bhi + gb);
            if (NT == 3) {
                cpasync16(st + 1 * TILE_B + sw, Alo + ga);
                cpasync16(st + 3 * TILE_B + sw, Blo + gb);
            }
        }
    };

    float acc[4][4][4];
#pragma unroll
    for (int i = 0; i < 4; i++)
#pragma unroll
        for (int j = 0; j < 4; j++)
#pragma unroll
            for (int v = 0; v < 4; v++) acc[i][j][v] = 0.f;

    const int arA = wm * 64 + (lane & 15);
    const int ahalf = lane >> 4;
    const uint32_t axor = (uint32_t)(arA & 7);
    uint32_t aoff[4];
#pragma unroll
    for (int mf = 0; mf < 4; mf++) aoff[mf] = (uint32_t)(arA + mf * 16) * RB;

    const int nrB = wn * 32 + (lane & 7) + ((lane >> 4) << 3);
    const int khalf = (lane >> 3) & 1;
    const uint32_t bxor = (uint32_t)(nrB & 7);
    uint32_t boff[2];
#pragma unroll
    for (int nf = 0; nf < 2; nf++) boff[nf] = (uint32_t)(nrB + nf * 16) * RB;

    const int NCH = K / BKE;
    load_chunk(0);
    asm volatile("cp.async.commit_group;");
    load_chunk(1);
    asm volatile("cp.async.commit_group;");

    for (int ch = 0; ch < NCH; ch++) {
        asm volatile("cp.async.wait_group 1;" ::: "memory");
        __syncthreads();
        const uint32_t st = sb + (uint32_t)(ch % NSTAGE) * STAGE_B;

#pragma unroll
        for (int ks = 0; ks < 4; ks++) {
            uint32_t a[4][4], bh[4][2], bl[4][2];
            const uint32_t asg = (((uint32_t)(ks * 2 + ahalf)) ^ axor) << 4;
            const uint32_t bsg = (((uint32_t)(ks * 2 + khalf)) ^ bxor) << 4;
#pragma unroll
            for (int nf = 0; nf < 2; nf++) {
                uint32_t rr[4];
                ldm_x4(rr, st + 2 * TILE_B + boff[nf] + bsg);
                bh[nf * 2 + 0][0] = rr[0]; bh[nf * 2 + 0][1] = rr[1];
                bh[nf * 2 + 1][0] = rr[2]; bh[nf * 2 + 1][1] = rr[3];
                if (NT == 3) {
                    ldm_x4(rr, st + 3 * TILE_B + boff[nf] + bsg);
                    bl[nf * 2 + 0][0] = rr[0]; bl[nf * 2 + 0][1] = rr[1];
                    bl[nf * 2 + 1][0] = rr[2]; bl[nf * 2 + 1][1] = rr[3];
                }
            }
#pragma unroll
            for (int mf = 0; mf < 4; mf++) {
                ldm_x4(a[mf], st + 0 * TILE_B + aoff[mf] + asg);
#pragma unroll
                for (int nfi = 0; nfi < 4; nfi++) {
                    mma_bf16(acc[mf][nfi], a[mf], bh[nfi]);
                    if (NT == 3) mma_bf16(acc[mf][nfi], a[mf], bl[nfi]);
                }
            }
            if (NT == 3) {
#pragma unroll
                for (int mf = 0; mf < 4; mf++) {
                    ldm_x4(a[mf], st + 1 * TILE_B + aoff[mf] + asg);
#pragma unroll
                    for (int nfi = 0; nfi < 4; nfi++)
                        mma_bf16(acc[mf][nfi], a[mf], bh[nfi]);
                }
            }
        }

        if (ch + 2 < NCH) load_chunk(ch + 2);
        asm volatile("cp.async.commit_group;");
    }

    if (MODE == 2) {
        __syncthreads();
        float* red = (float*)smem;
#pragma unroll
        for (int nfi = 0; nfi < 4; nfi++) {
            const int colb = bn0 + wn * 32 + nfi * 8 + (lane & 3) * 2;
            const float b0 = bias[colb], b1 = bias[colb + 1];
            float s0 = 0.f, s1 = 0.f;
#pragma unroll
            for (int mf = 0; mf < 4; mf++) {
                s0 += softplusf(acc[mf][nfi][0] + b0);
                s1 += softplusf(acc[mf][nfi][1] + b1);
                s0 += softplusf(acc[mf][nfi][2] + b0);
                s1 += softplusf(acc[mf][nfi][3] + b1);
            }
#pragma unroll
            for (int o = 4; o <= 16; o <<= 1) {
                s0 += __shfl_xor_sync(0xffffffffu, s0, o);
                s1 += __shfl_xor_sync(0xffffffffu, s1, o);
            }
            if (lane < 4) {
                int c = wn * 32 + nfi * 8 + lane * 2;
                red[wm * 128 + c] = s0;
                red[wm * 128 + c + 1] = s1;
            }
        }
        __syncthreads();
        if (tid < 128)
            colsum[(size_t)blockIdx.y * N + bn0 + tid] =
                red[tid] + red[128 + tid];
    } else {
#pragma unroll
        for (int mf = 0; mf < 4; mf++) {
            const int r0 = am0 + wm * 64 + mf * 16 + (lane >> 2);
#pragma unroll
            for (int h = 0; h < 2; h++) {
                const int row = r0 + h * 8;
#pragma unroll
                for (int nfi = 0; nfi < 4; nfi++) {
                    const int col = bn0 + wn * 32 + nfi * 8 + (lane & 3) * 2;
                    float v0 = acc[mf][nfi][h * 2 + 0] + bias[col];
                    float v1 = acc[mf][nfi][h * 2 + 1] + bias[col + 1];
                    *(float2*)&C[(size_t)row * N + col] = make_float2(v0, v1);
                }
            }
        }
    }
}

// ---------------- dt finalize + discretization --------------------------------
__global__ void disc_kernel(const float* __restrict__ A_raw,
                            const float* __restrict__ B_ssm)
{
    int idx = blockIdx.x * blockDim.x + threadIdx.x;
    if (idx >= HIDDEN * D_STATE) return;
    int h = idx / D_STATE;
    float sum = 0.f;
#pragma unroll
    for (int p = 0; p < MTOK / BM; p++) sum += g_dtpart[p * HIDDEN + h];
    float dt = sum * (1.f / (float)MTOK);
    dt = fminf(fmaxf(dt, 1e-3f), 2.0f);
    float a = -softplusf(A_raw[idx]);
    float ad = expf(a * dt);
    float bd = (ad - 1.0f) / (a + 1e-6f) * B_ssm[idx];
    g_Ad[idx] = ad;
    g_Bd[idx] = bd;
}

// ---------------- depthwise conv + gate (float4) -----------------------------
__global__ __launch_bounds__(256) void combine_kernel(
    const float* __restrict__ conv_w, const float* __restrict__ conv_b)
{
    int i4 = blockIdx.x * blockDim.x + threadIdx.x;   // < M*H/4
    int idx = i4 * 4;
    int h = idx & (HIDDEN - 1);
    int l = (idx >> 11) & (SEQ - 1);
    const float4* u4 = (const float4*)g_u;
    float4* g4 = (float4*)g_g;
    float4 u0 = u4[i4];
    float4 um = (l > 0) ? u4[i4 - HIDDEN / 4] : make_float4(0.f, 0.f, 0.f, 0.f);
    float4 up = (l < SEQ - 1) ? u4[i4 + HIDDEN / 4] : make_float4(0.f, 0.f, 0.f, 0.f);
    float4 g = g4[i4];
    float r[4];
    const float* uu0 = (const float*)&u0;
    const float* uum = (const float*)&um;
    const float* uup = (const float*)&up;
    const float* gg = (const float*)&g;
#pragma unroll
    for (int q = 0; q < 4; q++) {
        int hh = h + q;
        float hc = conv_b[hh]
                 + conv_w[hh * 3 + 0] * uum[q]
                 + conv_w[hh * 3 + 1] * uu0[q]
                 + conv_w[hh * 3 + 2] * uup[q];
        r[q] = uu0[q] * gg[q] + hc * (1.f - gg[q]);
    }
    g4[i4] = make_float4(r[0], r[1], r[2], r[3]);
}

// ---------------- scan pass 1: chunk-local scan ------------------------------
// thread = (b, c, h); reads g_g, writes y_local (fp32, into g_u) + final state
__global__ __launch_bounds__(128) void scan1_kernel(const float* __restrict__ C_ssm)
{
    int idx = blockIdx.x * blockDim.x + threadIdx.x;  // < BATCH*NCHK*HIDDEN
    int h = idx & (HIDDEN - 1);
    int bc = idx >> 11;                               // b*NCHK + c
    int c = bc & (NCHK - 1);
    int b = bc >> 4;

    float ad[D_STATE], bd[D_STATE], cc[D_STATE], st[D_STATE];
#pragma unroll
    for (int j = 0; j < D_STATE; j++) {
        ad[j] = g_Ad[h * D_STATE + j];
        bd[j] = g_Bd[h * D_STATE + j];
        cc[j] = C_ssm[h * D_STATE + j];
        st[j] = 0.f;
    }
    const size_t base = ((size_t)b * SEQ + (size_t)c * CHK) * HIDDEN + h;
    const float* up = g_g + base;
    float* yp = g_u + base;

    float pf[4];
#pragma unroll
    for (int q = 0; q < 4; q++) pf[q] = up[(size_t)q * HIDDEN];

    for (int t = 0; t < CHK; t += 4) {
#pragma unroll
        for (int q = 0; q < 4; q++) {
            float ucur = pf[q];
            int tn = t + 4 + q;
            pf[q] = (tn < CHK) ? up[(size_t)tn * HIDDEN] : 0.f;
            float y0 = 0.f, y1 = 0.f, y2 = 0.f, y3 = 0.f;
#pragma unroll
            for (int j = 0; j < D_STATE; j++)
                st[j] = fmaf(ad[j], st[j], bd[j] * ucur);
#pragma unroll
            for (int j = 0; j < D_STATE; j += 4) {
                y0 = fmaf(st[j + 0], cc[j + 0], y0);
                y1 = fmaf(st[j + 1], cc[j + 1], y1);
                y2 = fmaf(st[j + 2], cc[j + 2], y2);
                y3 = fmaf(st[j + 3], cc[j + 3], y3);
            }
            yp[(size_t)(t + q) * HIDDEN] = (y0 + y1) + (y2 + y3);
        }
    }
    float* sp = g_state + (size_t)idx * D_STATE;
#pragma unroll
    for (int j = 0; j < D_STATE; j += 4)
        *(float4*)&sp[j] = make_float4(st[j], st[j + 1], st[j + 2], st[j + 3]);
}

// ---------------- scan pass 2: chunk-state prefix ----------------------------
// thread = (b, h, j)
__global__ __launch_bounds__(256) void scan2_kernel()
{
    int idx = blockIdx.x * blockDim.x + threadIdx.x;  // < BATCH*HIDDEN*16
    int j = idx & (D_STATE - 1);
    int h = (idx >> 4) & (HIDDEN - 1);
    int b = idx >> 15;

    float ad = g_Ad[h * D_STATE + j];
    float af = ad;
#pragma unroll
    for (int i = 0; i < 7; i++) af = af * af;     // ad^128

    float carry = 0.f;
#pragma unroll
    for (int c = 0; c < NCHK; c++) {
        size_t off = (((size_t)b * NCHK + c) * HIDDEN + h) * D_STATE + j;
        g_init[off] = carry;
        carry = fmaf(af, carry, g_state[off]);
    }
}

// ---------------- scan pass 3: fixup + bf16 split ----------------------------
// thread = (b, c, h); y = y_local + C . (A^(tau+1) * s_init)
__global__ __launch_bounds__(128) void scan3_kernel(const float* __restrict__ C_ssm)
{
    int idx = blockIdx.x * blockDim.x + threadIdx.x;
    int h = idx & (HIDDEN - 1);
    int bc = idx >> 11;
    int c = bc & (NCHK - 1);
    int b = bc >> 4;

    const size_t base = ((size_t)b * SEQ + (size_t)c * CHK) * HIDDEN + h;
    const float* yp = g_u + base;
    __nv_bfloat16* yh = g_yhi + base;
    __nv_bfloat16* yl = g_ylo + base;

    if (c == 0) {
        for (int t = 0; t < CHK; t++) {
            float yv = yp[(size_t)t * HIDDEN];
            __nv_bfloat16 hi = __float2bfloat16(yv);
            __nv_bfloat16 lo = __float2bfloat16(yv - __bfloat162float(hi));
            yh[(size_t)t * HIDDEN] = hi;
            yl[(size_t)t * HIDDEN] = lo;
        }
        return;
    }

    float ad[D_STATE], cc[D_STATE], p[D_STATE];
    const float* ip = g_init + (size_t)idx * D_STATE;
#pragma unroll
    for (int j = 0; j < D_STATE; j++) {
        ad[j] = g_Ad[h * D_STATE + j];
        cc[j] = C_ssm[h * D_STATE + j];
        p[j] = ip[j];
    }
    for (int t = 0; t < CHK; t++) {
        float y0 = 0.f, y1 = 0.f, y2 = 0.f, y3 = 0.f;
#pragma unroll
        for (int j = 0; j < D_STATE; j++) p[j] *= ad[j];
#pragma unroll
        for (int j = 0; j < D_STATE; j += 4) {
            y0 = fmaf(p[j + 0], cc[j + 0], y0);
            y1 = fmaf(p[j + 1], cc[j + 1], y1);
            y2 = fmaf(p[j + 2], cc[j + 2], y2);
            y3 = fmaf(p[j + 3], cc[j + 3], y3);
        }
        float yv = yp[(size_t)t * HIDDEN] + ((y0 + y1) + (y2 + y3));
        __nv_bfloat16 hi = __float2bfloat16(yv);
        __nv_bfloat16 lo = __float2bfloat16(yv - __bfloat162float(hi));
        yh[(size_t)t * HIDDEN] = hi;
        yl[(size_t)t * HIDDEN] = lo;
    }
}

// ---------------- residual + layernorm ---------------------------------------
__global__ __launch_bounds__(256) void ln_kernel(
    const float* __restrict__ x, const float* __restrict__ lng,
    const float* __restrict__ lnb, float* __restrict__ out)
{
    int row = blockIdx.x;
    __shared__ float sh[D_MODEL];
    __shared__ float rs[20];
    const float* xr = x + (size_t)row * D_MODEL;
    const float* orow = g_outp + (size_t)row * D_MODEL;
    int tid = threadIdx.x;

    float s = 0.f, sq = 0.f;
    for (int i = tid; i < D_MODEL; i += 256) {
        float r = xr[i] + orow[i];
        sh[i] = r;
        s += r;
        sq += r * r;
    }
#pragma unroll
    for (int o = 16; o > 0; o >>= 1) {
        s += __shfl_xor_sync(0xffffffffu, s, o);
        sq += __shfl_xor_sync(0xffffffffu, sq, o);
    }
    int w = tid >> 5, ln = tid & 31;
    if (ln == 0) { rs[w] = s; rs[8 + w] = sq; }
    __syncthreads();
    if (tid == 0) {
        float ts = 0.f, tq = 0.f;
#pragma unroll
        for (int i = 0; i < 8; i++) { ts += rs[i]; tq += rs[8 + i]; }
        float mean = ts * (1.f / (float)D_MODEL);
        float var = tq * (1.f / (float)D_MODEL) - mean * mean;
        rs[16] = mean;
        rs[17] = rsqrtf(var + 1e-5f);
    }
    __syncthreads();
    float mean = rs[16], inv = rs[17];
    for (int i = tid; i < D_MODEL; i += 256)
        out[(size_t)row * D_MODEL + i] = (sh[i] - mean) * inv * lng[i] + lnb[i];
}

// ---------------- launch -----------------------------------------------------
extern "C" void kernel_launch(void* const* d_in, const int* in_sizes, int n_in,
                              void* d_out, int out_size)
{
    const float* x      = (const float*)d_in[0];
    const float* W_x    = (const float*)d_in[1];
    const float* b_x    = (const float*)d_in[2];
    const float* W_g    = (const float*)d_in[3];
    const float* b_g    = (const float*)d_in[4];
    const float* conv_w = (const float*)d_in[5];
    const float* conv_b = (const float*)d_in[6];
    const float* A_raw  = (const float*)d_in[7];
    const float* B_ssm  = (const float*)d_in[8];
    const float* C_ssm  = (const float*)d_in[9];
    const float* W_dt   = (const float*)d_in[10];
    const float* b_dt   = (const float*)d_in[11];
    const float* W_out  = (const float*)d_in[12];
    const float* b_out  = (const float*)d_in[13];
    const float* ln_g   = (const float*)d_in[14];
    const float* ln_b   = (const float*)d_in[15];
    float* out = (float*)d_out;

    float *pu, *pg, *pdt, *pout;
    __nv_bfloat16 *pxh, *pxl, *pwxh, *pwxl, *pwgh, *pwgl, *pwdh, *pwdl,
                  *pwoh, *pwol, *pyh, *pyl;
    cudaGetSymbolAddress((void**)&pu, g_u);
    cudaGetSymbolAddress((void**)&pg, g_g);
    cudaGetSymbolAddress((void**)&pdt, g_dtpart);
    cudaGetSymbolAddress((void**)&pout, g_outp);
    cudaGetSymbolAddress((void**)&pxh, g_xhi);
    cudaGetSymbolAddress((void**)&pxl, g_xlo);
    cudaGetSymbolAddress((void**)&pwxh, g_wxhi);
    cudaGetSymbolAddress((void**)&pwxl, g_wxlo);
    cudaGetSymbolAddress((void**)&pwgh, g_wghi);
    cudaGetSymbolAddress((void**)&pwgl, g_wglo);
    cudaGetSymbolAddress((void**)&pwdh, g_wdthi);
    cudaGetSymbolAddress((void**)&pwdl, g_wdtlo);
    cudaGetSymbolAddress((void**)&pwoh, g_wohi);
    cudaGetSymbolAddress((void**)&pwol, g_wolo);
    cudaGetSymbolAddress((void**)&pyh, g_yhi);
    cudaGetSymbolAddress((void**)&pyl, g_ylo);

    cudaFuncSetAttribute(gemm_ug, cudaFuncAttributeMaxDynamicSharedMemorySize, SMEM_UG);
    cudaFuncSetAttribute(gemm_bf16x3<0, 3>, cudaFuncAttributeMaxDynamicSharedMemorySize, SMEM_GEMM);
    cudaFuncSetAttribute(gemm_bf16x3<2, 1>, cudaFuncAttributeMaxDynamicSharedMemorySize, SMEM_GEMM);

    auto splitN = [&](const float* src, __nv_bfloat16* hi, __nv_bfloat16* lo, int n) {
        int n4 = n / 4;
        split_kernel<<<(n4 + 255) / 256, 256>>>((const float4*)src,
                                                (__nv_bfloat162*)hi,
                                                (__nv_bfloat162*)lo, n4);
    };
    splitN(x,     pxh, pxl, MTOK * D_MODEL);
    splitN(W_x,   pwxh, pwxl, HIDDEN * D_MODEL);
    splitN(W_g,   pwgh, pwgl, HIDDEN * D_MODEL);
    splitN(W_dt,  pwdh, pwdl, HIDDEN * D_MODEL);
    splitN(W_out, pwoh, pwol, D_MODEL * HIDDEN);

    dim3 gridH(HIDDEN / BN, MTOK / BM);    // (16, 32)
    dim3 gridD(D_MODEL / BN, MTOK / BM);   // (8, 32)

    gemm_ug<<<gridH, 256, SMEM_UG>>>(pxh, pxl, pwxh, pwxl, pwgh, pwgl,
                                     b_x, b_g, pu, pg, MTOK, HIDDEN, D_MODEL);
    gemm_bf16x3<2, 1><<<gridH, 256, SMEM_GEMM>>>(pxh, pxl, pwdh, pwdl, b_dt,
                                                 nullptr, pdt, MTOK, HIDDEN, D_MODEL);

    disc_kernel<<<(HIDDEN * D_STATE + 255) / 256, 256>>>(A_raw, B_ssm);
    combine_kernel<<<(MTOK * HIDDEN / 4) / 256, 256>>>(conv_w, conv_b);

    scan1_kernel<<<(BATCH * NCHK * HIDDEN) / 128, 128>>>(C_ssm);
    scan2_kernel<<<(BATCH * HIDDEN * D_STATE) / 256, 256>>>();
    scan3_kernel<<<(BATCH * NCHK * HIDDEN) / 128, 128>>>(C_ssm);

    gemm_bf16x3<0, 3><<<gridD, 256, SMEM_GEMM>>>(pyh, pyl, pwoh, pwol, b_out, pout,
                                                 nullptr, MTOK, D_MODEL, HIDDEN);

    ln_kernel<<<MTOK, 256>>>(x, ln_g, ln_b, out);
}

// round 6
// speedup vs baseline: 3.8675x; 1.0959x over previous
#include <cuda_runtime.h>
#include <cuda_bf16.h>
#include <cuda.h>
#include <dlfcn.h>
#include <cstdint>

#define D_MODEL 1024
#define HIDDEN  2048
#define D_STATE 16
#define BATCH   2
#define SEQ     2048
#define MTOK    4096
#define NCHK    16
#define CHK     128

// ---------------- GEMM tiling -------------------------------------------------
#define BM 128
#define BN 128
#define BKE 64
#define RB 128
#define TILE_B (128 * 128)
#define UG_STAGE (6 * TILE_B)                 // Ahi,Alo,Xhi,Xlo,Ghi,Glo
#define SMEM_UG (2 * UG_STAGE + 1024)         // 197632
#define SMEM_G3 (2 * 4 * TILE_B + 1024)       // 132096
#define SMEM_G1 (2 * 2 * TILE_B + 1024)       // 66560

// ---------------- scratch ----------------------------------------------------
__device__ float g_u[(size_t)MTOK * HIDDEN];      // u projection (read-only after ug GEMM)
__device__ float g_g[(size_t)MTOK * HIDDEN];      // gate, then y_local (fp32)
__device__ float g_outp[(size_t)MTOK * D_MODEL];
__device__ float g_dtpart[(MTOK / BM) * HIDDEN];
__device__ float g_Ad[HIDDEN * D_STATE];
__device__ float g_Bd[HIDDEN * D_STATE];
__device__ float g_state[(size_t)BATCH * NCHK * HIDDEN * D_STATE];
__device__ float g_init[(size_t)BATCH * NCHK * HIDDEN * D_STATE];

__device__ __nv_bfloat16 g_xhi[(size_t)MTOK * D_MODEL];
__device__ __nv_bfloat16 g_xlo[(size_t)MTOK * D_MODEL];
__device__ __nv_bfloat16 g_wxhi[HIDDEN * D_MODEL];
__device__ __nv_bfloat16 g_wxlo[HIDDEN * D_MODEL];
__device__ __nv_bfloat16 g_wghi[HIDDEN * D_MODEL];
__device__ __nv_bfloat16 g_wglo[HIDDEN * D_MODEL];
__device__ __nv_bfloat16 g_wdthi[HIDDEN * D_MODEL];
__device__ __nv_bfloat16 g_wohi[D_MODEL * HIDDEN];
__device__ __nv_bfloat16 g_wolo[D_MODEL * HIDDEN];
__device__ __nv_bfloat16 g_yhi[(size_t)MTOK * HIDDEN];
__device__ __nv_bfloat16 g_ylo[(size_t)MTOK * HIDDEN];

// ---------------- helpers ----------------------------------------------------
__device__ __forceinline__ float softplusf(float x) {
    return fmaxf(x, 0.f) + log1pf(expf(-fabsf(x)));
}
__device__ __forceinline__ float sigmoidf_(float x) {
    return 1.f / (1.f + expf(-x));
}
__device__ __forceinline__ uint32_t smem_u32(const void* p) {
    uint32_t a;
    asm("{ .reg .u64 t; cvta.to.shared.u64 t, %1; cvt.u32.u64 %0, t; }"
        : "=r"(a) : "l"(p));
    return a;
}
__device__ __forceinline__ void ldm_x4(uint32_t* r, uint32_t addr) {
    asm volatile("ldmatrix.sync.aligned.m8n8.x4.shared.b16 {%0,%1,%2,%3}, [%4];"
                 : "=r"(r[0]), "=r"(r[1]), "=r"(r[2]), "=r"(r[3]) : "r"(addr));
}
__device__ __forceinline__ void mma_bf16(float* d, const uint32_t* a,
                                         const uint32_t* b) {
    asm volatile(
        "mma.sync.aligned.m16n8k16.row.col.f32.bf16.bf16.f32 "
        "{%0,%1,%2,%3}, {%4,%5,%6,%7}, {%8,%9}, {%0,%1,%2,%3};"
        : "+f"(d[0]), "+f"(d[1]), "+f"(d[2]), "+f"(d[3])
        : "r"(a[0]), "r"(a[1]), "r"(a[2]), "r"(a[3]), "r"(b[0]), "r"(b[1]));
}
__device__ __forceinline__ void mbar_init(uint32_t addr) {
    asm volatile("mbarrier.init.shared.b64 [%0], 1;" :: "r"(addr) : "memory");
}
__device__ __forceinline__ void mbar_expect(uint32_t addr, uint32_t bytes) {
    asm volatile("mbarrier.arrive.expect_tx.shared.b64 _, [%0], %1;"
                 :: "r"(addr), "r"(bytes) : "memory");
}
__device__ __forceinline__ void mbar_wait(uint32_t addr, uint32_t parity) {
    asm volatile(
        "{\n\t.reg .pred P;\n\t"
        "W_%=:\n\t"
        "mbarrier.try_wait.parity.acquire.cta.shared::cta.b64 P, [%0], %1, 0x989680;\n\t"
        "@P bra D_%=;\n\t"
        "bra W_%=;\n\t"
        "D_%=:\n\t}"
        :: "r"(addr), "r"(parity) : "memory");
}
__device__ __forceinline__ void tma2d(uint32_t smaddr, const CUtensorMap* m,
                                      int cx, int cy, uint32_t mbar) {
    asm volatile(
        "cp.async.bulk.tensor.2d.shared::cta.global.tile.mbarrier::complete_tx::bytes "
        "[%0], [%1, {%2, %3}], [%4];"
        :: "r"(smaddr), "l"(m), "r"(cx), "r"(cy), "r"(mbar) : "memory");
}

// ---------------- fp32 -> bf16 hi/lo split -----------------------------------
__global__ __launch_bounds__(256) void split_kernel(
    const float4* __restrict__ src, __nv_bfloat162* __restrict__ hi,
    __nv_bfloat162* __restrict__ lo, int n4)
{
    int i = blockIdx.x * blockDim.x + threadIdx.x;
    if (i >= n4) return;
    float4 v = src[i];
    __nv_bfloat16 h0 = __float2bfloat16(v.x);
    __nv_bfloat16 h1 = __float2bfloat16(v.y);
    __nv_bfloat16 h2 = __float2bfloat16(v.z);
    __nv_bfloat16 h3 = __float2bfloat16(v.w);
    hi[i * 2 + 0] = __nv_bfloat162(h0, h1);
    hi[i * 2 + 1] = __nv_bfloat162(h2, h3);
    if (lo) {
        __nv_bfloat16 l0 = __float2bfloat16(v.x - __bfloat162float(h0));
        __nv_bfloat16 l1 = __float2bfloat16(v.y - __bfloat162float(h1));
        __nv_bfloat16 l2 = __float2bfloat16(v.z - __bfloat162float(h2));
        __nv_bfloat16 l3 = __float2bfloat16(v.w - __bfloat162float(h3));
        lo[i * 2 + 0] = __nv_bfloat162(l0, l1);
        lo[i * 2 + 1] = __nv_bfloat162(l2, l3);
    }
}

// ---------------- fused u + gate GEMM (TMA, 2-stage, 6 tiles) ----------------
__global__ __launch_bounds__(256, 1) void gemm_ug_tma(
    const __grid_constant__ CUtensorMap mAh, const __grid_constant__ CUtensorMap mAl,
    const __grid_constant__ CUtensorMap mXh, const __grid_constant__ CUtensorMap mXl,
    const __grid_constant__ CUtensorMap mGh, const __grid_constant__ CUtensorMap mGl,
    const float* __restrict__ bx, const float* __restrict__ bg,
    float* __restrict__ Cu, float* __restrict__ Cg)
{
    const int N = HIDDEN;
    extern __shared__ char smraw[];
    uint32_t sb = (smem_u32(smraw) + 1023u) & ~1023u;
    __shared__ uint64_t mbarS[2];
    uint32_t mb = smem_u32(mbarS);

    const int tid = threadIdx.x;
    const int wid = tid >> 5, lane = tid & 31;
    const int wm = wid & 1, wn = wid >> 1;
    const int am0 = blockIdx.y * BM;
    const int bn0 = blockIdx.x * BN;

    if (tid == 0) { mbar_init(mb); mbar_init(mb + 8); }
    __syncthreads();

    auto issue = [&](int s) {
        if (tid != 0) return;
        uint32_t bar = mb + (uint32_t)(s & 1) * 8;
        mbar_expect(bar, UG_STAGE);
        uint32_t st = sb + (uint32_t)(s & 1) * UG_STAGE;
        int kc = s * BKE;
        tma2d(st + 0 * TILE_B, &mAh, kc, am0, bar);
        tma2d(st + 1 * TILE_B, &mAl, kc, am0, bar);
        tma2d(st + 2 * TILE_B, &mXh, kc, bn0, bar);
        tma2d(st + 3 * TILE_B, &mXl, kc, bn0, bar);
        tma2d(st + 4 * TILE_B, &mGh, kc, bn0, bar);
        tma2d(st + 5 * TILE_B, &mGl, kc, bn0, bar);
    };
    issue(0); issue(1);

    float acc_u[4][4][4], acc_g[4][4][4];
#pragma unroll
    for (int i = 0; i < 4; i++)
#pragma unroll
        for (int j = 0; j < 4; j++)
#pragma unroll
            for (int v = 0; v < 4; v++) { acc_u[i][j][v] = 0.f; acc_g[i][j][v] = 0.f; }

    const int arA = wm * 64 + (lane & 15);
    const int ahalf = lane >> 4;
    const uint32_t axor = (uint32_t)(arA & 7);
    uint32_t aoff[4];
#pragma unroll
    for (int mf = 0; mf < 4; mf++) aoff[mf] = (uint32_t)(arA + mf * 16) * RB;

    const int nrB = wn * 32 + (lane & 7) + ((lane >> 4) << 3);
    const int khalf = (lane >> 3) & 1;
    const uint32_t bxor = (uint32_t)(nrB & 7);
    uint32_t boff[2];
#pragma unroll
    for (int nf = 0; nf < 2; nf++) boff[nf] = (uint32_t)(nrB + nf * 16) * RB;

    const int NCH = D_MODEL / BKE;   // 16
    for (int ch = 0; ch < NCH; ch++) {
        mbar_wait(mb + (uint32_t)(ch & 1) * 8, (uint32_t)((ch >> 1) & 1));
        const uint32_t st = sb + (uint32_t)(ch & 1) * UG_STAGE;

#pragma unroll
        for (int ks = 0; ks < 4; ks++) {
            const uint32_t asg = (((uint32_t)(ks * 2 + ahalf)) ^ axor) << 4;
            const uint32_t bsg = (((uint32_t)(ks * 2 + khalf)) ^ bxor) << 4;
            uint32_t ah[4][4], al[4][4];
#pragma unroll
            for (int mf = 0; mf < 4; mf++) {
                ldm_x4(ah[mf], st + 0 * TILE_B + aoff[mf] + asg);
                ldm_x4(al[mf], st + 1 * TILE_B + aoff[mf] + asg);
            }
#pragma unroll
            for (int w = 0; w < 2; w++) {
                uint32_t bh[4][2], bl[4][2];
#pragma unroll
                for (int nf = 0; nf < 2; nf++) {
                    uint32_t rr[4];
                    ldm_x4(rr, st + (2 + 2 * w) * TILE_B + boff[nf] + bsg);
                    bh[nf * 2 + 0][0] = rr[0]; bh[nf * 2 + 0][1] = rr[1];
                    bh[nf * 2 + 1][0] = rr[2]; bh[nf * 2 + 1][1] = rr[3];
                    ldm_x4(rr, st + (3 + 2 * w) * TILE_B + boff[nf] + bsg);
                    bl[nf * 2 + 0][0] = rr[0]; bl[nf * 2 + 0][1] = rr[1];
                    bl[nf * 2 + 1][0] = rr[2]; bl[nf * 2 + 1][1] = rr[3];
                }
                float (*acc)[4][4] = (w == 0) ? acc_u : acc_g;
#pragma unroll
                for (int mf = 0; mf < 4; mf++)
#pragma unroll
                    for (int nfi = 0; nfi < 4; nfi++) {
                        mma_bf16(acc[mf][nfi], ah[mf], bh[nfi]);
                        mma_bf16(acc[mf][nfi], ah[mf], bl[nfi]);
                        mma_bf16(acc[mf][nfi], al[mf], bh[nfi]);
                    }
            }
        }
        __syncthreads();
        if (ch + 2 < NCH) issue(ch + 2);
    }

#pragma unroll
    for (int mf = 0; mf < 4; mf++) {
        const int r0 = am0 + wm * 64 + mf * 16 + (lane >> 2);
#pragma unroll
        for (int h = 0; h < 2; h++) {
            const int row = r0 + h * 8;
#pragma unroll
            for (int nfi = 0; nfi < 4; nfi++) {
                const int col = bn0 + wn * 32 + nfi * 8 + (lane & 3) * 2;
                float u0 = acc_u[mf][nfi][h * 2 + 0] + bx[col];
                float u1 = acc_u[mf][nfi][h * 2 + 1] + bx[col + 1];
                float g0 = sigmoidf_(acc_g[mf][nfi][h * 2 + 0] + bg[col]);
                float g1 = sigmoidf_(acc_g[mf][nfi][h * 2 + 1] + bg[col + 1]);
                *(float2*)&Cu[(size_t)row * N + col] = make_float2(u0, u1);
                *(float2*)&Cg[(size_t)row * N + col] = make_float2(g0, g1);
            }
        }
    }
}

// ---------------- TMA GEMM (NT terms): MODE 0 raw, MODE 2 softplus colsums ---
template <int MODE, int NT>
__global__ __launch_bounds__(256, 1) void gemm_tma(
    const __grid_constant__ CUtensorMap mAh, const __grid_constant__ CUtensorMap mAl,
    const __grid_constant__ CUtensorMap mBh, const __grid_constant__ CUtensorMap mBl,
    const float* __restrict__ bias, float* __restrict__ C,
    float* __restrict__ colsum, int N, int K)
{
    constexpr uint32_t STAGE = (NT == 3 ? 4 : 2) * TILE_B;
    constexpr uint32_t ALOFF = 1 * TILE_B;
    constexpr uint32_t BHOFF = (NT == 3 ? 2 : 1) * TILE_B;
    constexpr uint32_t BLOFF = 3 * TILE_B;

    extern __shared__ char smraw[];
    uint32_t sb = (smem_u32(smraw) + 1023u) & ~1023u;
    __shared__ uint64_t mbarS[2];
    uint32_t mb = smem_u32(mbarS);

    const int tid = threadIdx.x;
    const int wid = tid >> 5, lane = tid & 31;
    const int wm = wid & 1, wn = wid >> 1;
    const int am0 = blockIdx.y * BM;
    const int bn0 = blockIdx.x * BN;

    if (tid == 0) { mbar_init(mb); mbar_init(mb + 8); }
    __syncthreads();

    auto issue = [&](int s) {
        if (tid != 0) return;
        uint32_t bar = mb + (uint32_t)(s & 1) * 8;
        mbar_expect(bar, STAGE);
        uint32_t st = sb + (uint32_t)(s & 1) * STAGE;
        int kc = s * BKE;
        tma2d(st, &mAh, kc, am0, bar);
        tma2d(st + BHOFF, &mBh, kc, bn0, bar);
        if (NT == 3) {
            tma2d(st + ALOFF, &mAl, kc, am0, bar);
            tma2d(st + BLOFF, &mBl, kc, bn0, bar);
        }
    };
    issue(0); issue(1);

    float acc[4][4][4];
#pragma unroll
    for (int i = 0; i < 4; i++)
#pragma unroll
        for (int j = 0; j < 4; j++)
#pragma unroll
            for (int v = 0; v < 4; v++) acc[i][j][v] = 0.f;

    const int arA = wm * 64 + (lane & 15);
    const int ahalf = lane >> 4;
    const uint32_t axor = (uint32_t)(arA & 7);
    uint32_t aoff[4];
#pragma unroll
    for (int mf = 0; mf < 4; mf++) aoff[mf] = (uint32_t)(arA + mf * 16) * RB;

    const int nrB = wn * 32 + (lane & 7) + ((lane >> 4) << 3);
    const int khalf = (lane >> 3) & 1;
    const uint32_t bxor = (uint32_t)(nrB & 7);
    uint32_t boff[2];
#pragma unroll
    for (int nf = 0; nf < 2; nf++) boff[nf] = (uint32_t)(nrB + nf * 16) * RB;

    const int NCH = K / BKE;
    for (int ch = 0; ch < NCH; ch++) {
        mbar_wait(mb + (uint32_t)(ch & 1) * 8, (uint32_t)((ch >> 1) & 1));
        const uint32_t st = sb + (uint32_t)(ch & 1) * STAGE;

#pragma unroll
        for (int ks = 0; ks < 4; ks++) {
            uint32_t a[4][4], bh[4][2], bl[4][2];
            const uint32_t asg = (((uint32_t)(ks * 2 + ahalf)) ^ axor) << 4;
            const uint32_t bsg = (((uint32_t)(ks * 2 + khalf)) ^ bxor) << 4;
#pragma unroll
            for (int nf = 0; nf < 2; nf++) {
                uint32_t rr[4];
                ldm_x4(rr, st + BHOFF + boff[nf] + bsg);
                bh[nf * 2 + 0][0] = rr[0]; bh[nf * 2 + 0][1] = rr[1];
                bh[nf * 2 + 1][0] = rr[2]; bh[nf * 2 + 1][1] = rr[3];
                if (NT == 3) {
                    ldm_x4(rr, st + BLOFF + boff[nf] + bsg);
                    bl[nf * 2 + 0][0] = rr[0]; bl[nf * 2 + 0][1] = rr[1];
                    bl[nf * 2 + 1][0] = rr[2]; bl[nf * 2 + 1][1] = rr[3];
                }
            }
#pragma unroll
            for (int mf = 0; mf < 4; mf++) {
                ldm_x4(a[mf], st + aoff[mf] + asg);
#pragma unroll
                for (int nfi = 0; nfi < 4; nfi++) {
                    mma_bf16(acc[mf][nfi], a[mf], bh[nfi]);
                    if (NT == 3) mma_bf16(acc[mf][nfi], a[mf], bl[nfi]);
                }
            }
            if (NT == 3) {
#pragma unroll
                for (int mf = 0; mf < 4; mf++) {
                    ldm_x4(a[mf], st + ALOFF + aoff[mf] + asg);
#pragma unroll
                    for (int nfi = 0; nfi < 4; nfi++)
                        mma_bf16(acc[mf][nfi], a[mf], bh[nfi]);
                }
            }
        }
        __syncthreads();
        if (ch + 2 < NCH) issue(ch + 2);
    }

    if (MODE == 2) {
        float* red = (float*)smraw;
#pragma unroll
        for (int nfi = 0; nfi < 4; nfi++) {
            const int colb = bn0 + wn * 32 + nfi * 8 + (lane & 3) * 2;
            const float b0 = bias[colb], b1 = bias[colb + 1];
            float s0 = 0.f, s1 = 0.f;
#pragma unroll
            for (int mf = 0; mf < 4; mf++) {
                s0 += softplusf(acc[mf][nfi][0] + b0);
                s1 += softplusf(acc[mf][nfi][1] + b1);
                s0 += softplusf(acc[mf][nfi][2] + b0);
                s1 += softplusf(acc[mf][nfi][3] + b1);
            }
#pragma unroll
            for (int o = 4; o <= 16; o <<= 1) {
                s0 += __shfl_xor_sync(0xffffffffu, s0, o);
                s1 += __shfl_xor_sync(0xffffffffu, s1, o);
            }
            if (lane < 4) {
                int c = wn * 32 + nfi * 8 + lane * 2;
                red[wm * 128 + c] = s0;
                red[wm * 128 + c + 1] = s1;
            }
        }
        __syncthreads();
        if (tid < 128)
            colsum[(size_t)blockIdx.y * N + bn0 + tid] =
                red[tid] + red[128 + tid];
    } else {
#pragma unroll
        for (int mf = 0; mf < 4; mf++) {
            const int r0 = am0 + wm * 64 + mf * 16 + (lane >> 2);
#pragma unroll
            for (int h = 0; h < 2; h++) {
                const int row = r0 + h * 8;
#pragma unroll
                for (int nfi = 0; nfi < 4; nfi++) {
                    const int col = bn0 + wn * 32 + nfi * 8 + (lane & 3) * 2;
                    float v0 = acc[mf][nfi][h * 2 + 0] + bias[col];
                    float v1 = acc[mf][nfi][h * 2 + 1] + bias[col + 1];
                    *(float2*)&C[(size_t)row * N + col] = make_float2(v0, v1);
                }
            }
        }
    }
}

// ---------------- dt finalize + discretization --------------------------------
__global__ void disc_kernel(const float* __restrict__ A_raw,
                            const float* __restrict__ B_ssm)
{
    int idx = blockIdx.x * blockDim.x + threadIdx.x;
    if (idx >= HIDDEN * D_STATE) return;
    int h = idx / D_STATE;
    float sum = 0.f;
#pragma unroll
    for (int p = 0; p < MTOK / BM; p++) sum += g_dtpart[p * HIDDEN + h];
    float dt = sum * (1.f / (float)MTOK);
    dt = fminf(fmaxf(dt, 1e-3f), 2.0f);
    float a = -softplusf(A_raw[idx]);
    float ad = expf(a * dt);
    float bd = (ad - 1.0f) / (a + 1e-6f) * B_ssm[idx];
    g_Ad[idx] = ad;
    g_Bd[idx] = bd;
}

// ---------------- scan pass 1: fused conv+gate + chunk-local scan ------------
// thread = (b, c, h); reads g_u (read-only) + g_g (gate), writes y_local into
// g_g + final state into g_state.
__global__ __launch_bounds__(128) void scan1_kernel(
    const float* __restrict__ C_ssm, const float* __restrict__ conv_w,
    const float* __restrict__ conv_b)
{
    int idx = blockIdx.x * blockDim.x + threadIdx.x;  // < BATCH*NCHK*HIDDEN
    int h = idx & (HIDDEN - 1);
    int bc = idx >> 11;
    int c = bc & (NCHK - 1);

    float ad[D_STATE], bd[D_STATE], cc[D_STATE], st[D_STATE];
#pragma unroll
    for (int j = 0; j < D_STATE; j++) {
        ad[j] = g_Ad[h * D_STATE + j];
        bd[j] = g_Bd[h * D_STATE + j];
        cc[j] = C_ssm[h * D_STATE + j];
        st[j] = 0.f;
    }
    const float w0 = conv_w[h * 3 + 0], w1 = conv_w[h * 3 + 1],
                w2 = conv_w[h * 3 + 2], cb = conv_b[h];

    const int b = bc >> 4;
    const int l0 = c * CHK;
    const size_t base = ((size_t)b * SEQ + l0) * HIDDEN + h;
    const float* up = g_u + base;
    float* gp = g_g + base;    // gate in, y_local out (same thread, same strip)

    float um = (l0 > 0) ? up[-(ptrdiff_t)HIDDEN] : 0.f;
    float cu[4], cg[4];
#pragma unroll
    for (int q = 0; q < 4; q++) {
        cu[q] = up[(size_t)q * HIDDEN];
        cg[q] = gp[(size_t)q * HIDDEN];
    }

    for (int t = 0; t < CHK; t += 4) {
        float nu[4], ng[4];
#pragma unroll
        for (int q = 0; q < 4; q++) {
            int l = l0 + t + 4 + q;
            nu[q] = (l < SEQ) ? up[(size_t)(t + 4 + q) * HIDDEN] : 0.f;
            int tt = t + 4 + q;
            ng[q] = (tt < CHK) ? gp[(size_t)tt * HIDDEN] : 0.f;
        }
#pragma unroll
        for (int q = 0; q < 4; q++) {
            float u0 = cu[q];
            float upn = (q < 3) ? cu[q + 1] : nu[0];
            // zero beyond the sequence end is handled by nu guard (l<SEQ)
            float hc = cb + w0 * um + w1 * u0 + w2 * upn;
            float g = cg[q];
            float uc = u0 * g + hc * (1.f - g);
            float y0 = 0.f, y1 = 0.f, y2 = 0.f, y3 = 0.f;
#pragma unroll
            for (int j = 0; j < D_STATE; j++)
                st[j] = fmaf(ad[j], st[j], bd[j] * uc);
#pragma unroll
            for (int j = 0; j < D_STATE; j += 4) {
                y0 = fmaf(st[j + 0], cc[j + 0], y0);
                y1 = fmaf(st[j + 1], cc[j + 1], y1);
                y2 = fmaf(st[j + 2], cc[j + 2], y2);
                y3 = fmaf(st[j + 3], cc[j + 3], y3);
            }
            gp[(size_t)(t + q) * HIDDEN] = (y0 + y1) + (y2 + y3);
            um = u0;
        }
#pragma unroll
        for (int q = 0; q < 4; q++) { cu[q] = nu[q]; cg[q] = ng[q]; }
    }
    float* sp = g_state + (size_t)idx * D_STATE;
#pragma unroll
    for (int j = 0; j < D_STATE; j += 4)
        *(float4*)&sp[j] = make_float4(st[j], st[j + 1], st[j + 2], st[j + 3]);
}

// ---------------- scan pass 2: chunk-state prefix ----------------------------
__global__ __launch_bounds__(256) void scan2_kernel()
{
    int idx = blockIdx.x * blockDim.x + threadIdx.x;  // < BATCH*HIDDEN*16
    int j = idx & (D_STATE - 1);
    int h = (idx >> 4) & (HIDDEN - 1);
    int b = idx >> 15;

    float ad = g_Ad[h * D_STATE + j];
    float af = ad;
#pragma unroll
    for (int i = 0; i < 7; i++) af = af * af;     // ad^128

    float carry = 0.f;
#pragma unroll
    for (int c = 0; c < NCHK; c++) {
        size_t off = (((size_t)b * NCHK + c) * HIDDEN + h) * D_STATE + j;
        g_init[off] = carry;
        carry = fmaf(af, carry, g_state[off]);
    }
}

// ---------------- scan pass 3: fixup + bf16 split ----------------------------
__global__ __launch_bounds__(128) void scan3_kernel(const float* __restrict__ C_ssm)
{
    int idx = blockIdx.x * blockDim.x + threadIdx.x;
    int h = idx & (HIDDEN - 1);
    int bc = idx >> 11;
    int c = bc & (NCHK - 1);
    int b = bc >> 4;

    const size_t base = ((size_t)b * SEQ + (size_t)c * CHK) * HIDDEN + h;
    const float* yp = g_g + base;
    __nv_bfloat16* yh = g_yhi + base;
    __nv_bfloat16* yl = g_ylo + base;

    if (c == 0) {
        for (int t = 0; t < CHK; t++) {
            float yv = yp[(size_t)t * HIDDEN];
            __nv_bfloat16 hi = __float2bfloat16(yv);
            __nv_bfloat16 lo = __float2bfloat16(yv - __bfloat162float(hi));
            yh[(size_t)t * HIDDEN] = hi;
            yl[(size_t)t * HIDDEN] = lo;
        }
        return;
    }

    float ad[D_STATE], cc[D_STATE], p[D_STATE];
    const float* ip = g_init + (size_t)idx * D_STATE;
#pragma unroll
    for (int j = 0; j < D_STATE; j++) {
        ad[j] = g_Ad[h * D_STATE + j];
        cc[j] = C_ssm[h * D_STATE + j];
        p[j] = ip[j];
    }
    for (int t = 0; t < CHK; t++) {
        float y0 = 0.f, y1 = 0.f, y2 = 0.f, y3 = 0.f;
#pragma unroll
        for (int j = 0; j < D_STATE; j++) p[j] *= ad[j];
#pragma unroll
        for (int j = 0; j < D_STATE; j += 4) {
            y0 = fmaf(p[j + 0], cc[j + 0], y0);
            y1 = fmaf(p[j + 1], cc[j + 1], y1);
            y2 = fmaf(p[j + 2], cc[j + 2], y2);
            y3 = fmaf(p[j + 3], cc[j + 3], y3);
        }
        float yv = yp[(size_t)t * HIDDEN] + ((y0 + y1) + (y2 + y3));
        __nv_bfloat16 hi = __float2bfloat16(yv);
        __nv_bfloat16 lo = __float2bfloat16(yv - __bfloat162float(hi));
        yh[(size_t)t * HIDDEN] = hi;
        yl[(size_t)t * HIDDEN] = lo;
    }
}

// ---------------- residual + layernorm ---------------------------------------
__global__ __launch_bounds__(256) void ln_kernel(
    const float* __restrict__ x, const float* __restrict__ lng,
    const float* __restrict__ lnb, float* __restrict__ out)
{
    int row = blockIdx.x;
    __shared__ float sh[D_MODEL];
    __shared__ float rs[20];
    const float* xr = x + (size_t)row * D_MODEL;
    const float* orow = g_outp + (size_t)row * D_MODEL;
    int tid = threadIdx.x;

    float s = 0.f, sq = 0.f;
    for (int i = tid; i < D_MODEL; i += 256) {
        float r = xr[i] + orow[i];
        sh[i] = r;
        s += r;
        sq += r * r;
    }
#pragma unroll
    for (int o = 16; o > 0; o >>= 1) {
        s += __shfl_xor_sync(0xffffffffu, s, o);
        sq += __shfl_xor_sync(0xffffffffu, sq, o);
    }
    int w = tid >> 5, ln = tid & 31;
    if (ln == 0) { rs[w] = s; rs[8 + w] = sq; }
    __syncthreads();
    if (tid == 0) {
        float ts = 0.f, tq = 0.f;
#pragma unroll
        for (int i = 0; i < 8; i++) { ts += rs[i]; tq += rs[8 + i]; }
        float mean = ts * (1.f / (float)D_MODEL);
        float var = tq * (1.f / (float)D_MODEL) - mean * mean;
        rs[16] = mean;
        rs[17] = rsqrtf(var + 1e-5f);
    }
    __syncthreads();
    float mean = rs[16], inv = rs[17];
    for (int i = tid; i < D_MODEL; i += 256)
        out[(size_t)row * D_MODEL + i] = (sh[i] - mean) * inv * lng[i] + lnb[i];
}

// ---------------- host: tensormap encode via dlopen ---------------------------
typedef CUresult (*PFN_encode)(CUtensorMap*, CUtensorMapDataType, cuuint32_t, void*,
    const cuuint64_t*, const cuuint64_t*, const cuuint32_t*, const cuuint32_t*,
    CUtensorMapInterleave, CUtensorMapSwizzle, CUtensorMapL2promotion,
    CUtensorMapFloatOOBfill);

static void make_map(PFN_encode enc, CUtensorMap* m, void* ptr, int rows, int K)
{
    cuuint64_t dims[2] = {(cuuint64_t)K, (cuuint64_t)rows};
    cuuint64_t strides[1] = {(cuuint64_t)K * 2};
    cuuint32_t box[2] = {64u, 128u};
    cuuint32_t es[2] = {1u, 1u};
    enc(m, CU_TENSOR_MAP_DATA_TYPE_BFLOAT16, 2, ptr, dims, strides, box, es,
        CU_TENSOR_MAP_INTERLEAVE_NONE, CU_TENSOR_MAP_SWIZZLE_128B,
        CU_TENSOR_MAP_L2_PROMOTION_L2_128B, CU_TENSOR_MAP_FLOAT_OOB_FILL_NONE);
}

// ---------------- launch -----------------------------------------------------
extern "C" void kernel_launch(void* const* d_in, const int* in_sizes, int n_in,
                              void* d_out, int out_size)
{
    const float* x      = (const float*)d_in[0];
    const float* b_x    = (const float*)d_in[2];
    const float* b_g    = (const float*)d_in[4];
    const float* conv_w = (const float*)d_in[5];
    const float* conv_b = (const float*)d_in[6];
    const float* A_raw  = (const float*)d_in[7];
    const float* B_ssm  = (const float*)d_in[8];
    const float* C_ssm  = (const float*)d_in[9];
    const float* W_x    = (const float*)d_in[1];
    const float* W_g    = (const float*)d_in[3];
    const float* W_dt   = (const float*)d_in[10];
    const float* b_dt   = (const float*)d_in[11];
    const float* W_out  = (const float*)d_in[12];
    const float* b_out  = (const float*)d_in[13];
    const float* ln_g   = (const float*)d_in[14];
    const float* ln_b   = (const float*)d_in[15];
    float* out = (float*)d_out;

    float *pu, *pg, *pdt, *pout;
    __nv_bfloat16 *pxh, *pxl, *pwxh, *pwxl, *pwgh, *pwgl, *pwdh,
                  *pwoh, *pwol, *pyh, *pyl;
    cudaGetSymbolAddress((void**)&pu, g_u);
    cudaGetSymbolAddress((void**)&pg, g_g);
    cudaGetSymbolAddress((void**)&pdt, g_dtpart);
    cudaGetSymbolAddress((void**)&pout, g_outp);
    cudaGetSymbolAddress((void**)&pxh, g_xhi);
    cudaGetSymbolAddress((void**)&pxl, g_xlo);
    cudaGetSymbolAddress((void**)&pwxh, g_wxhi);
    cudaGetSymbolAddress((void**)&pwxl, g_wxlo);
    cudaGetSymbolAddress((void**)&pwgh, g_wghi);
    cudaGetSymbolAddress((void**)&pwgl, g_wglo);
    cudaGetSymbolAddress((void**)&pwdh, g_wdthi);
    cudaGetSymbolAddress((void**)&pwoh, g_wohi);
    cudaGetSymbolAddress((void**)&pwol, g_wolo);
    cudaGetSymbolAddress((void**)&pyh, g_yhi);
    cudaGetSymbolAddress((void**)&pyl, g_ylo);

    // tensormaps (host-side; dlopen avoids -lcuda link dependency)
    void* dl = dlopen("libcuda.so.1", RTLD_NOW);
    if (!dl) dl = dlopen("libcuda.so", RTLD_NOW);
    PFN_encode enc = dl ? (PFN_encode)dlsym(dl, "cuTensorMapEncodeTiled") : nullptr;

    CUtensorMap Mxh, Mxl, Mwxh, Mwxl, Mwgh, Mwgl, Mwdh, Mwoh, Mwol, Myh, Myl;
    make_map(enc, &Mxh, pxh, MTOK, D_MODEL);
    make_map(enc, &Mxl, pxl, MTOK, D_MODEL);
    make_map(enc, &Mwxh, pwxh, HIDDEN, D_MODEL);
    make_map(enc, &Mwxl, pwxl, HIDDEN, D_MODEL);
    make_map(enc, &Mwgh, pwgh, HIDDEN, D_MODEL);
    make_map(enc, &Mwgl, pwgl, HIDDEN, D_MODEL);
    make_map(enc, &Mwdh, pwdh, HIDDEN, D_MODEL);
    make_map(enc, &Mwoh, pwoh, D_MODEL, HIDDEN);
    make_map(enc, &Mwol, pwol, D_MODEL, HIDDEN);
    make_map(enc, &Myh, pyh, MTOK, HIDDEN);
    make_map(enc, &Myl, pyl, MTOK, HIDDEN);

    cudaFuncSetAttribute(gemm_ug_tma, cudaFuncAttributeMaxDynamicSharedMemorySize, SMEM_UG);
    cudaFuncSetAttribute(gemm_tma<0, 3>, cudaFuncAttributeMaxDynamicSharedMemorySize, SMEM_G3);
    cudaFuncSetAttribute(gemm_tma<2, 1>, cudaFuncAttributeMaxDynamicSharedMemorySize, SMEM_G1);

    auto splitN = [&](const float* src, __nv_bfloat16* hi, __nv_bfloat16* lo, int n) {
        int n4 = n / 4;
        split_kernel<<<(n4 + 255) / 256, 256>>>((const float4*)src,
                                                (__nv_bfloat162*)hi,
                                                (__nv_bfloat162*)lo, n4);
    };
    splitN(x,     pxh, pxl, MTOK * D_MODEL);
    splitN(W_x,   pwxh, pwxl, HIDDEN * D_MODEL);
    splitN(W_g,   pwgh, pwgl, HIDDEN * D_MODEL);
    splitN(W_dt,  pwdh, nullptr, HIDDEN * D_MODEL);
    splitN(W_out, pwoh, pwol, D_MODEL * HIDDEN);

    dim3 gridH(HIDDEN / BN, MTOK / BM);    // (16, 32)
    dim3 gridD(D_MODEL / BN, MTOK / BM);   // (8, 32)

    gemm_ug_tma<<<gridH, 256, SMEM_UG>>>(Mxh, Mxl, Mwxh, Mwxl, Mwgh, Mwgl,
                                         b_x, b_g, pu, pg);
    gemm_tma<2, 1><<<gridH, 256, SMEM_G1>>>(Mxh, Mxh, Mwdh, Mwdh, b_dt,
                                            nullptr, pdt, HIDDEN, D_MODEL);

    disc_kernel<<<(HIDDEN * D_STATE + 255) / 256, 256>>>(A_raw, B_ssm);

    scan1_kernel<<<(BATCH * NCHK * HIDDEN) / 128, 128>>>(C_ssm, conv_w, conv_b);
    scan2_kernel<<<(BATCH * HIDDEN * D_STATE) / 256, 256>>>();
    scan3_kernel<<<(BATCH * NCHK * HIDDEN) / 128, 128>>>(C_ssm);

    gemm_tma<0, 3><<<gridD, 256, SMEM_G3>>>(Myh, Myl, Mwoh, Mwol, b_out,
                                            pout, nullptr, D_MODEL, HIDDEN);

    ln_kernel<<<MTOK, 256>>>(x, ln_g, ln_b, out);
}

// round 7
// speedup vs baseline: 4.0276x; 1.0414x over previous
#include <cuda_runtime.h>
#include <cuda_bf16.h>
#include <cuda.h>
#include <dlfcn.h>
#include <cstdint>

#define D_MODEL 1024
#define HIDDEN  2048
#define D_STATE 16
#define BATCH   2
#define SEQ     2048
#define MTOK    4096
#define NCHK    16
#define CHK     128

// ---------------- GEMM tiling -------------------------------------------------
#define BM 128
#define BN 128
#define BKE 64
#define RB 128
#define TILE_B (128 * 128)
#define UG_STAGE (5 * TILE_B)                 // Ahi,Alo,Xhi,Xlo,Ghi
#define SMEM_UG (2 * UG_STAGE + 1024)         // 164864
#define SMEM_G3 (3 * 4 * TILE_B + 1024)       // 197632 (3-stage out GEMM)
#define SMEM_G1 (4 * 2 * TILE_B + 1024)       // 132096 (4-stage dt GEMM)

// ---------------- scratch ----------------------------------------------------
__device__ float g_u[(size_t)MTOK * HIDDEN];      // u (read-only after ug GEMM)
__device__ float g_g[(size_t)MTOK * HIDDEN];      // gate, then y_local (fp32)
__device__ float g_outp[(size_t)MTOK * D_MODEL];
__device__ float g_dtpart[(MTOK / BM) * HIDDEN];
__device__ float g_Ad[HIDDEN * D_STATE];
__device__ float g_Bd[HIDDEN * D_STATE];
__device__ float g_state[(size_t)BATCH * NCHK * HIDDEN * D_STATE];
__device__ float g_init[(size_t)BATCH * NCHK * HIDDEN * D_STATE];

__device__ __nv_bfloat16 g_xhi[(size_t)MTOK * D_MODEL];
__device__ __nv_bfloat16 g_xlo[(size_t)MTOK * D_MODEL];
__device__ __nv_bfloat16 g_wxhi[HIDDEN * D_MODEL];
__device__ __nv_bfloat16 g_wxlo[HIDDEN * D_MODEL];
__device__ __nv_bfloat16 g_wghi[HIDDEN * D_MODEL];
__device__ __nv_bfloat16 g_wdthi[HIDDEN * D_MODEL];
__device__ __nv_bfloat16 g_wohi[D_MODEL * HIDDEN];
__device__ __nv_bfloat16 g_wolo[D_MODEL * HIDDEN];
__device__ __nv_bfloat16 g_yhi[(size_t)MTOK * HIDDEN];
__device__ __nv_bfloat16 g_ylo[(size_t)MTOK * HIDDEN];

// ---------------- helpers ----------------------------------------------------
__device__ __forceinline__ float softplusf(float x) {
    return fmaxf(x, 0.f) + log1pf(expf(-fabsf(x)));
}
__device__ __forceinline__ float sigmoidf_(float x) {
    return 1.f / (1.f + expf(-x));
}
__device__ __forceinline__ uint32_t smem_u32(const void* p) {
    uint32_t a;
    asm("{ .reg .u64 t; cvta.to.shared.u64 t, %1; cvt.u32.u64 %0, t; }"
        : "=r"(a) : "l"(p));
    return a;
}
__device__ __forceinline__ void ldm_x4(uint32_t* r, uint32_t addr) {
    asm volatile("ldmatrix.sync.aligned.m8n8.x4.shared.b16 {%0,%1,%2,%3}, [%4];"
                 : "=r"(r[0]), "=r"(r[1]), "=r"(r[2]), "=r"(r[3]) : "r"(addr));
}
__device__ __forceinline__ void mma_bf16(float* d, const uint32_t* a,
                                         const uint32_t* b) {
    asm volatile(
        "mma.sync.aligned.m16n8k16.row.col.f32.bf16.bf16.f32 "
        "{%0,%1,%2,%3}, {%4,%5,%6,%7}, {%8,%9}, {%0,%1,%2,%3};"
        : "+f"(d[0]), "+f"(d[1]), "+f"(d[2]), "+f"(d[3])
        : "r"(a[0]), "r"(a[1]), "r"(a[2]), "r"(a[3]), "r"(b[0]), "r"(b[1]));
}
__device__ __forceinline__ void mbar_init(uint32_t addr) {
    asm volatile("mbarrier.init.shared.b64 [%0], 1;" :: "r"(addr) : "memory");
}
__device__ __forceinline__ void mbar_expect(uint32_t addr, uint32_t bytes) {
    asm volatile("mbarrier.arrive.expect_tx.shared.b64 _, [%0], %1;"
                 :: "r"(addr), "r"(bytes) : "memory");
}
__device__ __forceinline__ void mbar_wait(uint32_t addr, uint32_t parity) {
    asm volatile(
        "{\n\t.reg .pred P;\n\t"
        "W_%=:\n\t"
        "mbarrier.try_wait.parity.acquire.cta.shared::cta.b64 P, [%0], %1, 0x989680;\n\t"
        "@P bra D_%=;\n\t"
        "bra W_%=;\n\t"
        "D_%=:\n\t}"
        :: "r"(addr), "r"(parity) : "memory");
}
__device__ __forceinline__ void tma2d(uint32_t smaddr, const CUtensorMap* m,
                                      int cx, int cy, uint32_t mbar) {
    asm volatile(
        "cp.async.bulk.tensor.2d.shared::cta.global.tile.mbarrier::complete_tx::bytes "
        "[%0], [%1, {%2, %3}], [%4];"
        :: "r"(smaddr), "l"(m), "r"(cx), "r"(cy), "r"(mbar) : "memory");
}

// ---------------- fp32 -> bf16 hi/lo split (x) --------------------------------
__global__ __launch_bounds__(256) void split_kernel(
    const float4* __restrict__ src, __nv_bfloat162* __restrict__ hi,
    __nv_bfloat162* __restrict__ lo, int n4)
{
    int i = blockIdx.x * blockDim.x + threadIdx.x;
    if (i >= n4) return;
    float4 v = src[i];
    __nv_bfloat16 h0 = __float2bfloat16(v.x);
    __nv_bfloat16 h1 = __float2bfloat16(v.y);
    __nv_bfloat16 h2 = __float2bfloat16(v.z);
    __nv_bfloat16 h3 = __float2bfloat16(v.w);
    hi[i * 2 + 0] = __nv_bfloat162(h0, h1);
    hi[i * 2 + 1] = __nv_bfloat162(h2, h3);
    if (lo) {
        __nv_bfloat16 l0 = __float2bfloat16(v.x - __bfloat162float(h0));
        __nv_bfloat16 l1 = __float2bfloat16(v.y - __bfloat162float(h1));
        __nv_bfloat16 l2 = __float2bfloat16(v.z - __bfloat162float(h2));
        __nv_bfloat16 l3 = __float2bfloat16(v.w - __bfloat162float(h3));
        lo[i * 2 + 0] = __nv_bfloat162(l0, l1);
        lo[i * 2 + 1] = __nv_bfloat162(l2, l3);
    }
}

// ---------------- fused weight split: W_x(hi,lo) W_g(hi) W_dt(hi) W_out(hi,lo)
#define WN4 (HIDDEN * D_MODEL / 4)   // 524288 = 2^19
__global__ __launch_bounds__(256) void split_w_kernel(
    const float4* __restrict__ wx, const float4* __restrict__ wg,
    const float4* __restrict__ wdt, const float4* __restrict__ wo)
{
    int gi = blockIdx.x * blockDim.x + threadIdx.x;   // < 4*WN4
    int arr = gi >> 19;
    int i = gi & (WN4 - 1);
    const float4* src = (arr == 0) ? wx : (arr == 1) ? wg : (arr == 2) ? wdt : wo;
    __nv_bfloat162* hi = (arr == 0) ? (__nv_bfloat162*)g_wxhi
                       : (arr == 1) ? (__nv_bfloat162*)g_wghi
                       : (arr == 2) ? (__nv_bfloat162*)g_wdthi
                                    : (__nv_bfloat162*)g_wohi;
    __nv_bfloat162* lo = (arr == 0) ? (__nv_bfloat162*)g_wxlo
                       : (arr == 3) ? (__nv_bfloat162*)g_wolo : nullptr;
    float4 v = src[i];
    __nv_bfloat16 h0 = __float2bfloat16(v.x);
    __nv_bfloat16 h1 = __float2bfloat16(v.y);
    __nv_bfloat16 h2 = __float2bfloat16(v.z);
    __nv_bfloat16 h3 = __float2bfloat16(v.w);
    hi[i * 2 + 0] = __nv_bfloat162(h0, h1);
    hi[i * 2 + 1] = __nv_bfloat162(h2, h3);
    if (lo) {
        __nv_bfloat16 l0 = __float2bfloat16(v.x - __bfloat162float(h0));
        __nv_bfloat16 l1 = __float2bfloat16(v.y - __bfloat162float(h1));
        __nv_bfloat16 l2 = __float2bfloat16(v.z - __bfloat162float(h2));
        __nv_bfloat16 l3 = __float2bfloat16(v.w - __bfloat162float(h3));
        lo[i * 2 + 0] = __nv_bfloat162(l0, l1);
        lo[i * 2 + 1] = __nv_bfloat162(l2, l3);
    }
}

// ---------------- fused u + gate GEMM (TMA, 2-stage, 5 tiles) ----------------
// u: 3 terms (ah*xh + ah*xl + al*xh); gate: 2 terms (ah*gh + al*gh)
__global__ __launch_bounds__(256, 1) void gemm_ug_tma(
    const __grid_constant__ CUtensorMap mAh, const __grid_constant__ CUtensorMap mAl,
    const __grid_constant__ CUtensorMap mXh, const __grid_constant__ CUtensorMap mXl,
    const __grid_constant__ CUtensorMap mGh,
    const float* __restrict__ bx, const float* __restrict__ bg,
    float* __restrict__ Cu, float* __restrict__ Cg)
{
    const int N = HIDDEN;
    extern __shared__ char smraw[];
    uint32_t sb = (smem_u32(smraw) + 1023u) & ~1023u;
    __shared__ uint64_t mbarS[2];
    uint32_t mb = smem_u32(mbarS);

    const int tid = threadIdx.x;
    const int wid = tid >> 5, lane = tid & 31;
    const int wm = wid & 1, wn = wid >> 1;
    const int am0 = blockIdx.y * BM;
    const int bn0 = blockIdx.x * BN;

    if (tid == 0) { mbar_init(mb); mbar_init(mb + 8); }
    __syncthreads();

    auto issue = [&](int s) {
        if (tid != 0) return;
        uint32_t bar = mb + (uint32_t)(s & 1) * 8;
        mbar_expect(bar, UG_STAGE);
        uint32_t st = sb + (uint32_t)(s & 1) * UG_STAGE;
        int kc = s * BKE;
        tma2d(st + 0 * TILE_B, &mAh, kc, am0, bar);
        tma2d(st + 1 * TILE_B, &mAl, kc, am0, bar);
        tma2d(st + 2 * TILE_B, &mXh, kc, bn0, bar);
        tma2d(st + 3 * TILE_B, &mXl, kc, bn0, bar);
        tma2d(st + 4 * TILE_B, &mGh, kc, bn0, bar);
    };
    issue(0); issue(1);

    float acc_u[4][4][4], acc_g[4][4][4];
#pragma unroll
    for (int i = 0; i < 4; i++)
#pragma unroll
        for (int j = 0; j < 4; j++)
#pragma unroll
            for (int v = 0; v < 4; v++) { acc_u[i][j][v] = 0.f; acc_g[i][j][v] = 0.f; }

    const int arA = wm * 64 + (lane & 15);
    const int ahalf = lane >> 4;
    const uint32_t axor = (uint32_t)(arA & 7);
    uint32_t aoff[4];
#pragma unroll
    for (int mf = 0; mf < 4; mf++) aoff[mf] = (uint32_t)(arA + mf * 16) * RB;

    const int nrB = wn * 32 + (lane & 7) + ((lane >> 4) << 3);
    const int khalf = (lane >> 3) & 1;
    const uint32_t bxor = (uint32_t)(nrB & 7);
    uint32_t boff[2];
#pragma unroll
    for (int nf = 0; nf < 2; nf++) boff[nf] = (uint32_t)(nrB + nf * 16) * RB;

    const int NCH = D_MODEL / BKE;   // 16
    for (int ch = 0; ch < NCH; ch++) {
        mbar_wait(mb + (uint32_t)(ch & 1) * 8, (uint32_t)((ch >> 1) & 1));
        const uint32_t st = sb + (uint32_t)(ch & 1) * UG_STAGE;

#pragma unroll
        for (int ks = 0; ks < 4; ks++) {
            const uint32_t asg = (((uint32_t)(ks * 2 + ahalf)) ^ axor) << 4;
            const uint32_t bsg = (((uint32_t)(ks * 2 + khalf)) ^ bxor) << 4;
            uint32_t ah[4][4], al[4][4];
#pragma unroll
            for (int mf = 0; mf < 4; mf++) {
                ldm_x4(ah[mf], st + 0 * TILE_B + aoff[mf] + asg);
                ldm_x4(al[mf], st + 1 * TILE_B + aoff[mf] + asg);
            }
            // ---- u: B = Xh (hi) and Xl (lo) ----
            {
                uint32_t bh[4][2], bl[4][2];
#pragma unroll
                for (int nf = 0; nf < 2; nf++) {
                    uint32_t rr[4];
                    ldm_x4(rr, st + 2 * TILE_B + boff[nf] + bsg);
                    bh[nf * 2 + 0][0] = rr[0]; bh[nf * 2 + 0][1] = rr[1];
                    bh[nf * 2 + 1][0] = rr[2]; bh[nf * 2 + 1][1] = rr[3];
                    ldm_x4(rr, st + 3 * TILE_B + boff[nf] + bsg);
                    bl[nf * 2 + 0][0] = rr[0]; bl[nf * 2 + 0][1] = rr[1];
                    bl[nf * 2 + 1][0] = rr[2]; bl[nf * 2 + 1][1] = rr[3];
                }
#pragma unroll
                for (int mf = 0; mf < 4; mf++)
#pragma unroll
                    for (int nfi = 0; nfi < 4; nfi++) {
                        mma_bf16(acc_u[mf][nfi], ah[mf], bh[nfi]);
                        mma_bf16(acc_u[mf][nfi], ah[mf], bl[nfi]);
                        mma_bf16(acc_u[mf][nfi], al[mf], bh[nfi]);
                    }
            }
            // ---- gate: B = Gh only ----
            {
                uint32_t gh[4][2];
#pragma unroll
                for (int nf = 0; nf < 2; nf++) {
                    uint32_t rr[4];
                    ldm_x4(rr, st + 4 * TILE_B + boff[nf] + bsg);
                    gh[nf * 2 + 0][0] = rr[0]; gh[nf * 2 + 0][1] = rr[1];
                    gh[nf * 2 + 1][0] = rr[2]; gh[nf * 2 + 1][1] = rr[3];
                }
#pragma unroll
                for (int mf = 0; mf < 4; mf++)
#pragma unroll
                    for (int nfi = 0; nfi < 4; nfi++) {
                        mma_bf16(acc_g[mf][nfi], ah[mf], gh[nfi]);
                        mma_bf16(acc_g[mf][nfi], al[mf], gh[nfi]);
                    }
            }
        }
        __syncthreads();
        if (ch + 2 < NCH) issue(ch + 2);
    }

#pragma unroll
    for (int mf = 0; mf < 4; mf++) {
        const int r0 = am0 + wm * 64 + mf * 16 + (lane >> 2);
#pragma unroll
        for (int h = 0; h < 2; h++) {
            const int row = r0 + h * 8;
#pragma unroll
            for (int nfi = 0; nfi < 4; nfi++) {
                const int col = bn0 + wn * 32 + nfi * 8 + (lane & 3) * 2;
                float u0 = acc_u[mf][nfi][h * 2 + 0] + bx[col];
                float u1 = acc_u[mf][nfi][h * 2 + 1] + bx[col + 1];
                float g0 = sigmoidf_(acc_g[mf][nfi][h * 2 + 0] + bg[col]);
                float g1 = sigmoidf_(acc_g[mf][nfi][h * 2 + 1] + bg[col + 1]);
                *(float2*)&Cu[(size_t)row * N + col] = make_float2(u0, u1);
                *(float2*)&Cg[(size_t)row * N + col] = make_float2(g0, g1);
            }
        }
    }
}

// ---------------- TMA GEMM (NT terms, NS stages) ------------------------------
// MODE 0: raw+bias store. MODE 2: per-M-block softplus column sums.
template <int MODE, int NT, int NS>
__global__ __launch_bounds__(256, 1) void gemm_tma(
    const __grid_constant__ CUtensorMap mAh, const __grid_constant__ CUtensorMap mAl,
    const __grid_constant__ CUtensorMap mBh, const __grid_constant__ CUtensorMap mBl,
    const float* __restrict__ bias, float* __restrict__ C,
    float* __restrict__ colsum, int N, int K)
{
    constexpr uint32_t STAGE = (NT == 3 ? 4 : 2) * TILE_B;
    constexpr uint32_t ALOFF = 1 * TILE_B;
    constexpr uint32_t BHOFF = (NT == 3 ? 2 : 1) * TILE_B;
    constexpr uint32_t BLOFF = 3 * TILE_B;

    extern __shared__ char smraw[];
    uint32_t sb = (smem_u32(smraw) + 1023u) & ~1023u;
    __shared__ uint64_t mbarS[NS];
    uint32_t mb = smem_u32(mbarS);

    const int tid = threadIdx.x;
    const int wid = tid >> 5, lane = tid & 31;
    const int wm = wid & 1, wn = wid >> 1;
    const int am0 = blockIdx.y * BM;
    const int bn0 = blockIdx.x * BN;

    if (tid == 0) {
#pragma unroll
        for (int s = 0; s < NS; s++) mbar_init(mb + s * 8);
    }
    __syncthreads();

    auto issue = [&](int s) {
        if (tid != 0) return;
        int slot = s % NS;
        uint32_t bar = mb + (uint32_t)slot * 8;
        mbar_expect(bar, STAGE);
        uint32_t st = sb + (uint32_t)slot * STAGE;
        int kc = s * BKE;
        tma2d(st, &mAh, kc, am0, bar);
        tma2d(st + BHOFF, &mBh, kc, bn0, bar);
        if (NT == 3) {
            tma2d(st + ALOFF, &mAl, kc, am0, bar);
            tma2d(st + BLOFF, &mBl, kc, bn0, bar);
        }
    };
    const int NCH = K / BKE;
#pragma unroll
    for (int s = 0; s < NS; s++) if (s < NCH) issue(s);

    float acc[4][4][4];
#pragma unroll
    for (int i = 0; i < 4; i++)
#pragma unroll
        for (int j = 0; j < 4; j++)
#pragma unroll
            for (int v = 0; v < 4; v++) acc[i][j][v] = 0.f;

    const int arA = wm * 64 + (lane & 15);
    const int ahalf = lane >> 4;
    const uint32_t axor = (uint32_t)(arA & 7);
    uint32_t aoff[4];
#pragma unroll
    for (int mf = 0; mf < 4; mf++) aoff[mf] = (uint32_t)(arA + mf * 16) * RB;

    const int nrB = wn * 32 + (lane & 7) + ((lane >> 4) << 3);
    const int khalf = (lane >> 3) & 1;
    const uint32_t bxor = (uint32_t)(nrB & 7);
    uint32_t boff[2];
#pragma unroll
    for (int nf = 0; nf < 2; nf++) boff[nf] = (uint32_t)(nrB + nf * 16) * RB;

    for (int ch = 0; ch < NCH; ch++) {
        int slot = ch % NS;
        mbar_wait(mb + (uint32_t)slot * 8, (uint32_t)((ch / NS) & 1));
        const uint32_t st = sb + (uint32_t)slot * STAGE;

#pragma unroll
        for (int ks = 0; ks < 4; ks++) {
            uint32_t a[4][4], bh[4][2], bl[4][2];
            const uint32_t asg = (((uint32_t)(ks * 2 + ahalf)) ^ axor) << 4;
            const uint32_t bsg = (((uint32_t)(ks * 2 + khalf)) ^ bxor) << 4;
#pragma unroll
            for (int nf = 0; nf < 2; nf++) {
                uint32_t rr[4];
                ldm_x4(rr, st + BHOFF + boff[nf] + bsg);
                bh[nf * 2 + 0][0] = rr[0]; bh[nf * 2 + 0][1] = rr[1];
                bh[nf * 2 + 1][0] = rr[2]; bh[nf * 2 + 1][1] = rr[3];
                if (NT == 3) {
                    ldm_x4(rr, st + BLOFF + boff[nf] + bsg);
                    bl[nf * 2 + 0][0] = rr[0]; bl[nf * 2 + 0][1] = rr[1];
                    bl[nf * 2 + 1][0] = rr[2]; bl[nf * 2 + 1][1] = rr[3];
                }
            }
#pragma unroll
            for (int mf = 0; mf < 4; mf++) {
                ldm_x4(a[mf], st + aoff[mf] + asg);
#pragma unroll
                for (int nfi = 0; nfi < 4; nfi++) {
                    mma_bf16(acc[mf][nfi], a[mf], bh[nfi]);
                    if (NT == 3) mma_bf16(acc[mf][nfi], a[mf], bl[nfi]);
                }
            }
            if (NT == 3) {
#pragma unroll
                for (int mf = 0; mf < 4; mf++) {
                    ldm_x4(a[mf], st + ALOFF + aoff[mf] + asg);
#pragma unroll
                    for (int nfi = 0; nfi < 4; nfi++)
                        mma_bf16(acc[mf][nfi], a[mf], bh[nfi]);
                }
            }
        }
        __syncthreads();
        if (ch + NS < NCH) issue(ch + NS);
    }

    if (MODE == 2) {
        float* red = (float*)smraw;
#pragma unroll
        for (int nfi = 0; nfi < 4; nfi++) {
            const int colb = bn0 + wn * 32 + nfi * 8 + (lane & 3) * 2;
            const float b0 = bias[colb], b1 = bias[colb + 1];
            float s0 = 0.f, s1 = 0.f;
#pragma unroll
            for (int mf = 0; mf < 4; mf++) {
                s0 += softplusf(acc[mf][nfi][0] + b0);
                s1 += softplusf(acc[mf][nfi][1] + b1);
                s0 += softplusf(acc[mf][nfi][2] + b0);
                s1 += softplusf(acc[mf][nfi][3] + b1);
            }
#pragma unroll
            for (int o = 4; o <= 16; o <<= 1) {
                s0 += __shfl_xor_sync(0xffffffffu, s0, o);
                s1 += __shfl_xor_sync(0xffffffffu, s1, o);
            }
            if (lane < 4) {
                int c = wn * 32 + nfi * 8 + lane * 2;
                red[wm * 128 + c] = s0;
                red[wm * 128 + c + 1] = s1;
            }
        }
        __syncthreads();
        if (tid < 128)
            colsum[(size_t)blockIdx.y * N + bn0 + tid] =
                red[tid] + red[128 + tid];
    } else {
#pragma unroll
        for (int mf = 0; mf < 4; mf++) {
            const int r0 = am0 + wm * 64 + mf * 16 + (lane >> 2);
#pragma unroll
            for (int h = 0; h < 2; h++) {
                const int row = r0 + h * 8;
#pragma unroll
                for (int nfi = 0; nfi < 4; nfi++) {
                    const int col = bn0 + wn * 32 + nfi * 8 + (lane & 3) * 2;
                    float v0 = acc[mf][nfi][h * 2 + 0] + bias[col];
                    float v1 = acc[mf][nfi][h * 2 + 1] + bias[col + 1];
                    *(float2*)&C[(size_t)row * N + col] = make_float2(v0, v1);
                }
            }
        }
    }
}

// ---------------- dt finalize + discretization --------------------------------
__global__ void disc_kernel(const float* __restrict__ A_raw,
                            const float* __restrict__ B_ssm)
{
    int idx = blockIdx.x * blockDim.x + threadIdx.x;
    if (idx >= HIDDEN * D_STATE) return;
    int h = idx / D_STATE;
    float sum = 0.f;
#pragma unroll
    for (int p = 0; p < MTOK / BM; p++) sum += g_dtpart[p * HIDDEN + h];
    float dt = sum * (1.f / (float)MTOK);
    dt = fminf(fmaxf(dt, 1e-3f), 2.0f);
    float a = -softplusf(A_raw[idx]);
    float ad = expf(a * dt);
    float bd = (ad - 1.0f) / (a + 1e-6f) * B_ssm[idx];
    g_Ad[idx] = ad;
    g_Bd[idx] = bd;
}

// ---------------- scan pass 1: fused conv+gate + chunk-local scan ------------
__global__ __launch_bounds__(128) void scan1_kernel(
    const float* __restrict__ C_ssm, const float* __restrict__ conv_w,
    const float* __restrict__ conv_b)
{
    int idx = blockIdx.x * blockDim.x + threadIdx.x;  // < BATCH*NCHK*HIDDEN
    int h = idx & (HIDDEN - 1);
    int bc = idx >> 11;
    int c = bc & (NCHK - 1);

    float ad[D_STATE], bd[D_STATE], cc[D_STATE], st[D_STATE];
#pragma unroll
    for (int j = 0; j < D_STATE; j++) {
        ad[j] = g_Ad[h * D_STATE + j];
        bd[j] = g_Bd[h * D_STATE + j];
        cc[j] = C_ssm[h * D_STATE + j];
        st[j] = 0.f;
    }
    const float w0 = conv_w[h * 3 + 0], w1 = conv_w[h * 3 + 1],
                w2 = conv_w[h * 3 + 2], cb = conv_b[h];

    const int b = bc >> 4;
    const int l0 = c * CHK;
    const size_t base = ((size_t)b * SEQ + l0) * HIDDEN + h;
    const float* up = g_u + base;
    float* gp = g_g + base;

    float um = (l0 > 0) ? up[-(ptrdiff_t)HIDDEN] : 0.f;
    float cu[4], cg[4];
#pragma unroll
    for (int q = 0; q < 4; q++) {
        cu[q] = up[(size_t)q * HIDDEN];
        cg[q] = gp[(size_t)q * HIDDEN];
    }

    for (int t = 0; t < CHK; t += 4) {
        float nu[4], ng[4];
#pragma unroll
        for (int q = 0; q < 4; q++) {
            int l = l0 + t + 4 + q;
            nu[q] = (l < SEQ) ? up[(size_t)(t + 4 + q) * HIDDEN] : 0.f;
            int tt = t + 4 + q;
            ng[q] = (tt < CHK) ? gp[(size_t)tt * HIDDEN] : 0.f;
        }
#pragma unroll
        for (int q = 0; q < 4; q++) {
            float u0 = cu[q];
            float upn = (q < 3) ? cu[q + 1] : nu[0];
            float hc = cb + w0 * um + w1 * u0 + w2 * upn;
            float g = cg[q];
            float uc = u0 * g + hc * (1.f - g);
            float y0 = 0.f, y1 = 0.f, y2 = 0.f, y3 = 0.f;
#pragma unroll
            for (int j = 0; j < D_STATE; j++)
                st[j] = fmaf(ad[j], st[j], bd[j] * uc);
#pragma unroll
            for (int j = 0; j < D_STATE; j += 4) {
                y0 = fmaf(st[j + 0], cc[j + 0], y0);
                y1 = fmaf(st[j + 1], cc[j + 1], y1);
                y2 = fmaf(st[j + 2], cc[j + 2], y2);
                y3 = fmaf(st[j + 3], cc[j + 3], y3);
            }
            gp[(size_t)(t + q) * HIDDEN] = (y0 + y1) + (y2 + y3);
            um = u0;
        }
#pragma unroll
        for (int q = 0; q < 4; q++) { cu[q] = nu[q]; cg[q] = ng[q]; }
    }
    float* sp = g_state + (size_t)idx * D_STATE;
#pragma unroll
    for (int j = 0; j < D_STATE; j += 4)
        *(float4*)&sp[j] = make_float4(st[j], st[j + 1], st[j + 2], st[j + 3]);
}

// ---------------- scan pass 2: chunk-state prefix ----------------------------
__global__ __launch_bounds__(256) void scan2_kernel()
{
    int idx = blockIdx.x * blockDim.x + threadIdx.x;  // < BATCH*HIDDEN*16
    int j = idx & (D_STATE - 1);
    int h = (idx >> 4) & (HIDDEN - 1);
    int b = idx >> 15;

    float ad = g_Ad[h * D_STATE + j];
    float af = ad;
#pragma unroll
    for (int i = 0; i < 7; i++) af = af * af;     // ad^128

    float carry = 0.f;
#pragma unroll
    for (int c = 0; c < NCHK; c++) {
        size_t off = (((size_t)b * NCHK + c) * HIDDEN + h) * D_STATE + j;
        g_init[off] = carry;
        carry = fmaf(af, carry, g_state[off]);
    }
}

// ---------------- scan pass 3: fixup + bf16 split ----------------------------
__global__ __launch_bounds__(128) void scan3_kernel(const float* __restrict__ C_ssm)
{
    int idx = blockIdx.x * blockDim.x + threadIdx.x;
    int h = idx & (HIDDEN - 1);
    int bc = idx >> 11;
    int c = bc & (NCHK - 1);
    int b = bc >> 4;

    const size_t base = ((size_t)b * SEQ + (size_t)c * CHK) * HIDDEN + h;
    const float* yp = g_g + base;
    __nv_bfloat16* yh = g_yhi + base;
    __nv_bfloat16* yl = g_ylo + base;

    if (c == 0) {
        for (int t = 0; t < CHK; t++) {
            float yv = yp[(size_t)t * HIDDEN];
            __nv_bfloat16 hi = __float2bfloat16(yv);
            __nv_bfloat16 lo = __float2bfloat16(yv - __bfloat162float(hi));
            yh[(size_t)t * HIDDEN] = hi;
            yl[(size_t)t * HIDDEN] = lo;
        }
        return;
    }

    float ad[D_STATE], cc[D_STATE], p[D_STATE];
    const float* ip = g_init + (size_t)idx * D_STATE;
#pragma unroll
    for (int j = 0; j < D_STATE; j++) {
        ad[j] = g_Ad[h * D_STATE + j];
        cc[j] = C_ssm[h * D_STATE + j];
        p[j] = ip[j];
    }
    for (int t = 0; t < CHK; t++) {
        float y0 = 0.f, y1 = 0.f, y2 = 0.f, y3 = 0.f;
#pragma unroll
        for (int j = 0; j < D_STATE; j++) p[j] *= ad[j];
#pragma unroll
        for (int j = 0; j < D_STATE; j += 4) {
            y0 = fmaf(p[j + 0], cc[j + 0], y0);
            y1 = fmaf(p[j + 1], cc[j + 1], y1);
            y2 = fmaf(p[j + 2], cc[j + 2], y2);
            y3 = fmaf(p[j + 3], cc[j + 3], y3);
        }
        float yv = yp[(size_t)t * HIDDEN] + ((y0 + y1) + (y2 + y3));
        __nv_bfloat16 hi = __float2bfloat16(yv);
        __nv_bfloat16 lo = __float2bfloat16(yv - __bfloat162float(hi));
        yh[(size_t)t * HIDDEN] = hi;
        yl[(size_t)t * HIDDEN] = lo;
    }
}

// ---------------- residual + layernorm ---------------------------------------
__global__ __launch_bounds__(256) void ln_kernel(
    const float* __restrict__ x, const float* __restrict__ lng,
    const float* __restrict__ lnb, float* __restrict__ out)
{
    int row = blockIdx.x;
    __shared__ float sh[D_MODEL];
    __shared__ float rs[20];
    const float* xr = x + (size_t)row * D_MODEL;
    const float* orow = g_outp + (size_t)row * D_MODEL;
    int tid = threadIdx.x;

    float s = 0.f, sq = 0.f;
    for (int i = tid; i < D_MODEL; i += 256) {
        float r = xr[i] + orow[i];
        sh[i] = r;
        s += r;
        sq += r * r;
    }
#pragma unroll
    for (int o = 16; o > 0; o >>= 1) {
        s += __shfl_xor_sync(0xffffffffu, s, o);
        sq += __shfl_xor_sync(0xffffffffu, sq, o);
    }
    int w = tid >> 5, ln = tid & 31;
    if (ln == 0) { rs[w] = s; rs[8 + w] = sq; }
    __syncthreads();
    if (tid == 0) {
        float ts = 0.f, tq = 0.f;
#pragma unroll
        for (int i = 0; i < 8; i++) { ts += rs[i]; tq += rs[8 + i]; }
        float mean = ts * (1.f / (float)D_MODEL);
        float var = tq * (1.f / (float)D_MODEL) - mean * mean;
        rs[16] = mean;
        rs[17] = rsqrtf(var + 1e-5f);
    }
    __syncthreads();
    float mean = rs[16], inv = rs[17];
    for (int i = tid; i < D_MODEL; i += 256)
        out[(size_t)row * D_MODEL + i] = (sh[i] - mean) * inv * lng[i] + lnb[i];
}

// ---------------- host: tensormap encode via dlopen ---------------------------
typedef CUresult (*PFN_encode)(CUtensorMap*, CUtensorMapDataType, cuuint32_t, void*,
    const cuuint64_t*, const cuuint64_t*, const cuuint32_t*, const cuuint32_t*,
    CUtensorMapInterleave, CUtensorMapSwizzle, CUtensorMapL2promotion,
    CUtensorMapFloatOOBfill);

static void make_map(PFN_encode enc, CUtensorMap* m, void* ptr, int rows, int K)
{
    cuuint64_t dims[2] = {(cuuint64_t)K, (cuuint64_t)rows};
    cuuint64_t strides[1] = {(cuuint64_t)K * 2};
    cuuint32_t box[2] = {64u, 128u};
    cuuint32_t es[2] = {1u, 1u};
    enc(m, CU_TENSOR_MAP_DATA_TYPE_BFLOAT16, 2, ptr, dims, strides, box, es,
        CU_TENSOR_MAP_INTERLEAVE_NONE, CU_TENSOR_MAP_SWIZZLE_128B,
        CU_TENSOR_MAP_L2_PROMOTION_L2_128B, CU_TENSOR_MAP_FLOAT_OOB_FILL_NONE);
}

// ---------------- launch -----------------------------------------------------
extern "C" void kernel_launch(void* const* d_in, const int* in_sizes, int n_in,
                              void* d_out, int out_size)
{
    const float* x      = (const float*)d_in[0];
    const float* W_x    = (const float*)d_in[1];
    const float* b_x    = (const float*)d_in[2];
    const float* W_g    = (const float*)d_in[3];
    const float* b_g    = (const float*)d_in[4];
    const float* conv_w = (const float*)d_in[5];
    const float* conv_b = (const float*)d_in[6];
    const float* A_raw  = (const float*)d_in[7];
    const float* B_ssm  = (const float*)d_in[8];
    const float* C_ssm  = (const float*)d_in[9];
    const float* W_dt   = (const float*)d_in[10];
    const float* b_dt   = (const float*)d_in[11];
    const float* W_out  = (const float*)d_in[12];
    const float* b_out  = (const float*)d_in[13];
    const float* ln_g   = (const float*)d_in[14];
    const float* ln_b   = (const float*)d_in[15];
    float* out = (float*)d_out;

    float *pu, *pg, *pdt, *pout;
    __nv_bfloat16 *pxh, *pxl, *pwxh, *pwxl, *pwgh, *pwdh, *pwoh, *pwol, *pyh, *pyl;
    cudaGetSymbolAddress((void**)&pu, g_u);
    cudaGetSymbolAddress((void**)&pg, g_g);
    cudaGetSymbolAddress((void**)&pdt, g_dtpart);
    cudaGetSymbolAddress((void**)&pout, g_outp);
    cudaGetSymbolAddress((void**)&pxh, g_xhi);
    cudaGetSymbolAddress((void**)&pxl, g_xlo);
    cudaGetSymbolAddress((void**)&pwxh, g_wxhi);
    cudaGetSymbolAddress((void**)&pwxl, g_wxlo);
    cudaGetSymbolAddress((void**)&pwgh, g_wghi);
    cudaGetSymbolAddress((void**)&pwdh, g_wdthi);
    cudaGetSymbolAddress((void**)&pwoh, g_wohi);
    cudaGetSymbolAddress((void**)&pwol, g_wolo);
    cudaGetSymbolAddress((void**)&pyh, g_yhi);
    cudaGetSymbolAddress((void**)&pyl, g_ylo);

    void* dl = dlopen("libcuda.so.1", RTLD_NOW);
    if (!dl) dl = dlopen("libcuda.so", RTLD_NOW);
    PFN_encode enc = dl ? (PFN_encode)dlsym(dl, "cuTensorMapEncodeTiled") : nullptr;

    CUtensorMap Mxh, Mxl, Mwxh, Mwxl, Mwgh, Mwdh, Mwoh, Mwol, Myh, Myl;
    make_map(enc, &Mxh, pxh, MTOK, D_MODEL);
    make_map(enc, &Mxl, pxl, MTOK, D_MODEL);
    make_map(enc, &Mwxh, pwxh, HIDDEN, D_MODEL);
    make_map(enc, &Mwxl, pwxl, HIDDEN, D_MODEL);
    make_map(enc, &Mwgh, pwgh, HIDDEN, D_MODEL);
    make_map(enc, &Mwdh, pwdh, HIDDEN, D_MODEL);
    make_map(enc, &Mwoh, pwoh, D_MODEL, HIDDEN);
    make_map(enc, &Mwol, pwol, D_MODEL, HIDDEN);
    make_map(enc, &Myh, pyh, MTOK, HIDDEN);
    make_map(enc, &Myl, pyl, MTOK, HIDDEN);

    cudaFuncSetAttribute(gemm_ug_tma, cudaFuncAttributeMaxDynamicSharedMemorySize, SMEM_UG);
    cudaFuncSetAttribute(gemm_tma<0, 3, 3>, cudaFuncAttributeMaxDynamicSharedMemorySize, SMEM_G3);
    cudaFuncSetAttribute(gemm_tma<2, 1, 4>, cudaFuncAttributeMaxDynamicSharedMemorySize, SMEM_G1);

    // splits: x (hi+lo) and all weights in one fused launch
    {
        int n4 = MTOK * D_MODEL / 4;
        split_kernel<<<(n4 + 255) / 256, 256>>>((const float4*)x,
                                                (__nv_bfloat162*)pxh,
                                                (__nv_bfloat162*)pxl, n4);
        split_w_kernel<<<(4 * WN4) / 256, 256>>>((const float4*)W_x,
                                                 (const float4*)W_g,
                                                 (const float4*)W_dt,
                                                 (const float4*)W_out);
    }

    dim3 gridH(HIDDEN / BN, MTOK / BM);    // (16, 32)
    dim3 gridD(D_MODEL / BN, MTOK / BM);   // (8, 32)

    gemm_ug_tma<<<gridH, 256, SMEM_UG>>>(Mxh, Mxl, Mwxh, Mwxl, Mwgh,
                                         b_x, b_g, pu, pg);
    gemm_tma<2, 1, 4><<<gridH, 256, SMEM_G1>>>(Mxh, Mxh, Mwdh, Mwdh, b_dt,
                                               nullptr, pdt, HIDDEN, D_MODEL);

    disc_kernel<<<(HIDDEN * D_STATE + 255) / 256, 256>>>(A_raw, B_ssm);

    scan1_kernel<<<(BATCH * NCHK * HIDDEN) / 128, 128>>>(C_ssm, conv_w, conv_b);
    scan2_kernel<<<(BATCH * HIDDEN * D_STATE) / 256, 256>>>();
    scan3_kernel<<<(BATCH * NCHK * HIDDEN) / 128, 128>>>(C_ssm);

    gemm_tma<0, 3, 3><<<gridD, 256, SMEM_G3>>>(Myh, Myl, Mwoh, Mwol, b_out,
                                               pout, nullptr, D_MODEL, HIDDEN);

    ln_kernel<<<MTOK, 256>>>(x, ln_g, ln_b, out);
}

// round 8
// speedup vs baseline: 4.0574x; 1.0074x over previous
#include <cuda_runtime.h>
#include <cuda_bf16.h>
#include <cuda.h>
#include <dlfcn.h>
#include <cstdint>

#define D_MODEL 1024
#define HIDDEN  2048
#define D_STATE 16
#define BATCH   2
#define SEQ     2048
#define MTOK    4096
#define NCHK    16
#define CHK     128

// ---------------- GEMM tiling -------------------------------------------------
#define BM 128
#define BN 128
#define BKE 64
#define RB 128
#define TILE_B (128 * 128)
#define UG_STAGE (5 * TILE_B)                 // Ahi,Alo,Xhi,Xlo,Ghi
#define SMEM_UG (2 * UG_STAGE + 1024)         // 164864
#define SMEM_OUT (3 * 4 * TILE_B + 1024)      // 197632 (3-stage, 4 tiles)
#define SMEM_DT (3 * 2 * TILE_B + 1024)       // 99328  (3-stage, 2 tiles, 2 CTA/SM)

// ---------------- scratch ----------------------------------------------------
__device__ float g_u[(size_t)MTOK * HIDDEN];
__device__ float g_g[(size_t)MTOK * HIDDEN];
__device__ float g_outp[(size_t)MTOK * D_MODEL];
__device__ float g_dtpart[(MTOK / BM) * HIDDEN];
__device__ float g_Ad[HIDDEN * D_STATE];
__device__ float g_Bd[HIDDEN * D_STATE];
__device__ float g_state[(size_t)BATCH * NCHK * HIDDEN * D_STATE];
__device__ float g_init[(size_t)BATCH * NCHK * HIDDEN * D_STATE];

__device__ __nv_bfloat16 g_xhi[(size_t)MTOK * D_MODEL];
__device__ __nv_bfloat16 g_xlo[(size_t)MTOK * D_MODEL];
__device__ __nv_bfloat16 g_wxhi[HIDDEN * D_MODEL];
__device__ __nv_bfloat16 g_wxlo[HIDDEN * D_MODEL];
__device__ __nv_bfloat16 g_wghi[HIDDEN * D_MODEL];
__device__ __nv_bfloat16 g_wdthi[HIDDEN * D_MODEL];
__device__ __nv_bfloat16 g_wohi[D_MODEL * HIDDEN];
__device__ __nv_bfloat16 g_wolo[D_MODEL * HIDDEN];
__device__ __nv_bfloat16 g_yhi[(size_t)MTOK * HIDDEN];
__device__ __nv_bfloat16 g_ylo[(size_t)MTOK * HIDDEN];

// ---------------- helpers ----------------------------------------------------
__device__ __forceinline__ float softplusf(float x) {
    return fmaxf(x, 0.f) + log1pf(expf(-fabsf(x)));
}
__device__ __forceinline__ float sigmoidf_(float x) {
    return 1.f / (1.f + expf(-x));
}
__device__ __forceinline__ uint32_t smem_u32(const void* p) {
    uint32_t a;
    asm("{ .reg .u64 t; cvta.to.shared.u64 t, %1; cvt.u32.u64 %0, t; }"
        : "=r"(a) : "l"(p));
    return a;
}
__device__ __forceinline__ void ldm_x4(uint32_t* r, uint32_t addr) {
    asm volatile("ldmatrix.sync.aligned.m8n8.x4.shared.b16 {%0,%1,%2,%3}, [%4];"
                 : "=r"(r[0]), "=r"(r[1]), "=r"(r[2]), "=r"(r[3]) : "r"(addr));
}
__device__ __forceinline__ void mma_bf16(float* d, const uint32_t* a,
                                         const uint32_t* b) {
    asm volatile(
        "mma.sync.aligned.m16n8k16.row.col.f32.bf16.bf16.f32 "
        "{%0,%1,%2,%3}, {%4,%5,%6,%7}, {%8,%9}, {%0,%1,%2,%3};"
        : "+f"(d[0]), "+f"(d[1]), "+f"(d[2]), "+f"(d[3])
        : "r"(a[0]), "r"(a[1]), "r"(a[2]), "r"(a[3]), "r"(b[0]), "r"(b[1]));
}
__device__ __forceinline__ void mbar_init(uint32_t addr) {
    asm volatile("mbarrier.init.shared.b64 [%0], 1;" :: "r"(addr) : "memory");
}
__device__ __forceinline__ void mbar_expect(uint32_t addr, uint32_t bytes) {
    asm volatile("mbarrier.arrive.expect_tx.shared.b64 _, [%0], %1;"
                 :: "r"(addr), "r"(bytes) : "memory");
}
__device__ __forceinline__ void mbar_wait(uint32_t addr, uint32_t parity) {
    asm volatile(
        "{\n\t.reg .pred P;\n\t"
        "W_%=:\n\t"
        "mbarrier.try_wait.parity.acquire.cta.shared::cta.b64 P, [%0], %1, 0x989680;\n\t"
        "@P bra D_%=;\n\t"
        "bra W_%=;\n\t"
        "D_%=:\n\t}"
        :: "r"(addr), "r"(parity) : "memory");
}
__device__ __forceinline__ void tma2d(uint32_t smaddr, const CUtensorMap* m,
                                      int cx, int cy, uint32_t mbar) {
    asm volatile(
        "cp.async.bulk.tensor.2d.shared::cta.global.tile.mbarrier::complete_tx::bytes "
        "[%0], [%1, {%2, %3}], [%4];"
        :: "r"(smaddr), "l"(m), "r"(cx), "r"(cy), "r"(mbar) : "memory");
}

// ---------------- fp32 -> bf16 hi/lo split (x) --------------------------------
__global__ __launch_bounds__(256) void split_kernel(
    const float4* __restrict__ src, __nv_bfloat162* __restrict__ hi,
    __nv_bfloat162* __restrict__ lo, int n4)
{
    int i = blockIdx.x * blockDim.x + threadIdx.x;
    if (i >= n4) return;
    float4 v = src[i];
    __nv_bfloat16 h0 = __float2bfloat16(v.x);
    __nv_bfloat16 h1 = __float2bfloat16(v.y);
    __nv_bfloat16 h2 = __float2bfloat16(v.z);
    __nv_bfloat16 h3 = __float2bfloat16(v.w);
    hi[i * 2 + 0] = __nv_bfloat162(h0, h1);
    hi[i * 2 + 1] = __nv_bfloat162(h2, h3);
    if (lo) {
        __nv_bfloat16 l0 = __float2bfloat16(v.x - __bfloat162float(h0));
        __nv_bfloat16 l1 = __float2bfloat16(v.y - __bfloat162float(h1));
        __nv_bfloat16 l2 = __float2bfloat16(v.z - __bfloat162float(h2));
        __nv_bfloat16 l3 = __float2bfloat16(v.w - __bfloat162float(h3));
        lo[i * 2 + 0] = __nv_bfloat162(l0, l1);
        lo[i * 2 + 1] = __nv_bfloat162(l2, l3);
    }
}

// ---------------- fused weight split ------------------------------------------
#define WN4 (HIDDEN * D_MODEL / 4)   // 524288 = 2^19
__global__ __launch_bounds__(256) void split_w_kernel(
    const float4* __restrict__ wx, const float4* __restrict__ wg,
    const float4* __restrict__ wdt, const float4* __restrict__ wo)
{
    int gi = blockIdx.x * blockDim.x + threadIdx.x;
    int arr = gi >> 19;
    int i = gi & (WN4 - 1);
    const float4* src = (arr == 0) ? wx : (arr == 1) ? wg : (arr == 2) ? wdt : wo;
    __nv_bfloat162* hi = (arr == 0) ? (__nv_bfloat162*)g_wxhi
                       : (arr == 1) ? (__nv_bfloat162*)g_wghi
                       : (arr == 2) ? (__nv_bfloat162*)g_wdthi
                                    : (__nv_bfloat162*)g_wohi;
    __nv_bfloat162* lo = (arr == 0) ? (__nv_bfloat162*)g_wxlo
                       : (arr == 3) ? (__nv_bfloat162*)g_wolo : nullptr;
    float4 v = src[i];
    __nv_bfloat16 h0 = __float2bfloat16(v.x);
    __nv_bfloat16 h1 = __float2bfloat16(v.y);
    __nv_bfloat16 h2 = __float2bfloat16(v.z);
    __nv_bfloat16 h3 = __float2bfloat16(v.w);
    hi[i * 2 + 0] = __nv_bfloat162(h0, h1);
    hi[i * 2 + 1] = __nv_bfloat162(h2, h3);
    if (lo) {
        __nv_bfloat16 l0 = __float2bfloat16(v.x - __bfloat162float(h0));
        __nv_bfloat16 l1 = __float2bfloat16(v.y - __bfloat162float(h1));
        __nv_bfloat16 l2 = __float2bfloat16(v.z - __bfloat162float(h2));
        __nv_bfloat16 l3 = __float2bfloat16(v.w - __bfloat162float(h3));
        lo[i * 2 + 0] = __nv_bfloat162(l0, l1);
        lo[i * 2 + 1] = __nv_bfloat162(l2, l3);
    }
}

// ---------------- fused u + gate GEMM (TMA, 2-stage, 5 tiles) ----------------
__global__ __launch_bounds__(256, 1) void gemm_ug_tma(
    const __grid_constant__ CUtensorMap mAh, const __grid_constant__ CUtensorMap mAl,
    const __grid_constant__ CUtensorMap mXh, const __grid_constant__ CUtensorMap mXl,
    const __grid_constant__ CUtensorMap mGh,
    const float* __restrict__ bx, const float* __restrict__ bg,
    float* __restrict__ Cu, float* __restrict__ Cg)
{
    const int N = HIDDEN;
    extern __shared__ char smraw[];
    uint32_t sb = (smem_u32(smraw) + 1023u) & ~1023u;
    __shared__ uint64_t mbarS[2];
    uint32_t mb = smem_u32(mbarS);

    const int tid = threadIdx.x;
    const int wid = tid >> 5, lane = tid & 31;
    const int wm = wid & 1, wn = wid >> 1;
    const int am0 = blockIdx.y * BM;
    const int bn0 = blockIdx.x * BN;

    if (tid == 0) { mbar_init(mb); mbar_init(mb + 8); }
    __syncthreads();

    auto issue = [&](int s) {
        if (tid != 0) return;
        uint32_t bar = mb + (uint32_t)(s & 1) * 8;
        mbar_expect(bar, UG_STAGE);
        uint32_t st = sb + (uint32_t)(s & 1) * UG_STAGE;
        int kc = s * BKE;
        tma2d(st + 0 * TILE_B, &mAh, kc, am0, bar);
        tma2d(st + 1 * TILE_B, &mAl, kc, am0, bar);
        tma2d(st + 2 * TILE_B, &mXh, kc, bn0, bar);
        tma2d(st + 3 * TILE_B, &mXl, kc, bn0, bar);
        tma2d(st + 4 * TILE_B, &mGh, kc, bn0, bar);
    };
    issue(0); issue(1);

    float acc_u[4][4][4], acc_g[4][4][4];
#pragma unroll
    for (int i = 0; i < 4; i++)
#pragma unroll
        for (int j = 0; j < 4; j++)
#pragma unroll
            for (int v = 0; v < 4; v++) { acc_u[i][j][v] = 0.f; acc_g[i][j][v] = 0.f; }

    const int arA = wm * 64 + (lane & 15);
    const int ahalf = lane >> 4;
    const uint32_t axor = (uint32_t)(arA & 7);
    uint32_t aoff[4];
#pragma unroll
    for (int mf = 0; mf < 4; mf++) aoff[mf] = (uint32_t)(arA + mf * 16) * RB;

    const int nrB = wn * 32 + (lane & 7) + ((lane >> 4) << 3);
    const int khalf = (lane >> 3) & 1;
    const uint32_t bxor = (uint32_t)(nrB & 7);
    uint32_t boff[2];
#pragma unroll
    for (int nf = 0; nf < 2; nf++) boff[nf] = (uint32_t)(nrB + nf * 16) * RB;

    const int NCH = D_MODEL / BKE;   // 16
    for (int ch = 0; ch < NCH; ch++) {
        mbar_wait(mb + (uint32_t)(ch & 1) * 8, (uint32_t)((ch >> 1) & 1));
        const uint32_t st = sb + (uint32_t)(ch & 1) * UG_STAGE;

#pragma unroll
        for (int ks = 0; ks < 4; ks++) {
            const uint32_t asg = (((uint32_t)(ks * 2 + ahalf)) ^ axor) << 4;
            const uint32_t bsg = (((uint32_t)(ks * 2 + khalf)) ^ bxor) << 4;
            uint32_t ah[4][4], al[4][4];
#pragma unroll
            for (int mf = 0; mf < 4; mf++) {
                ldm_x4(ah[mf], st + 0 * TILE_B + aoff[mf] + asg);
                ldm_x4(al[mf], st + 1 * TILE_B + aoff[mf] + asg);
            }
            {
                uint32_t bh[4][2], bl[4][2];
#pragma unroll
                for (int nf = 0; nf < 2; nf++) {
                    uint32_t rr[4];
                    ldm_x4(rr, st + 2 * TILE_B + boff[nf] + bsg);
                    bh[nf * 2 + 0][0] = rr[0]; bh[nf * 2 + 0][1] = rr[1];
                    bh[nf * 2 + 1][0] = rr[2]; bh[nf * 2 + 1][1] = rr[3];
                    ldm_x4(rr, st + 3 * TILE_B + boff[nf] + bsg);
                    bl[nf * 2 + 0][0] = rr[0]; bl[nf * 2 + 0][1] = rr[1];
                    bl[nf * 2 + 1][0] = rr[2]; bl[nf * 2 + 1][1] = rr[3];
                }
#pragma unroll
                for (int mf = 0; mf < 4; mf++)
#pragma unroll
                    for (int nfi = 0; nfi < 4; nfi++) {
                        mma_bf16(acc_u[mf][nfi], ah[mf], bh[nfi]);
                        mma_bf16(acc_u[mf][nfi], ah[mf], bl[nfi]);
                        mma_bf16(acc_u[mf][nfi], al[mf], bh[nfi]);
                    }
            }
            {
                uint32_t gh[4][2];
#pragma unroll
                for (int nf = 0; nf < 2; nf++) {
                    uint32_t rr[4];
                    ldm_x4(rr, st + 4 * TILE_B + boff[nf] + bsg);
                    gh[nf * 2 + 0][0] = rr[0]; gh[nf * 2 + 0][1] = rr[1];
                    gh[nf * 2 + 1][0] = rr[2]; gh[nf * 2 + 1][1] = rr[3];
                }
#pragma unroll
                for (int mf = 0; mf < 4; mf++)
#pragma unroll
                    for (int nfi = 0; nfi < 4; nfi++) {
                        mma_bf16(acc_g[mf][nfi], ah[mf], gh[nfi]);
                        mma_bf16(acc_g[mf][nfi], al[mf], gh[nfi]);
                    }
            }
        }
        __syncthreads();
        if (ch + 2 < NCH) issue(ch + 2);
    }

#pragma unroll
    for (int mf = 0; mf < 4; mf++) {
        const int r0 = am0 + wm * 64 + mf * 16 + (lane >> 2);
#pragma unroll
        for (int h = 0; h < 2; h++) {
            const int row = r0 + h * 8;
#pragma unroll
            for (int nfi = 0; nfi < 4; nfi++) {
                const int col = bn0 + wn * 32 + nfi * 8 + (lane & 3) * 2;
                float u0 = acc_u[mf][nfi][h * 2 + 0] + bx[col];
                float u1 = acc_u[mf][nfi][h * 2 + 1] + bx[col + 1];
                float g0 = sigmoidf_(acc_g[mf][nfi][h * 2 + 0] + bg[col]);
                float g1 = sigmoidf_(acc_g[mf][nfi][h * 2 + 1] + bg[col + 1]);
                *(float2*)&Cu[(size_t)row * N + col] = make_float2(u0, u1);
                *(float2*)&Cg[(size_t)row * N + col] = make_float2(g0, g1);
            }
        }
    }
}

// ---------------- dt GEMM: 1-term, 3-stage, 2 CTAs/SM -------------------------
__global__ __launch_bounds__(256, 2) void gemm_dt(
    const __grid_constant__ CUtensorMap mAh, const __grid_constant__ CUtensorMap mBh,
    const float* __restrict__ bias, float* __restrict__ colsum)
{
    constexpr int NS = 3;
    constexpr uint32_t STAGE = 2 * TILE_B;
    constexpr uint32_t BHOFF = 1 * TILE_B;
    const int N = HIDDEN, K = D_MODEL;

    extern __shared__ char smraw[];
    uint32_t sb = (smem_u32(smraw) + 1023u) & ~1023u;
    __shared__ uint64_t mbarS[NS];
    uint32_t mb = smem_u32(mbarS);

    const int tid = threadIdx.x;
    const int wid = tid >> 5, lane = tid & 31;
    const int wm = wid & 1, wn = wid >> 1;
    const int am0 = blockIdx.y * BM;
    const int bn0 = blockIdx.x * BN;

    if (tid == 0) {
#pragma unroll
        for (int s = 0; s < NS; s++) mbar_init(mb + s * 8);
    }
    __syncthreads();

    auto issue = [&](int s) {
        if (tid != 0) return;
        int slot = s % NS;
        uint32_t bar = mb + (uint32_t)slot * 8;
        mbar_expect(bar, STAGE);
        uint32_t st = sb + (uint32_t)slot * STAGE;
        int kc = s * BKE;
        tma2d(st, &mAh, kc, am0, bar);
        tma2d(st + BHOFF, &mBh, kc, bn0, bar);
    };
    const int NCH = K / BKE;
#pragma unroll
    for (int s = 0; s < NS; s++) if (s < NCH) issue(s);

    float acc[4][4][4];
#pragma unroll
    for (int i = 0; i < 4; i++)
#pragma unroll
        for (int j = 0; j < 4; j++)
#pragma unroll
            for (int v = 0; v < 4; v++) acc[i][j][v] = 0.f;

    const int arA = wm * 64 + (lane & 15);
    const int ahalf = lane >> 4;
    const uint32_t axor = (uint32_t)(arA & 7);
    uint32_t aoff[4];
#pragma unroll
    for (int mf = 0; mf < 4; mf++) aoff[mf] = (uint32_t)(arA + mf * 16) * RB;

    const int nrB = wn * 32 + (lane & 7) + ((lane >> 4) << 3);
    const int khalf = (lane >> 3) & 1;
    const uint32_t bxor = (uint32_t)(nrB & 7);
    uint32_t boff[2];
#pragma unroll
    for (int nf = 0; nf < 2; nf++) boff[nf] = (uint32_t)(nrB + nf * 16) * RB;

    for (int ch = 0; ch < NCH; ch++) {
        int slot = ch % NS;
        mbar_wait(mb + (uint32_t)slot * 8, (uint32_t)((ch / NS) & 1));
        const uint32_t st = sb + (uint32_t)slot * STAGE;

#pragma unroll
        for (int ks = 0; ks < 4; ks++) {
            uint32_t a[4][4], bh[4][2];
            const uint32_t asg = (((uint32_t)(ks * 2 + ahalf)) ^ axor) << 4;
            const uint32_t bsg = (((uint32_t)(ks * 2 + khalf)) ^ bxor) << 4;
#pragma unroll
            for (int nf = 0; nf < 2; nf++) {
                uint32_t rr[4];
                ldm_x4(rr, st + BHOFF + boff[nf] + bsg);
                bh[nf * 2 + 0][0] = rr[0]; bh[nf * 2 + 0][1] = rr[1];
                bh[nf * 2 + 1][0] = rr[2]; bh[nf * 2 + 1][1] = rr[3];
            }
#pragma unroll
            for (int mf = 0; mf < 4; mf++) ldm_x4(a[mf], st + aoff[mf] + asg);
#pragma unroll
            for (int mf = 0; mf < 4; mf++)
#pragma unroll
                for (int nfi = 0; nfi < 4; nfi++)
                    mma_bf16(acc[mf][nfi], a[mf], bh[nfi]);
        }
        __syncthreads();
        if (ch + NS < NCH) issue(ch + NS);
    }

    float* red = (float*)smraw;
#pragma unroll
    for (int nfi = 0; nfi < 4; nfi++) {
        const int colb = bn0 + wn * 32 + nfi * 8 + (lane & 3) * 2;
        const float b0 = bias[colb], b1 = bias[colb + 1];
        float s0 = 0.f, s1 = 0.f;
#pragma unroll
        for (int mf = 0; mf < 4; mf++) {
            s0 += softplusf(acc[mf][nfi][0] + b0);
            s1 += softplusf(acc[mf][nfi][1] + b1);
            s0 += softplusf(acc[mf][nfi][2] + b0);
            s1 += softplusf(acc[mf][nfi][3] + b1);
        }
#pragma unroll
        for (int o = 4; o <= 16; o <<= 1) {
            s0 += __shfl_xor_sync(0xffffffffu, s0, o);
            s1 += __shfl_xor_sync(0xffffffffu, s1, o);
        }
        if (lane < 4) {
            int c = wn * 32 + nfi * 8 + lane * 2;
            red[wm * 128 + c] = s0;
            red[wm * 128 + c + 1] = s1;
        }
    }
    __syncthreads();
    if (tid < 128)
        colsum[(size_t)blockIdx.y * N + bn0 + tid] = red[tid] + red[128 + tid];
}

// ---------------- out GEMM: 3-term, 3-stage, ks-pipelined fragments ----------
__global__ __launch_bounds__(256, 1) void gemm_out(
    const __grid_constant__ CUtensorMap mAh, const __grid_constant__ CUtensorMap mAl,
    const __grid_constant__ CUtensorMap mBh, const __grid_constant__ CUtensorMap mBl,
    const float* __restrict__ bias, float* __restrict__ C)
{
    constexpr int NS = 3;
    constexpr uint32_t STAGE = 4 * TILE_B;
    constexpr uint32_t ALOFF = 1 * TILE_B;
    constexpr uint32_t BHOFF = 2 * TILE_B;
    constexpr uint32_t BLOFF = 3 * TILE_B;
    const int N = D_MODEL, K = HIDDEN;

    extern __shared__ char smraw[];
    uint32_t sb = (smem_u32(smraw) + 1023u) & ~1023u;
    __shared__ uint64_t mbarS[NS];
    uint32_t mb = smem_u32(mbarS);

    const int tid = threadIdx.x;
    const int wid = tid >> 5, lane = tid & 31;
    const int wm = wid & 1, wn = wid >> 1;
    const int am0 = blockIdx.y * BM;
    const int bn0 = blockIdx.x * BN;

    if (tid == 0) {
#pragma unroll
        for (int s = 0; s < NS; s++) mbar_init(mb + s * 8);
    }
    __syncthreads();

    auto issue = [&](int s) {
        if (tid != 0) return;
        int slot = s % NS;
        uint32_t bar = mb + (uint32_t)slot * 8;
        mbar_expect(bar, STAGE);
        uint32_t st = sb + (uint32_t)slot * STAGE;
        int kc = s * BKE;
        tma2d(st, &mAh, kc, am0, bar);
        tma2d(st + ALOFF, &mAl, kc, am0, bar);
        tma2d(st + BHOFF, &mBh, kc, bn0, bar);
        tma2d(st + BLOFF, &mBl, kc, bn0, bar);
    };
    const int NCH = K / BKE;   // 32
#pragma unroll
    for (int s = 0; s < NS; s++) issue(s);

    float acc[4][4][4];
#pragma unroll
    for (int i = 0; i < 4; i++)
#pragma unroll
        for (int j = 0; j < 4; j++)
#pragma unroll
            for (int v = 0; v < 4; v++) acc[i][j][v] = 0.f;

    const int arA = wm * 64 + (lane & 15);
    const int ahalf = lane >> 4;
    const uint32_t axor = (uint32_t)(arA & 7);
    uint32_t aoff[4];
#pragma unroll
    for (int mf = 0; mf < 4; mf++) aoff[mf] = (uint32_t)(arA + mf * 16) * RB;

    const int nrB = wn * 32 + (lane & 7) + ((lane >> 4) << 3);
    const int khalf = (lane >> 3) & 1;
    const uint32_t bxor = (uint32_t)(nrB & 7);
    uint32_t boff[2];
#pragma unroll
    for (int nf = 0; nf < 2; nf++) boff[nf] = (uint32_t)(nrB + nf * 16) * RB;

    // double-buffered fragments (software pipeline across ks)
    uint32_t ah[2][4][4], al[2][4][4], bh[2][4][2], bl[2][4][2];

    auto load_frags = [&](int buf, uint32_t st, int ks) {
#pragma unroll
        for (int kk = 0; kk < 1; kk++) {   // keep lambda simple
            const uint32_t asg = (((uint32_t)(ks * 2 + ahalf)) ^ axor) << 4;
            const uint32_t bsg = (((uint32_t)(ks * 2 + khalf)) ^ bxor) << 4;
#pragma unroll
            for (int nf = 0; nf < 2; nf++) {
                uint32_t rr[4];
                ldm_x4(rr, st + BHOFF + boff[nf] + bsg);
                bh[buf][nf * 2 + 0][0] = rr[0]; bh[buf][nf * 2 + 0][1] = rr[1];
                bh[buf][nf * 2 + 1][0] = rr[2]; bh[buf][nf * 2 + 1][1] = rr[3];
                ldm_x4(rr, st + BLOFF + boff[nf] + bsg);
                bl[buf][nf * 2 + 0][0] = rr[0]; bl[buf][nf * 2 + 0][1] = rr[1];
                bl[buf][nf * 2 + 1][0] = rr[2]; bl[buf][nf * 2 + 1][1] = rr[3];
            }
#pragma unroll
            for (int mf = 0; mf < 4; mf++) {
                ldm_x4(ah[buf][mf], st + aoff[mf] + asg);
                ldm_x4(al[buf][mf], st + ALOFF + aoff[mf] + asg);
            }
        }
    };

    for (int ch = 0; ch < NCH; ch++) {
        int slot = ch % NS;
        mbar_wait(mb + (uint32_t)slot * 8, (uint32_t)((ch / NS) & 1));
        const uint32_t st = sb + (uint32_t)slot * STAGE;

        load_frags(0, st, 0);
#pragma unroll
        for (int ks = 0; ks < 4; ks++) {
            const int cur = ks & 1;
            if (ks < 3) load_frags(cur ^ 1, st, ks + 1);
#pragma unroll
            for (int mf = 0; mf < 4; mf++)
#pragma unroll
                for (int nfi = 0; nfi < 4; nfi++) {
                    mma_bf16(acc[mf][nfi], ah[cur][mf], bh[cur][nfi]);
                    mma_bf16(acc[mf][nfi], ah[cur][mf], bl[cur][nfi]);
                    mma_bf16(acc[mf][nfi], al[cur][mf], bh[cur][nfi]);
                }
        }
        __syncthreads();
        if (ch + NS < NCH) issue(ch + NS);
    }

#pragma unroll
    for (int mf = 0; mf < 4; mf++) {
        const int r0 = am0 + wm * 64 + mf * 16 + (lane >> 2);
#pragma unroll
        for (int h = 0; h < 2; h++) {
            const int row = r0 + h * 8;
#pragma unroll
            for (int nfi = 0; nfi < 4; nfi++) {
                const int col = bn0 + wn * 32 + nfi * 8 + (lane & 3) * 2;
                float v0 = acc[mf][nfi][h * 2 + 0] + bias[col];
                float v1 = acc[mf][nfi][h * 2 + 1] + bias[col + 1];
                *(float2*)&C[(size_t)row * N + col] = make_float2(v0, v1);
            }
        }
    }
}

// ---------------- dt finalize + discretization --------------------------------
__global__ void disc_kernel(const float* __restrict__ A_raw,
                            const float* __restrict__ B_ssm)
{
    int idx = blockIdx.x * blockDim.x + threadIdx.x;
    if (idx >= HIDDEN * D_STATE) return;
    int h = idx / D_STATE;
    float sum = 0.f;
#pragma unroll
    for (int p = 0; p < MTOK / BM; p++) sum += g_dtpart[p * HIDDEN + h];
    float dt = sum * (1.f / (float)MTOK);
    dt = fminf(fmaxf(dt, 1e-3f), 2.0f);
    float a = -softplusf(A_raw[idx]);
    float ad = expf(a * dt);
    float bd = (ad - 1.0f) / (a + 1e-6f) * B_ssm[idx];
    g_Ad[idx] = ad;
    g_Bd[idx] = bd;
}

// ---------------- scan pass 1: fused conv+gate + chunk-local scan ------------
__global__ __launch_bounds__(128) void scan1_kernel(
    const float* __restrict__ C_ssm, const float* __restrict__ conv_w,
    const float* __restrict__ conv_b)
{
    int idx = blockIdx.x * blockDim.x + threadIdx.x;
    int h = idx & (HIDDEN - 1);
    int bc = idx >> 11;
    int c = bc & (NCHK - 1);

    float ad[D_STATE], bd[D_STATE], cc[D_STATE], st[D_STATE];
#pragma unroll
    for (int j = 0; j < D_STATE; j++) {
        ad[j] = g_Ad[h * D_STATE + j];
        bd[j] = g_Bd[h * D_STATE + j];
        cc[j] = C_ssm[h * D_STATE + j];
        st[j] = 0.f;
    }
    const float w0 = conv_w[h * 3 + 0], w1 = conv_w[h * 3 + 1],
                w2 = conv_w[h * 3 + 2], cb = conv_b[h];

    const int b = bc >> 4;
    const int l0 = c * CHK;
    const size_t base = ((size_t)b * SEQ + l0) * HIDDEN + h;
    const float* up = g_u + base;
    float* gp = g_g + base;

    float um = (l0 > 0) ? up[-(ptrdiff_t)HIDDEN] : 0.f;
    float cu[4], cg[4];
#pragma unroll
    for (int q = 0; q < 4; q++) {
        cu[q] = up[(size_t)q * HIDDEN];
        cg[q] = gp[(size_t)q * HIDDEN];
    }

    for (int t = 0; t < CHK; t += 4) {
        float nu[4], ng[4];
#pragma unroll
        for (int q = 0; q < 4; q++) {
            int l = l0 + t + 4 + q;
            nu[q] = (l < SEQ) ? up[(size_t)(t + 4 + q) * HIDDEN] : 0.f;
            int tt = t + 4 + q;
            ng[q] = (tt < CHK) ? gp[(size_t)tt * HIDDEN] : 0.f;
        }
#pragma unroll
        for (int q = 0; q < 4; q++) {
            float u0 = cu[q];
            float upn = (q < 3) ? cu[q + 1] : nu[0];
            float hc = cb + w0 * um + w1 * u0 + w2 * upn;
            float g = cg[q];
            float uc = u0 * g + hc * (1.f - g);
            float y0 = 0.f, y1 = 0.f, y2 = 0.f, y3 = 0.f;
#pragma unroll
            for (int j = 0; j < D_STATE; j++)
                st[j] = fmaf(ad[j], st[j], bd[j] * uc);
#pragma unroll
            for (int j = 0; j < D_STATE; j += 4) {
                y0 = fmaf(st[j + 0], cc[j + 0], y0);
                y1 = fmaf(st[j + 1], cc[j + 1], y1);
                y2 = fmaf(st[j + 2], cc[j + 2], y2);
                y3 = fmaf(st[j + 3], cc[j + 3], y3);
            }
            gp[(size_t)(t + q) * HIDDEN] = (y0 + y1) + (y2 + y3);
            um = u0;
        }
#pragma unroll
        for (int q = 0; q < 4; q++) { cu[q] = nu[q]; cg[q] = ng[q]; }
    }
    float* sp = g_state + (size_t)idx * D_STATE;
#pragma unroll
    for (int j = 0; j < D_STATE; j += 4)
        *(float4*)&sp[j] = make_float4(st[j], st[j + 1], st[j + 2], st[j + 3]);
}

// ---------------- scan pass 2: chunk-state prefix ----------------------------
__global__ __launch_bounds__(256) void scan2_kernel()
{
    int idx = blockIdx.x * blockDim.x + threadIdx.x;
    int j = idx & (D_STATE - 1);
    int h = (idx >> 4) & (HIDDEN - 1);
    int b = idx >> 15;

    float ad = g_Ad[h * D_STATE + j];
    float af = ad;
#pragma unroll
    for (int i = 0; i < 7; i++) af = af * af;

    float carry = 0.f;
#pragma unroll
    for (int c = 0; c < NCHK; c++) {
        size_t off = (((size_t)b * NCHK + c) * HIDDEN + h) * D_STATE + j;
        g_init[off] = carry;
        carry = fmaf(af, carry, g_state[off]);
    }
}

// ---------------- scan pass 3: fixup + bf16 split ----------------------------
__global__ __launch_bounds__(128) void scan3_kernel(const float* __restrict__ C_ssm)
{
    int idx = blockIdx.x * blockDim.x + threadIdx.x;
    int h = idx & (HIDDEN - 1);
    int bc = idx >> 11;
    int c = bc & (NCHK - 1);
    int b = bc >> 4;

    const size_t base = ((size_t)b * SEQ + (size_t)c * CHK) * HIDDEN + h;
    const float* yp = g_g + base;
    __nv_bfloat16* yh = g_yhi + base;
    __nv_bfloat16* yl = g_ylo + base;

    if (c == 0) {
        for (int t = 0; t < CHK; t++) {
            float yv = yp[(size_t)t * HIDDEN];
            __nv_bfloat16 hi = __float2bfloat16(yv);
            __nv_bfloat16 lo = __float2bfloat16(yv - __bfloat162float(hi));
            yh[(size_t)t * HIDDEN] = hi;
            yl[(size_t)t * HIDDEN] = lo;
        }
        return;
    }

    float ad[D_STATE], cc[D_STATE], p[D_STATE];
    const float* ip = g_init + (size_t)idx * D_STATE;
#pragma unroll
    for (int j = 0; j < D_STATE; j++) {
        ad[j] = g_Ad[h * D_STATE + j];
        cc[j] = C_ssm[h * D_STATE + j];
        p[j] = ip[j];
    }
    for (int t = 0; t < CHK; t++) {
        float y0 = 0.f, y1 = 0.f, y2 = 0.f, y3 = 0.f;
#pragma unroll
        for (int j = 0; j < D_STATE; j++) p[j] *= ad[j];
#pragma unroll
        for (int j = 0; j < D_STATE; j += 4) {
            y0 = fmaf(p[j + 0], cc[j + 0], y0);
            y1 = fmaf(p[j + 1], cc[j + 1], y1);
            y2 = fmaf(p[j + 2], cc[j + 2], y2);
            y3 = fmaf(p[j + 3], cc[j + 3], y3);
        }
        float yv = yp[(size_t)t * HIDDEN] + ((y0 + y1) + (y2 + y3));
        __nv_bfloat16 hi = __float2bfloat16(yv);
        __nv_bfloat16 lo = __float2bfloat16(yv - __bfloat162float(hi));
        yh[(size_t)t * HIDDEN] = hi;
        yl[(size_t)t * HIDDEN] = lo;
    }
}

// ---------------- residual + layernorm ---------------------------------------
__global__ __launch_bounds__(256) void ln_kernel(
    const float* __restrict__ x, const float* __restrict__ lng,
    const float* __restrict__ lnb, float* __restrict__ out)
{
    int row = blockIdx.x;
    __shared__ float sh[D_MODEL];
    __shared__ float rs[20];
    const float* xr = x + (size_t)row * D_MODEL;
    const float* orow = g_outp + (size_t)row * D_MODEL;
    int tid = threadIdx.x;

    float s = 0.f, sq = 0.f;
    for (int i = tid; i < D_MODEL; i += 256) {
        float r = xr[i] + orow[i];
        sh[i] = r;
        s += r;
        sq += r * r;
    }
#pragma unroll
    for (int o = 16; o > 0; o >>= 1) {
        s += __shfl_xor_sync(0xffffffffu, s, o);
        sq += __shfl_xor_sync(0xffffffffu, sq, o);
    }
    int w = tid >> 5, ln = tid & 31;
    if (ln == 0) { rs[w] = s; rs[8 + w] = sq; }
    __syncthreads();
    if (tid == 0) {
        float ts = 0.f, tq = 0.f;
#pragma unroll
        for (int i = 0; i < 8; i++) { ts += rs[i]; tq += rs[8 + i]; }
        float mean = ts * (1.f / (float)D_MODEL);
        float var = tq * (1.f / (float)D_MODEL) - mean * mean;
        rs[16] = mean;
        rs[17] = rsqrtf(var + 1e-5f);
    }
    __syncthreads();
    float mean = rs[16], inv = rs[17];
    for (int i = tid; i < D_MODEL; i += 256)
        out[(size_t)row * D_MODEL + i] = (sh[i] - mean) * inv * lng[i] + lnb[i];
}

// ---------------- host: tensormap encode via dlopen ---------------------------
typedef CUresult (*PFN_encode)(CUtensorMap*, CUtensorMapDataType, cuuint32_t, void*,
    const cuuint64_t*, const cuuint64_t*, const cuuint32_t*, const cuuint32_t*,
    CUtensorMapInterleave, CUtensorMapSwizzle, CUtensorMapL2promotion,
    CUtensorMapFloatOOBfill);

static void make_map(PFN_encode enc, CUtensorMap* m, void* ptr, int rows, int K)
{
    cuuint64_t dims[2] = {(cuuint64_t)K, (cuuint64_t)rows};
    cuuint64_t strides[1] = {(cuuint64_t)K * 2};
    cuuint32_t box[2] = {64u, 128u};
    cuuint32_t es[2] = {1u, 1u};
    enc(m, CU_TENSOR_MAP_DATA_TYPE_BFLOAT16, 2, ptr, dims, strides, box, es,
        CU_TENSOR_MAP_INTERLEAVE_NONE, CU_TENSOR_MAP_SWIZZLE_128B,
        CU_TENSOR_MAP_L2_PROMOTION_L2_128B, CU_TENSOR_MAP_FLOAT_OOB_FILL_NONE);
}

// ---------------- launch -----------------------------------------------------
extern "C" void kernel_launch(void* const* d_in, const int* in_sizes, int n_in,
                              void* d_out, int out_size)
{
    const float* x      = (const float*)d_in[0];
    const float* W_x    = (const float*)d_in[1];
    const float* b_x    = (const float*)d_in[2];
    const float* W_g    = (const float*)d_in[3];
    const float* b_g    = (const float*)d_in[4];
    const float* conv_w = (const float*)d_in[5];
    const float* conv_b = (const float*)d_in[6];
    const float* A_raw  = (const float*)d_in[7];
    const float* B_ssm  = (const float*)d_in[8];
    const float* C_ssm  = (const float*)d_in[9];
    const float* W_dt   = (const float*)d_in[10];
    const float* b_dt   = (const float*)d_in[11];
    const float* W_out  = (const float*)d_in[12];
    const float* b_out  = (const float*)d_in[13];
    const float* ln_g   = (const float*)d_in[14];
    const float* ln_b   = (const float*)d_in[15];
    float* out = (float*)d_out;

    float *pu, *pg, *pdt, *pout;
    __nv_bfloat16 *pxh, *pxl, *pwxh, *pwxl, *pwgh, *pwdh, *pwoh, *pwol, *pyh, *pyl;
    cudaGetSymbolAddress((void**)&pu, g_u);
    cudaGetSymbolAddress((void**)&pg, g_g);
    cudaGetSymbolAddress((void**)&pdt, g_dtpart);
    cudaGetSymbolAddress((void**)&pout, g_outp);
    cudaGetSymbolAddress((void**)&pxh, g_xhi);
    cudaGetSymbolAddress((void**)&pxl, g_xlo);
    cudaGetSymbolAddress((void**)&pwxh, g_wxhi);
    cudaGetSymbolAddress((void**)&pwxl, g_wxlo);
    cudaGetSymbolAddress((void**)&pwgh, g_wghi);
    cudaGetSymbolAddress((void**)&pwdh, g_wdthi);
    cudaGetSymbolAddress((void**)&pwoh, g_wohi);
    cudaGetSymbolAddress((void**)&pwol, g_wolo);
    cudaGetSymbolAddress((void**)&pyh, g_yhi);
    cudaGetSymbolAddress((void**)&pyl, g_ylo);

    void* dl = dlopen("libcuda.so.1", RTLD_NOW);
    if (!dl) dl = dlopen("libcuda.so", RTLD_NOW);
    PFN_encode enc = dl ? (PFN_encode)dlsym(dl, "cuTensorMapEncodeTiled") : nullptr;

    CUtensorMap Mxh, Mxl, Mwxh, Mwxl, Mwgh, Mwdh, Mwoh, Mwol, Myh, Myl;
    make_map(enc, &Mxh, pxh, MTOK, D_MODEL);
    make_map(enc, &Mxl, pxl, MTOK, D_MODEL);
    make_map(enc, &Mwxh, pwxh, HIDDEN, D_MODEL);
    make_map(enc, &Mwxl, pwxl, HIDDEN, D_MODEL);
    make_map(enc, &Mwgh, pwgh, HIDDEN, D_MODEL);
    make_map(enc, &Mwdh, pwdh, HIDDEN, D_MODEL);
    make_map(enc, &Mwoh, pwoh, D_MODEL, HIDDEN);
    make_map(enc, &Mwol, pwol, D_MODEL, HIDDEN);
    make_map(enc, &Myh, pyh, MTOK, HIDDEN);
    make_map(enc, &Myl, pyl, MTOK, HIDDEN);

    cudaFuncSetAttribute(gemm_ug_tma, cudaFuncAttributeMaxDynamicSharedMemorySize, SMEM_UG);
    cudaFuncSetAttribute(gemm_out, cudaFuncAttributeMaxDynamicSharedMemorySize, SMEM_OUT);
    cudaFuncSetAttribute(gemm_dt, cudaFuncAttributeMaxDynamicSharedMemorySize, SMEM_DT);

    {
        int n4 = MTOK * D_MODEL / 4;
        split_kernel<<<(n4 + 255) / 256, 256>>>((const float4*)x,
                                                (__nv_bfloat162*)pxh,
                                                (__nv_bfloat162*)pxl, n4);
        split_w_kernel<<<(4 * WN4) / 256, 256>>>((const float4*)W_x,
                                                 (const float4*)W_g,
                                                 (const float4*)W_dt,
                                                 (const float4*)W_out);
    }

    dim3 gridH(HIDDEN / BN, MTOK / BM);    // (16, 32)
    dim3 gridD(D_MODEL / BN, MTOK / BM);   // (8, 32)

    gemm_ug_tma<<<gridH, 256, SMEM_UG>>>(Mxh, Mxl, Mwxh, Mwxl, Mwgh,
                                         b_x, b_g, pu, pg);
    gemm_dt<<<gridH, 256, SMEM_DT>>>(Mxh, Mwdh, b_dt, pdt);

    disc_kernel<<<(HIDDEN * D_STATE + 255) / 256, 256>>>(A_raw, B_ssm);

    scan1_kernel<<<(BATCH * NCHK * HIDDEN) / 128, 128>>>(C_ssm, conv_w, conv_b);
    scan2_kernel<<<(BATCH * HIDDEN * D_STATE) / 256, 256>>>();
    scan3_kernel<<<(BATCH * NCHK * HIDDEN) / 128, 128>>>(C_ssm);

    gemm_out<<<gridD, 256, SMEM_OUT>>>(Myh, Myl, Mwoh, Mwol, b_out, pout);

    ln_kernel<<<MTOK, 256>>>(x, ln_g, ln_b, out);
}

// round 9
// speedup vs baseline: 4.3204x; 1.0648x over previous
#include <cuda_runtime.h>
#include <cuda_bf16.h>
#include <cuda.h>
#include <dlfcn.h>
#include <cstdint>

#define D_MODEL 1024
#define HIDDEN  2048
#define D_STATE 16
#define BATCH   2
#define SEQ     2048
#define MTOK    4096
#define NCHK    16
#define CHK     128

// ---------------- GEMM tiling -------------------------------------------------
#define BM 128
#define BN 128
#define BKE 64
#define RB 128
#define TILE_B (128 * 128)
#define UG_STAGE (5 * TILE_B)                 // Ahi,Alo,Xhi,Xlo,Ghi
#define SMEM_UG (2 * UG_STAGE + 1024)         // 164864
#define SMEM_OUT (3 * 4 * TILE_B + 1024)      // 197632 (3-stage, 4 tiles)
#define SMEM_DT (3 * 2 * TILE_B + 1024)       // 99328  (3-stage, 2 tiles, 2 CTA/SM)

// ---------------- scratch ----------------------------------------------------
__device__ float g_u[(size_t)MTOK * HIDDEN];
__device__ float g_g[(size_t)MTOK * HIDDEN];
__device__ float g_outp[(size_t)MTOK * D_MODEL];
__device__ float g_dtpart[(MTOK / BM) * HIDDEN];
__device__ float g_Ad[HIDDEN * D_STATE];
__device__ float g_Bd[HIDDEN * D_STATE];
__device__ float g_state[(size_t)BATCH * NCHK * HIDDEN * D_STATE];
__device__ float g_init[(size_t)BATCH * NCHK * HIDDEN * D_STATE];

__device__ __nv_bfloat16 g_xhi[(size_t)MTOK * D_MODEL];
__device__ __nv_bfloat16 g_xlo[(size_t)MTOK * D_MODEL];
__device__ __nv_bfloat16 g_wxhi[HIDDEN * D_MODEL];
__device__ __nv_bfloat16 g_wxlo[HIDDEN * D_MODEL];
__device__ __nv_bfloat16 g_wghi[HIDDEN * D_MODEL];
__device__ __nv_bfloat16 g_wdthi[HIDDEN * D_MODEL];
__device__ __nv_bfloat16 g_wohi[D_MODEL * HIDDEN];
__device__ __nv_bfloat16 g_wolo[D_MODEL * HIDDEN];
__device__ __nv_bfloat16 g_yhi[(size_t)MTOK * HIDDEN];
__device__ __nv_bfloat16 g_ylo[(size_t)MTOK * HIDDEN];

// ---------------- helpers ----------------------------------------------------
__device__ __forceinline__ float softplusf(float x) {
    return fmaxf(x, 0.f) + log1pf(expf(-fabsf(x)));
}
__device__ __forceinline__ float sigmoidf_(float x) {
    return 1.f / (1.f + expf(-x));
}
__device__ __forceinline__ uint32_t smem_u32(const void* p) {
    uint32_t a;
    asm("{ .reg .u64 t; cvta.to.shared.u64 t, %1; cvt.u32.u64 %0, t; }"
        : "=r"(a) : "l"(p));
    return a;
}
__device__ __forceinline__ void ldm_x4(uint32_t* r, uint32_t addr) {
    asm volatile("ldmatrix.sync.aligned.m8n8.x4.shared.b16 {%0,%1,%2,%3}, [%4];"
                 : "=r"(r[0]), "=r"(r[1]), "=r"(r[2]), "=r"(r[3]) : "r"(addr));
}
__device__ __forceinline__ void mma_bf16(float* d, const uint32_t* a,
                                         const uint32_t* b) {
    asm volatile(
        "mma.sync.aligned.m16n8k16.row.col.f32.bf16.bf16.f32 "
        "{%0,%1,%2,%3}, {%4,%5,%6,%7}, {%8,%9}, {%0,%1,%2,%3};"
        : "+f"(d[0]), "+f"(d[1]), "+f"(d[2]), "+f"(d[3])
        : "r"(a[0]), "r"(a[1]), "r"(a[2]), "r"(a[3]), "r"(b[0]), "r"(b[1]));
}
__device__ __forceinline__ void mbar_init(uint32_t addr) {
    asm volatile("mbarrier.init.shared.b64 [%0], 1;" :: "r"(addr) : "memory");
}
__device__ __forceinline__ void mbar_expect(uint32_t addr, uint32_t bytes) {
    asm volatile("mbarrier.arrive.expect_tx.shared.b64 _, [%0], %1;"
                 :: "r"(addr), "r"(bytes) : "memory");
}
__device__ __forceinline__ void mbar_wait(uint32_t addr, uint32_t parity) {
    asm volatile(
        "{\n\t.reg .pred P;\n\t"
        "W_%=:\n\t"
        "mbarrier.try_wait.parity.acquire.cta.shared::cta.b64 P, [%0], %1, 0x989680;\n\t"
        "@P bra D_%=;\n\t"
        "bra W_%=;\n\t"
        "D_%=:\n\t}"
        :: "r"(addr), "r"(parity) : "memory");
}
__device__ __forceinline__ void tma2d(uint32_t smaddr, const CUtensorMap* m,
                                      int cx, int cy, uint32_t mbar) {
    asm volatile(
        "cp.async.bulk.tensor.2d.shared::cta.global.tile.mbarrier::complete_tx::bytes "
        "[%0], [%1, {%2, %3}], [%4];"
        :: "r"(smaddr), "l"(m), "r"(cx), "r"(cy), "r"(mbar) : "memory");
}

// ---------------- fp32 -> bf16 hi/lo split (x) --------------------------------
__global__ __launch_bounds__(256) void split_kernel(
    const float4* __restrict__ src, __nv_bfloat162* __restrict__ hi,
    __nv_bfloat162* __restrict__ lo, int n4)
{
    int i = blockIdx.x * blockDim.x + threadIdx.x;
    if (i >= n4) return;
    float4 v = src[i];
    __nv_bfloat16 h0 = __float2bfloat16(v.x);
    __nv_bfloat16 h1 = __float2bfloat16(v.y);
    __nv_bfloat16 h2 = __float2bfloat16(v.z);
    __nv_bfloat16 h3 = __float2bfloat16(v.w);
    hi[i * 2 + 0] = __nv_bfloat162(h0, h1);
    hi[i * 2 + 1] = __nv_bfloat162(h2, h3);
    if (lo) {
        __nv_bfloat16 l0 = __float2bfloat16(v.x - __bfloat162float(h0));
        __nv_bfloat16 l1 = __float2bfloat16(v.y - __bfloat162float(h1));
        __nv_bfloat16 l2 = __float2bfloat16(v.z - __bfloat162float(h2));
        __nv_bfloat16 l3 = __float2bfloat16(v.w - __bfloat162float(h3));
        lo[i * 2 + 0] = __nv_bfloat162(l0, l1);
        lo[i * 2 + 1] = __nv_bfloat162(l2, l3);
    }
}

// ---------------- fused weight split ------------------------------------------
#define WN4 (HIDDEN * D_MODEL / 4)   // 524288 = 2^19
__global__ __launch_bounds__(256) void split_w_kernel(
    const float4* __restrict__ wx, const float4* __restrict__ wg,
    const float4* __restrict__ wdt, const float4* __restrict__ wo)
{
    int gi = blockIdx.x * blockDim.x + threadIdx.x;
    int arr = gi >> 19;
    int i = gi & (WN4 - 1);
    const float4* src = (arr == 0) ? wx : (arr == 1) ? wg : (arr == 2) ? wdt : wo;
    __nv_bfloat162* hi = (arr == 0) ? (__nv_bfloat162*)g_wxhi
                       : (arr == 1) ? (__nv_bfloat162*)g_wghi
                       : (arr == 2) ? (__nv_bfloat162*)g_wdthi
                                    : (__nv_bfloat162*)g_wohi;
    __nv_bfloat162* lo = (arr == 0) ? (__nv_bfloat162*)g_wxlo
                       : (arr == 3) ? (__nv_bfloat162*)g_wolo : nullptr;
    float4 v = src[i];
    __nv_bfloat16 h0 = __float2bfloat16(v.x);
    __nv_bfloat16 h1 = __float2bfloat16(v.y);
    __nv_bfloat16 h2 = __float2bfloat16(v.z);
    __nv_bfloat16 h3 = __float2bfloat16(v.w);
    hi[i * 2 + 0] = __nv_bfloat162(h0, h1);
    hi[i * 2 + 1] = __nv_bfloat162(h2, h3);
    if (lo) {
        __nv_bfloat16 l0 = __float2bfloat16(v.x - __bfloat162float(h0));
        __nv_bfloat16 l1 = __float2bfloat16(v.y - __bfloat162float(h1));
        __nv_bfloat16 l2 = __float2bfloat16(v.z - __bfloat162float(h2));
        __nv_bfloat16 l3 = __float2bfloat16(v.w - __bfloat162float(h3));
        lo[i * 2 + 0] = __nv_bfloat162(l0, l1);
        lo[i * 2 + 1] = __nv_bfloat162(l2, l3);
    }
}

// ---------------- fused u + gate GEMM (TMA, 2-stage, 5 tiles) ----------------
__global__ __launch_bounds__(256, 1) void gemm_ug_tma(
    const __grid_constant__ CUtensorMap mAh, const __grid_constant__ CUtensorMap mAl,
    const __grid_constant__ CUtensorMap mXh, const __grid_constant__ CUtensorMap mXl,
    const __grid_constant__ CUtensorMap mGh,
    const float* __restrict__ bx, const float* __restrict__ bg,
    float* __restrict__ Cu, float* __restrict__ Cg)
{
    const int N = HIDDEN;
    extern __shared__ char smraw[];
    uint32_t sb = (smem_u32(smraw) + 1023u) & ~1023u;
    __shared__ uint64_t mbarS[2];
    uint32_t mb = smem_u32(mbarS);

    const int tid = threadIdx.x;
    const int wid = tid >> 5, lane = tid & 31;
    const int wm = wid & 1, wn = wid >> 1;
    const int am0 = blockIdx.y * BM;
    const int bn0 = blockIdx.x * BN;

    if (tid == 0) { mbar_init(mb); mbar_init(mb + 8); }
    __syncthreads();

    auto issue = [&](int s) {
        if (tid != 0) return;
        uint32_t bar = mb + (uint32_t)(s & 1) * 8;
        mbar_expect(bar, UG_STAGE);
        uint32_t st = sb + (uint32_t)(s & 1) * UG_STAGE;
        int kc = s * BKE;
        tma2d(st + 0 * TILE_B, &mAh, kc, am0, bar);
        tma2d(st + 1 * TILE_B, &mAl, kc, am0, bar);
        tma2d(st + 2 * TILE_B, &mXh, kc, bn0, bar);
        tma2d(st + 3 * TILE_B, &mXl, kc, bn0, bar);
        tma2d(st + 4 * TILE_B, &mGh, kc, bn0, bar);
    };
    issue(0); issue(1);

    float acc_u[4][4][4], acc_g[4][4][4];
#pragma unroll
    for (int i = 0; i < 4; i++)
#pragma unroll
        for (int j = 0; j < 4; j++)
#pragma unroll
            for (int v = 0; v < 4; v++) { acc_u[i][j][v] = 0.f; acc_g[i][j][v] = 0.f; }

    const int arA = wm * 64 + (lane & 15);
    const int ahalf = lane >> 4;
    const uint32_t axor = (uint32_t)(arA & 7);
    uint32_t aoff[4];
#pragma unroll
    for (int mf = 0; mf < 4; mf++) aoff[mf] = (uint32_t)(arA + mf * 16) * RB;

    const int nrB = wn * 32 + (lane & 7) + ((lane >> 4) << 3);
    const int khalf = (lane >> 3) & 1;
    const uint32_t bxor = (uint32_t)(nrB & 7);
    uint32_t boff[2];
#pragma unroll
    for (int nf = 0; nf < 2; nf++) boff[nf] = (uint32_t)(nrB + nf * 16) * RB;

    const int NCH = D_MODEL / BKE;   // 16
    for (int ch = 0; ch < NCH; ch++) {
        mbar_wait(mb + (uint32_t)(ch & 1) * 8, (uint32_t)((ch >> 1) & 1));
        const uint32_t st = sb + (uint32_t)(ch & 1) * UG_STAGE;

#pragma unroll
        for (int ks = 0; ks < 4; ks++) {
            const uint32_t asg = (((uint32_t)(ks * 2 + ahalf)) ^ axor) << 4;
            const uint32_t bsg = (((uint32_t)(ks * 2 + khalf)) ^ bxor) << 4;
            uint32_t ah[4][4], al[4][4];
#pragma unroll
            for (int mf = 0; mf < 4; mf++) {
                ldm_x4(ah[mf], st + 0 * TILE_B + aoff[mf] + asg);
                ldm_x4(al[mf], st + 1 * TILE_B + aoff[mf] + asg);
            }
            {
                uint32_t bh[4][2], bl[4][2];
#pragma unroll
                for (int nf = 0; nf < 2; nf++) {
                    uint32_t rr[4];
                    ldm_x4(rr, st + 2 * TILE_B + boff[nf] + bsg);
                    bh[nf * 2 + 0][0] = rr[0]; bh[nf * 2 + 0][1] = rr[1];
                    bh[nf * 2 + 1][0] = rr[2]; bh[nf * 2 + 1][1] = rr[3];
                    ldm_x4(rr, st + 3 * TILE_B + boff[nf] + bsg);
                    bl[nf * 2 + 0][0] = rr[0]; bl[nf * 2 + 0][1] = rr[1];
                    bl[nf * 2 + 1][0] = rr[2]; bl[nf * 2 + 1][1] = rr[3];
                }
#pragma unroll
                for (int mf = 0; mf < 4; mf++)
#pragma unroll
                    for (int nfi = 0; nfi < 4; nfi++) {
                        mma_bf16(acc_u[mf][nfi], ah[mf], bh[nfi]);
                        mma_bf16(acc_u[mf][nfi], ah[mf], bl[nfi]);
                        mma_bf16(acc_u[mf][nfi], al[mf], bh[nfi]);
                    }
            }
            {
                uint32_t gh[4][2];
#pragma unroll
                for (int nf = 0; nf < 2; nf++) {
                    uint32_t rr[4];
                    ldm_x4(rr, st + 4 * TILE_B + boff[nf] + bsg);
                    gh[nf * 2 + 0][0] = rr[0]; gh[nf * 2 + 0][1] = rr[1];
                    gh[nf * 2 + 1][0] = rr[2]; gh[nf * 2 + 1][1] = rr[3];
                }
#pragma unroll
                for (int mf = 0; mf < 4; mf++)
#pragma unroll
                    for (int nfi = 0; nfi < 4; nfi++) {
                        mma_bf16(acc_g[mf][nfi], ah[mf], gh[nfi]);
                        mma_bf16(acc_g[mf][nfi], al[mf], gh[nfi]);
                    }
            }
        }
        __syncthreads();
        if (ch + 2 < NCH) issue(ch + 2);
    }

#pragma unroll
    for (int mf = 0; mf < 4; mf++) {
        const int r0 = am0 + wm * 64 + mf * 16 + (lane >> 2);
#pragma unroll
        for (int h = 0; h < 2; h++) {
            const int row = r0 + h * 8;
#pragma unroll
            for (int nfi = 0; nfi < 4; nfi++) {
                const int col = bn0 + wn * 32 + nfi * 8 + (lane & 3) * 2;
                float u0 = acc_u[mf][nfi][h * 2 + 0] + bx[col];
                float u1 = acc_u[mf][nfi][h * 2 + 1] + bx[col + 1];
                float g0 = sigmoidf_(acc_g[mf][nfi][h * 2 + 0] + bg[col]);
                float g1 = sigmoidf_(acc_g[mf][nfi][h * 2 + 1] + bg[col + 1]);
                *(float2*)&Cu[(size_t)row * N + col] = make_float2(u0, u1);
                *(float2*)&Cg[(size_t)row * N + col] = make_float2(g0, g1);
            }
        }
    }
}

// ---------------- dt GEMM: 1-term, 3-stage, 2 CTAs/SM -------------------------
__global__ __launch_bounds__(256, 2) void gemm_dt(
    const __grid_constant__ CUtensorMap mAh, const __grid_constant__ CUtensorMap mBh,
    const float* __restrict__ bias, float* __restrict__ colsum)
{
    constexpr int NS = 3;
    constexpr uint32_t STAGE = 2 * TILE_B;
    constexpr uint32_t BHOFF = 1 * TILE_B;
    const int N = HIDDEN, K = D_MODEL;

    extern __shared__ char smraw[];
    uint32_t sb = (smem_u32(smraw) + 1023u) & ~1023u;
    __shared__ uint64_t mbarS[NS];
    uint32_t mb = smem_u32(mbarS);

    const int tid = threadIdx.x;
    const int wid = tid >> 5, lane = tid & 31;
    const int wm = wid & 1, wn = wid >> 1;
    const int am0 = blockIdx.y * BM;
    const int bn0 = blockIdx.x * BN;

    if (tid == 0) {
#pragma unroll
        for (int s = 0; s < NS; s++) mbar_init(mb + s * 8);
    }
    __syncthreads();

    auto issue = [&](int s) {
        if (tid != 0) return;
        int slot = s % NS;
        uint32_t bar = mb + (uint32_t)slot * 8;
        mbar_expect(bar, STAGE);
        uint32_t st = sb + (uint32_t)slot * STAGE;
        int kc = s * BKE;
        tma2d(st, &mAh, kc, am0, bar);
        tma2d(st + BHOFF, &mBh, kc, bn0, bar);
    };
    const int NCH = K / BKE;
#pragma unroll
    for (int s = 0; s < NS; s++) if (s < NCH) issue(s);

    float acc[4][4][4];
#pragma unroll
    for (int i = 0; i < 4; i++)
#pragma unroll
        for (int j = 0; j < 4; j++)
#pragma unroll
            for (int v = 0; v < 4; v++) acc[i][j][v] = 0.f;

    const int arA = wm * 64 + (lane & 15);
    const int ahalf = lane >> 4;
    const uint32_t axor = (uint32_t)(arA & 7);
    uint32_t aoff[4];
#pragma unroll
    for (int mf = 0; mf < 4; mf++) aoff[mf] = (uint32_t)(arA + mf * 16) * RB;

    const int nrB = wn * 32 + (lane & 7) + ((lane >> 4) << 3);
    const int khalf = (lane >> 3) & 1;
    const uint32_t bxor = (uint32_t)(nrB & 7);
    uint32_t boff[2];
#pragma unroll
    for (int nf = 0; nf < 2; nf++) boff[nf] = (uint32_t)(nrB + nf * 16) * RB;

    for (int ch = 0; ch < NCH; ch++) {
        int slot = ch % NS;
        mbar_wait(mb + (uint32_t)slot * 8, (uint32_t)((ch / NS) & 1));
        const uint32_t st = sb + (uint32_t)slot * STAGE;

#pragma unroll
        for (int ks = 0; ks < 4; ks++) {
            uint32_t a[4][4], bh[4][2];
            const uint32_t asg = (((uint32_t)(ks * 2 + ahalf)) ^ axor) << 4;
            const uint32_t bsg = (((uint32_t)(ks * 2 + khalf)) ^ bxor) << 4;
#pragma unroll
            for (int nf = 0; nf < 2; nf++) {
                uint32_t rr[4];
                ldm_x4(rr, st + BHOFF + boff[nf] + bsg);
                bh[nf * 2 + 0][0] = rr[0]; bh[nf * 2 + 0][1] = rr[1];
                bh[nf * 2 + 1][0] = rr[2]; bh[nf * 2 + 1][1] = rr[3];
            }
#pragma unroll
            for (int mf = 0; mf < 4; mf++) ldm_x4(a[mf], st + aoff[mf] + asg);
#pragma unroll
            for (int mf = 0; mf < 4; mf++)
#pragma unroll
                for (int nfi = 0; nfi < 4; nfi++)
                    mma_bf16(acc[mf][nfi], a[mf], bh[nfi]);
        }
        __syncthreads();
        if (ch + NS < NCH) issue(ch + NS);
    }

    float* red = (float*)smraw;
#pragma unroll
    for (int nfi = 0; nfi < 4; nfi++) {
        const int colb = bn0 + wn * 32 + nfi * 8 + (lane & 3) * 2;
        const float b0 = bias[colb], b1 = bias[colb + 1];
        float s0 = 0.f, s1 = 0.f;
#pragma unroll
        for (int mf = 0; mf < 4; mf++) {
            s0 += softplusf(acc[mf][nfi][0] + b0);
            s1 += softplusf(acc[mf][nfi][1] + b1);
            s0 += softplusf(acc[mf][nfi][2] + b0);
            s1 += softplusf(acc[mf][nfi][3] + b1);
        }
#pragma unroll
        for (int o = 4; o <= 16; o <<= 1) {
            s0 += __shfl_xor_sync(0xffffffffu, s0, o);
            s1 += __shfl_xor_sync(0xffffffffu, s1, o);
        }
        if (lane < 4) {
            int c = wn * 32 + nfi * 8 + lane * 2;
            red[wm * 128 + c] = s0;
            red[wm * 128 + c + 1] = s1;
        }
    }
    __syncthreads();
    if (tid < 128)
        colsum[(size_t)blockIdx.y * N + bn0 + tid] = red[tid] + red[128 + tid];
}

// ---------------- out GEMM: 3-term, 3-stage, ks-pipelined fragments ----------
__global__ __launch_bounds__(256, 1) void gemm_out(
    const __grid_constant__ CUtensorMap mAh, const __grid_constant__ CUtensorMap mAl,
    const __grid_constant__ CUtensorMap mBh, const __grid_constant__ CUtensorMap mBl,
    const float* __restrict__ bias, float* __restrict__ C)
{
    constexpr int NS = 3;
    constexpr uint32_t STAGE = 4 * TILE_B;
    constexpr uint32_t ALOFF = 1 * TILE_B;
    constexpr uint32_t BHOFF = 2 * TILE_B;
    constexpr uint32_t BLOFF = 3 * TILE_B;
    const int N = D_MODEL, K = HIDDEN;

    extern __shared__ char smraw[];
    uint32_t sb = (smem_u32(smraw) + 1023u) & ~1023u;
    __shared__ uint64_t mbarS[NS];
    uint32_t mb = smem_u32(mbarS);

    const int tid = threadIdx.x;
    const int wid = tid >> 5, lane = tid & 31;
    const int wm = wid & 1, wn = wid >> 1;
    const int am0 = blockIdx.y * BM;
    const int bn0 = blockIdx.x * BN;

    if (tid == 0) {
#pragma unroll
        for (int s = 0; s < NS; s++) mbar_init(mb + s * 8);
    }
    __syncthreads();

    auto issue = [&](int s) {
        if (tid != 0) return;
        int slot = s % NS;
        uint32_t bar = mb + (uint32_t)slot * 8;
        mbar_expect(bar, STAGE);
        uint32_t st = sb + (uint32_t)slot * STAGE;
        int kc = s * BKE;
        tma2d(st, &mAh, kc, am0, bar);
        tma2d(st + ALOFF, &mAl, kc, am0, bar);
        tma2d(st + BHOFF, &mBh, kc, bn0, bar);
        tma2d(st + BLOFF, &mBl, kc, bn0, bar);
    };
    const int NCH = K / BKE;   // 32
#pragma unroll
    for (int s = 0; s < NS; s++) issue(s);

    float acc[4][4][4];
#pragma unroll
    for (int i = 0; i < 4; i++)
#pragma unroll
        for (int j = 0; j < 4; j++)
#pragma unroll
            for (int v = 0; v < 4; v++) acc[i][j][v] = 0.f;

    const int arA = wm * 64 + (lane & 15);
    const int ahalf = lane >> 4;
    const uint32_t axor = (uint32_t)(arA & 7);
    uint32_t aoff[4];
#pragma unroll
    for (int mf = 0; mf < 4; mf++) aoff[mf] = (uint32_t)(arA + mf * 16) * RB;

    const int nrB = wn * 32 + (lane & 7) + ((lane >> 4) << 3);
    const int khalf = (lane >> 3) & 1;
    const uint32_t bxor = (uint32_t)(nrB & 7);
    uint32_t boff[2];
#pragma unroll
    for (int nf = 0; nf < 2; nf++) boff[nf] = (uint32_t)(nrB + nf * 16) * RB;

    uint32_t ah[2][4][4], al[2][4][4], bh[2][4][2], bl[2][4][2];

    auto load_frags = [&](int buf, uint32_t st, int ks) {
        const uint32_t asg = (((uint32_t)(ks * 2 + ahalf)) ^ axor) << 4;
        const uint32_t bsg = (((uint32_t)(ks * 2 + khalf)) ^ bxor) << 4;
#pragma unroll
        for (int nf = 0; nf < 2; nf++) {
            uint32_t rr[4];
            ldm_x4(rr, st + BHOFF + boff[nf] + bsg);
            bh[buf][nf * 2 + 0][0] = rr[0]; bh[buf][nf * 2 + 0][1] = rr[1];
            bh[buf][nf * 2 + 1][0] = rr[2]; bh[buf][nf * 2 + 1][1] = rr[3];
            ldm_x4(rr, st + BLOFF + boff[nf] + bsg);
            bl[buf][nf * 2 + 0][0] = rr[0]; bl[buf][nf * 2 + 0][1] = rr[1];
            bl[buf][nf * 2 + 1][0] = rr[2]; bl[buf][nf * 2 + 1][1] = rr[3];
        }
#pragma unroll
        for (int mf = 0; mf < 4; mf++) {
            ldm_x4(ah[buf][mf], st + aoff[mf] + asg);
            ldm_x4(al[buf][mf], st + ALOFF + aoff[mf] + asg);
        }
    };

    for (int ch = 0; ch < NCH; ch++) {
        int slot = ch % NS;
        mbar_wait(mb + (uint32_t)slot * 8, (uint32_t)((ch / NS) & 1));
        const uint32_t st = sb + (uint32_t)slot * STAGE;

        load_frags(0, st, 0);
#pragma unroll
        for (int ks = 0; ks < 4; ks++) {
            const int cur = ks & 1;
            if (ks < 3) load_frags(cur ^ 1, st, ks + 1);
#pragma unroll
            for (int mf = 0; mf < 4; mf++)
#pragma unroll
                for (int nfi = 0; nfi < 4; nfi++) {
                    mma_bf16(acc[mf][nfi], ah[cur][mf], bh[cur][nfi]);
                    mma_bf16(acc[mf][nfi], ah[cur][mf], bl[cur][nfi]);
                    mma_bf16(acc[mf][nfi], al[cur][mf], bh[cur][nfi]);
                }
        }
        __syncthreads();
        if (ch + NS < NCH) issue(ch + NS);
    }

#pragma unroll
    for (int mf = 0; mf < 4; mf++) {
        const int r0 = am0 + wm * 64 + mf * 16 + (lane >> 2);
#pragma unroll
        for (int h = 0; h < 2; h++) {
            const int row = r0 + h * 8;
#pragma unroll
            for (int nfi = 0; nfi < 4; nfi++) {
                const int col = bn0 + wn * 32 + nfi * 8 + (lane & 3) * 2;
                float v0 = acc[mf][nfi][h * 2 + 0] + bias[col];
                float v1 = acc[mf][nfi][h * 2 + 1] + bias[col + 1];
                *(float2*)&C[(size_t)row * N + col] = make_float2(v0, v1);
            }
        }
    }
}

// ---------------- dt finalize + discretization --------------------------------
__global__ void disc_kernel(const float* __restrict__ A_raw,
                            const float* __restrict__ B_ssm)
{
    int idx = blockIdx.x * blockDim.x + threadIdx.x;
    if (idx >= HIDDEN * D_STATE) return;
    int h = idx / D_STATE;
    float sum = 0.f;
#pragma unroll
    for (int p = 0; p < MTOK / BM; p++) sum += g_dtpart[p * HIDDEN + h];
    float dt = sum * (1.f / (float)MTOK);
    dt = fminf(fmaxf(dt, 1e-3f), 2.0f);
    float a = -softplusf(A_raw[idx]);
    float ad = expf(a * dt);
    float bd = (ad - 1.0f) / (a + 1e-6f) * B_ssm[idx];
    g_Ad[idx] = ad;
    g_Bd[idx] = bd;
}

// ---------------- scan pass 1: fused conv+gate + chunk-local scan ------------
__global__ __launch_bounds__(128) void scan1_kernel(
    const float* __restrict__ C_ssm, const float* __restrict__ conv_w,
    const float* __restrict__ conv_b)
{
    int idx = blockIdx.x * blockDim.x + threadIdx.x;
    int h = idx & (HIDDEN - 1);
    int bc = idx >> 11;
    int c = bc & (NCHK - 1);

    float ad[D_STATE], bd[D_STATE], cc[D_STATE], st[D_STATE];
#pragma unroll
    for (int j = 0; j < D_STATE; j++) {
        ad[j] = g_Ad[h * D_STATE + j];
        bd[j] = g_Bd[h * D_STATE + j];
        cc[j] = C_ssm[h * D_STATE + j];
        st[j] = 0.f;
    }
    const float w0 = conv_w[h * 3 + 0], w1 = conv_w[h * 3 + 1],
                w2 = conv_w[h * 3 + 2], cb = conv_b[h];

    const int b = bc >> 4;
    const int l0 = c * CHK;
    const size_t base = ((size_t)b * SEQ + l0) * HIDDEN + h;
    const float* up = g_u + base;
    float* gp = g_g + base;

    float um = (l0 > 0) ? up[-(ptrdiff_t)HIDDEN] : 0.f;
    float cu[4], cg[4];
#pragma unroll
    for (int q = 0; q < 4; q++) {
        cu[q] = up[(size_t)q * HIDDEN];
        cg[q] = gp[(size_t)q * HIDDEN];
    }

    for (int t = 0; t < CHK; t += 4) {
        float nu[4], ng[4];
#pragma unroll
        for (int q = 0; q < 4; q++) {
            int l = l0 + t + 4 + q;
            nu[q] = (l < SEQ) ? up[(size_t)(t + 4 + q) * HIDDEN] : 0.f;
            int tt = t + 4 + q;
            ng[q] = (tt < CHK) ? gp[(size_t)tt * HIDDEN] : 0.f;
        }
#pragma unroll
        for (int q = 0; q < 4; q++) {
            float u0 = cu[q];
            float upn = (q < 3) ? cu[q + 1] : nu[0];
            float hc = cb + w0 * um + w1 * u0 + w2 * upn;
            float g = cg[q];
            float uc = u0 * g + hc * (1.f - g);
            float y0 = 0.f, y1 = 0.f, y2 = 0.f, y3 = 0.f;
#pragma unroll
            for (int j = 0; j < D_STATE; j++)
                st[j] = fmaf(ad[j], st[j], bd[j] * uc);
#pragma unroll
            for (int j = 0; j < D_STATE; j += 4) {
                y0 = fmaf(st[j + 0], cc[j + 0], y0);
                y1 = fmaf(st[j + 1], cc[j + 1], y1);
                y2 = fmaf(st[j + 2], cc[j + 2], y2);
                y3 = fmaf(st[j + 3], cc[j + 3], y3);
            }
            gp[(size_t)(t + q) * HIDDEN] = (y0 + y1) + (y2 + y3);
            um = u0;
        }
#pragma unroll
        for (int q = 0; q < 4; q++) { cu[q] = nu[q]; cg[q] = ng[q]; }
    }
    float* sp = g_state + (size_t)idx * D_STATE;
#pragma unroll
    for (int j = 0; j < D_STATE; j += 4)
        *(float4*)&sp[j] = make_float4(st[j], st[j + 1], st[j + 2], st[j + 3]);
}

// ---------------- scan pass 2: chunk-state prefix ----------------------------
__global__ __launch_bounds__(256) void scan2_kernel()
{
    int idx = blockIdx.x * blockDim.x + threadIdx.x;
    int j = idx & (D_STATE - 1);
    int h = (idx >> 4) & (HIDDEN - 1);
    int b = idx >> 15;

    float ad = g_Ad[h * D_STATE + j];
    float af = ad;
#pragma unroll
    for (int i = 0; i < 7; i++) af = af * af;

    float carry = 0.f;
#pragma unroll
    for (int c = 0; c < NCHK; c++) {
        size_t off = (((size_t)b * NCHK + c) * HIDDEN + h) * D_STATE + j;
        g_init[off] = carry;
        carry = fmaf(af, carry, g_state[off]);
    }
}

// ---------------- scan pass 3: fixup + bf16 split ----------------------------
__global__ __launch_bounds__(128) void scan3_kernel(const float* __restrict__ C_ssm)
{
    int idx = blockIdx.x * blockDim.x + threadIdx.x;
    int h = idx & (HIDDEN - 1);
    int bc = idx >> 11;
    int c = bc & (NCHK - 1);
    int b = bc >> 4;

    const size_t base = ((size_t)b * SEQ + (size_t)c * CHK) * HIDDEN + h;
    const float* yp = g_g + base;
    __nv_bfloat16* yh = g_yhi + base;
    __nv_bfloat16* yl = g_ylo + base;

    if (c == 0) {
        for (int t = 0; t < CHK; t++) {
            float yv = yp[(size_t)t * HIDDEN];
            __nv_bfloat16 hi = __float2bfloat16(yv);
            __nv_bfloat16 lo = __float2bfloat16(yv - __bfloat162float(hi));
            yh[(size_t)t * HIDDEN] = hi;
            yl[(size_t)t * HIDDEN] = lo;
        }
        return;
    }

    float ad[D_STATE], cc[D_STATE], p[D_STATE];
    const float* ip = g_init + (size_t)idx * D_STATE;
#pragma unroll
    for (int j = 0; j < D_STATE; j++) {
        ad[j] = g_Ad[h * D_STATE + j];
        cc[j] = C_ssm[h * D_STATE + j];
        p[j] = ip[j];
    }
    for (int t = 0; t < CHK; t++) {
        float y0 = 0.f, y1 = 0.f, y2 = 0.f, y3 = 0.f;
#pragma unroll
        for (int j = 0; j < D_STATE; j++) p[j] *= ad[j];
#pragma unroll
        for (int j = 0; j < D_STATE; j += 4) {
            y0 = fmaf(p[j + 0], cc[j + 0], y0);
            y1 = fmaf(p[j + 1], cc[j + 1], y1);
            y2 = fmaf(p[j + 2], cc[j + 2], y2);
            y3 = fmaf(p[j + 3], cc[j + 3], y3);
        }
        float yv = yp[(size_t)t * HIDDEN] + ((y0 + y1) + (y2 + y3));
        __nv_bfloat16 hi = __float2bfloat16(yv);
        __nv_bfloat16 lo = __float2bfloat16(yv - __bfloat162float(hi));
        yh[(size_t)t * HIDDEN] = hi;
        yl[(size_t)t * HIDDEN] = lo;
    }
}

// ---------------- residual + layernorm ---------------------------------------
__global__ __launch_bounds__(256) void ln_kernel(
    const float* __restrict__ x, const float* __restrict__ lng,
    const float* __restrict__ lnb, float* __restrict__ out)
{
    int row = blockIdx.x;
    __shared__ float sh[D_MODEL];
    __shared__ float rs[20];
    const float* xr = x + (size_t)row * D_MODEL;
    const float* orow = g_outp + (size_t)row * D_MODEL;
    int tid = threadIdx.x;

    float s = 0.f, sq = 0.f;
    for (int i = tid; i < D_MODEL; i += 256) {
        float r = xr[i] + orow[i];
        sh[i] = r;
        s += r;
        sq += r * r;
    }
#pragma unroll
    for (int o = 16; o > 0; o >>= 1) {
        s += __shfl_xor_sync(0xffffffffu, s, o);
        sq += __shfl_xor_sync(0xffffffffu, sq, o);
    }
    int w = tid >> 5, ln = tid & 31;
    if (ln == 0) { rs[w] = s; rs[8 + w] = sq; }
    __syncthreads();
    if (tid == 0) {
        float ts = 0.f, tq = 0.f;
#pragma unroll
        for (int i = 0; i < 8; i++) { ts += rs[i]; tq += rs[8 + i]; }
        float mean = ts * (1.f / (float)D_MODEL);
        float var = tq * (1.f / (float)D_MODEL) - mean * mean;
        rs[16] = mean;
        rs[17] = rsqrtf(var + 1e-5f);
    }
    __syncthreads();
    float mean = rs[16], inv = rs[17];
    for (int i = tid; i < D_MODEL; i += 256)
        out[(size_t)row * D_MODEL + i] = (sh[i] - mean) * inv * lng[i] + lnb[i];
}

// ---------------- host: tensormap encode via dlopen ---------------------------
typedef CUresult (*PFN_encode)(CUtensorMap*, CUtensorMapDataType, cuuint32_t, void*,
    const cuuint64_t*, const cuuint64_t*, const cuuint32_t*, const cuuint32_t*,
    CUtensorMapInterleave, CUtensorMapSwizzle, CUtensorMapL2promotion,
    CUtensorMapFloatOOBfill);

static void make_map(PFN_encode enc, CUtensorMap* m, void* ptr, int rows, int K)
{
    cuuint64_t dims[2] = {(cuuint64_t)K, (cuuint64_t)rows};
    cuuint64_t strides[1] = {(cuuint64_t)K * 2};
    cuuint32_t box[2] = {64u, 128u};
    cuuint32_t es[2] = {1u, 1u};
    enc(m, CU_TENSOR_MAP_DATA_TYPE_BFLOAT16, 2, ptr, dims, strides, box, es,
        CU_TENSOR_MAP_INTERLEAVE_NONE, CU_TENSOR_MAP_SWIZZLE_128B,
        CU_TENSOR_MAP_L2_PROMOTION_L2_128B, CU_TENSOR_MAP_FLOAT_OOB_FILL_NONE);
}

// ---------------- launch -----------------------------------------------------
extern "C" void kernel_launch(void* const* d_in, const int* in_sizes, int n_in,
                              void* d_out, int out_size)
{
    const float* x      = (const float*)d_in[0];
    const float* W_x    = (const float*)d_in[1];
    const float* b_x    = (const float*)d_in[2];
    const float* W_g    = (const float*)d_in[3];
    const float* b_g    = (const float*)d_in[4];
    const float* conv_w = (const float*)d_in[5];
    const float* conv_b = (const float*)d_in[6];
    const float* A_raw  = (const float*)d_in[7];
    const float* B_ssm  = (const float*)d_in[8];
    const float* C_ssm  = (const float*)d_in[9];
    const float* W_dt   = (const float*)d_in[10];
    const float* b_dt   = (const float*)d_in[11];
    const float* W_out  = (const float*)d_in[12];
    const float* b_out  = (const float*)d_in[13];
    const float* ln_g   = (const float*)d_in[14];
    const float* ln_b   = (const float*)d_in[15];
    float* out = (float*)d_out;

    float *pu, *pg, *pdt, *pout;
    __nv_bfloat16 *pxh, *pxl, *pwxh, *pwxl, *pwgh, *pwdh, *pwoh, *pwol, *pyh, *pyl;
    cudaGetSymbolAddress((void**)&pu, g_u);
    cudaGetSymbolAddress((void**)&pg, g_g);
    cudaGetSymbolAddress((void**)&pdt, g_dtpart);
    cudaGetSymbolAddress((void**)&pout, g_outp);
    cudaGetSymbolAddress((void**)&pxh, g_xhi);
    cudaGetSymbolAddress((void**)&pxl, g_xlo);
    cudaGetSymbolAddress((void**)&pwxh, g_wxhi);
    cudaGetSymbolAddress((void**)&pwxl, g_wxlo);
    cudaGetSymbolAddress((void**)&pwgh, g_wghi);
    cudaGetSymbolAddress((void**)&pwdh, g_wdthi);
    cudaGetSymbolAddress((void**)&pwoh, g_wohi);
    cudaGetSymbolAddress((void**)&pwol, g_wolo);
    cudaGetSymbolAddress((void**)&pyh, g_yhi);
    cudaGetSymbolAddress((void**)&pyl, g_ylo);

    void* dl = dlopen("libcuda.so.1", RTLD_NOW);
    if (!dl) dl = dlopen("libcuda.so", RTLD_NOW);
    PFN_encode enc = dl ? (PFN_encode)dlsym(dl, "cuTensorMapEncodeTiled") : nullptr;

    CUtensorMap Mxh, Mxl, Mwxh, Mwxl, Mwgh, Mwdh, Mwoh, Mwol, Myh, Myl;
    make_map(enc, &Mxh, pxh, MTOK, D_MODEL);
    make_map(enc, &Mxl, pxl, MTOK, D_MODEL);
    make_map(enc, &Mwxh, pwxh, HIDDEN, D_MODEL);
    make_map(enc, &Mwxl, pwxl, HIDDEN, D_MODEL);
    make_map(enc, &Mwgh, pwgh, HIDDEN, D_MODEL);
    make_map(enc, &Mwdh, pwdh, HIDDEN, D_MODEL);
    make_map(enc, &Mwoh, pwoh, D_MODEL, HIDDEN);
    make_map(enc, &Mwol, pwol, D_MODEL, HIDDEN);
    make_map(enc, &Myh, pyh, MTOK, HIDDEN);
    make_map(enc, &Myl, pyl, MTOK, HIDDEN);

    cudaFuncSetAttribute(gemm_ug_tma, cudaFuncAttributeMaxDynamicSharedMemorySize, SMEM_UG);
    cudaFuncSetAttribute(gemm_out, cudaFuncAttributeMaxDynamicSharedMemorySize, SMEM_OUT);
    cudaFuncSetAttribute(gemm_dt, cudaFuncAttributeMaxDynamicSharedMemorySize, SMEM_DT);

    // side stream + fork/join events (host objects; created/destroyed per call)
    cudaStream_t s1;
    cudaStreamCreateWithFlags(&s1, cudaStreamNonBlocking);
    cudaEvent_t eFork, eJoin;
    cudaEventCreateWithFlags(&eFork, cudaEventDisableTiming);
    cudaEventCreateWithFlags(&eJoin, cudaEventDisableTiming);

    {
        int n4 = MTOK * D_MODEL / 4;
        split_kernel<<<(n4 + 255) / 256, 256>>>((const float4*)x,
                                                (__nv_bfloat162*)pxh,
                                                (__nv_bfloat162*)pxl, n4);
        split_w_kernel<<<(4 * WN4) / 256, 256>>>((const float4*)W_x,
                                                 (const float4*)W_g,
                                                 (const float4*)W_dt,
                                                 (const float4*)W_out);
    }

    dim3 gridH(HIDDEN / BN, MTOK / BM);    // (16, 32)
    dim3 gridD(D_MODEL / BN, MTOK / BM);   // (8, 32)

    // fork: dt GEMM + disc run on s1 concurrently with ug GEMM on main
    cudaEventRecord(eFork, 0);
    cudaStreamWaitEvent(s1, eFork, 0);

    gemm_ug_tma<<<gridH, 256, SMEM_UG>>>(Mxh, Mxl, Mwxh, Mwxl, Mwgh,
                                         b_x, b_g, pu, pg);

    gemm_dt<<<gridH, 256, SMEM_DT, s1>>>(Mxh, Mwdh, b_dt, pdt);
    disc_kernel<<<(HIDDEN * D_STATE + 255) / 256, 256, 0, s1>>>(A_raw, B_ssm);
    cudaEventRecord(eJoin, s1);

    // join: scan needs ug output (main) AND Ad/Bd (s1)
    cudaStreamWaitEvent(0, eJoin, 0);

    scan1_kernel<<<(BATCH * NCHK * HIDDEN) / 128, 128>>>(C_ssm, conv_w, conv_b);
    scan2_kernel<<<(BATCH * HIDDEN * D_STATE) / 256, 256>>>();
    scan3_kernel<<<(BATCH * NCHK * HIDDEN) / 128, 128>>>(C_ssm);

    gemm_out<<<gridD, 256, SMEM_OUT>>>(Myh, Myl, Mwoh, Mwol, b_out, pout);

    ln_kernel<<<MTOK, 256>>>(x, ln_g, ln_b, out);

    cudaEventDestroy(eFork);
    cudaEventDestroy(eJoin);
    cudaStreamDestroy(s1);
}